// round 5
// baseline (speedup 1.0000x reference)
#include <cuda_runtime.h>
#include <cuda_fp16.h>
#include <math.h>
#include <stdint.h>

#define NE 100000
#define NR 10
#define EDIM 128
#define HID 256
#define NREG 2000
#define NKG 600000
#define NMP_REL 5
#define NMP_E 300000
#define NB 1024
#define ATT 128

#define NMSG (NR * EDIM)            /* 1280 message columns */
#define KMP (NMP_REL * EDIM + EDIM) /* 768 */

// ---------------- scratch ----------------------------------------------------
__device__ __half g_Ymsg[(size_t)NE * NMSG];  // fp16 messages (256MB); fp32 mp scratch alias
__device__ float g_Yroot[(size_t)NE * EDIM];  // fp32 root term + atomic accumulator
__device__ float g_E[(size_t)NE * EDIM];
__device__ __half g_Eh[(size_t)NE * EDIM];    // E fp16 (pred B operand)
__device__ __half g_BmainTh[(NMSG + EDIM) * EDIM];  // [n][k] fp16
__device__ float g_Bmp[2][KMP * HID];
__device__ __half g_xh[NB * EDIM];            // (E[h]*R[r]) fp16
__device__ float g_sem[2][NREG * HID];
__device__ float g_w[2];

// ---------------- primitives -------------------------------------------------
__device__ __forceinline__ void red_add_v4(float* addr, float4 v) {
    asm volatile("red.global.add.v4.f32 [%0], {%1, %2, %3, %4};"
                 :: "l"(addr), "f"(v.x), "f"(v.y), "f"(v.z), "f"(v.w) : "memory");
}
__device__ __forceinline__ void mma16816(float* c, const uint32_t* a, const uint32_t* b) {
    asm volatile(
        "mma.sync.aligned.m16n8k16.row.col.f32.f16.f16.f32 "
        "{%0,%1,%2,%3}, {%4,%5,%6,%7}, {%8,%9}, {%0,%1,%2,%3};"
        : "+f"(c[0]), "+f"(c[1]), "+f"(c[2]), "+f"(c[3])
        : "r"(a[0]), "r"(a[1]), "r"(a[2]), "r"(a[3]), "r"(b[0]), "r"(b[1]));
}
__device__ __forceinline__ float cvt_tf32(float x) {
    unsigned u;
    asm("cvt.rna.tf32.f32 %0, %1;" : "=r"(u) : "f"(x));
    return __uint_as_float(u);
}
__device__ __forceinline__ float4 cvt_tf32_4(float4 v) {
    return make_float4(cvt_tf32(v.x), cvt_tf32(v.y), cvt_tf32(v.z), cvt_tf32(v.w));
}
__device__ __forceinline__ void mma8(float* c, const unsigned* a, const unsigned* b) {
    asm volatile(
        "mma.sync.aligned.m16n8k8.row.col.f32.tf32.tf32.f32 "
        "{%0,%1,%2,%3}, {%4,%5,%6,%7}, {%8,%9}, {%0,%1,%2,%3};"
        : "+f"(c[0]), "+f"(c[1]), "+f"(c[2]), "+f"(c[3])
        : "r"(a[0]), "r"(a[1]), "r"(a[2]), "r"(a[3]), "r"(b[0]), "r"(b[1]));
}

// ---------------- shared fp16 K=128 tile compute ------------------------------
#define SPAD 136
typedef __half htile_t[SPAD];

__device__ __forceinline__ void compute_k128(const htile_t* As, const htile_t* Bs,
                                             float c[2][8][4], int wm, int wn, int g, int t) {
#pragma unroll
    for (int kb = 0; kb < 128; kb += 16) {
        uint32_t a[2][4], b[8][2];
#pragma unroll
        for (int mt = 0; mt < 2; mt++) {
            int row = wm + mt * 16 + g;
            a[mt][0] = *(const uint32_t*)&As[row][kb + 2 * t];
            a[mt][1] = *(const uint32_t*)&As[row + 8][kb + 2 * t];
            a[mt][2] = *(const uint32_t*)&As[row][kb + 2 * t + 8];
            a[mt][3] = *(const uint32_t*)&As[row + 8][kb + 2 * t + 8];
        }
#pragma unroll
        for (int nt = 0; nt < 8; nt++) {
            int col = wn + nt * 8 + g;
            b[nt][0] = *(const uint32_t*)&Bs[col][kb + 2 * t];
            b[nt][1] = *(const uint32_t*)&Bs[col][kb + 2 * t + 8];
        }
#pragma unroll
        for (int mt = 0; mt < 2; mt++)
#pragma unroll
            for (int nt = 0; nt < 8; nt++) mma16816(c[mt][nt], a[mt], b[nt]);
    }
}

// load a 128x128 fp16 tile (zero-pad rows >= nrows) via register staging
__device__ __forceinline__ void ldg_h_tile(uint4* reg, const __half* __restrict__ src,
                                           int row0, int nrows, int tid) {
    const uint4 z = make_uint4(0, 0, 0, 0);
#pragma unroll
    for (int l = 0; l < 8; l++) {
        int e = l * 256 + tid;
        int r = e >> 4, c8 = (e & 15) * 8;
        reg[l] = (r < nrows) ? *(const uint4*)&src[(size_t)(row0 + r) * 128 + c8] : z;
    }
}
__device__ __forceinline__ void sts_h_tile(htile_t* dst, const uint4* reg, int tid) {
#pragma unroll
    for (int l = 0; l < 8; l++) {
        int e = l * 256 + tid;
        int r = e >> 4, c8 = (e & 15) * 8;
        *(uint4*)&dst[r][c8] = reg[l];
    }
}

// ---------------- GEMM1 strip: Y = X[M,128] @ BmainTh[1408,128]^T -------------
// A tile resident (fp32 src converted in-kernel); loop 11 B tiles double-buffered.
// Output: tiles 0..9 -> fp16 g_Ymsg [M,1280]; tile 10 -> fp32 g_Yroot [M,128].
__global__ __launch_bounds__(256, 2)
void gemm1_strip(const float* __restrict__ A, const __half* __restrict__ Bt, int M) {
    extern __shared__ __half sm[];
    htile_t* As = (htile_t*)sm;
    htile_t* Bs0 = (htile_t*)(sm + 128 * SPAD);
    htile_t* Bs1 = (htile_t*)(sm + 2 * 128 * SPAD);
    const int tid = threadIdx.x, lane = tid & 31, warp = tid >> 5;
    const int g = lane >> 2, t = lane & 3;
    const int wm = (warp >> 1) * 32, wn = (warp & 1) * 64;
    const int m0 = blockIdx.x * 128;
    const int arows = (M - m0 < 128) ? (M - m0) : 128;

    // A tile: fp32 -> fp16 into SMEM
    {
        const float4 zf = make_float4(0.f, 0.f, 0.f, 0.f);
#pragma unroll
        for (int l = 0; l < 16; l++) {
            int e = l * 256 + tid;
            int r = e >> 5, c4 = (e & 31) * 4;
            float4 v = (r < arows) ? *(const float4*)&A[(size_t)(m0 + r) * 128 + c4] : zf;
            __half2 h0 = __floats2half2_rn(v.x, v.y);
            __half2 h1 = __floats2half2_rn(v.z, v.w);
            *(uint2*)&As[r][c4] = make_uint2(*(uint32_t*)&h0, *(uint32_t*)&h1);
        }
    }
    uint4 br[8];
    ldg_h_tile(br, Bt, 0, 128, tid);
    sts_h_tile(Bs0, br, tid);
    __syncthreads();

    for (int nt = 0; nt < 11; nt++) {
        htile_t* Bcur = (nt & 1) ? Bs1 : Bs0;
        htile_t* Bnext = (nt & 1) ? Bs0 : Bs1;
        if (nt + 1 < 11) ldg_h_tile(br, Bt, (nt + 1) * 128, 128, tid);

        float c[2][8][4];
#pragma unroll
        for (int i = 0; i < 2; i++)
#pragma unroll
            for (int j = 0; j < 8; j++)
#pragma unroll
                for (int l = 0; l < 4; l++) c[i][j][l] = 0.f;
        compute_k128(As, Bcur, c, wm, wn, g, t);

        if (nt + 1 < 11) sts_h_tile(Bnext, br, tid);

#pragma unroll
        for (int mt = 0; mt < 2; mt++) {
#pragma unroll
            for (int h = 0; h < 2; h++) {
                int row = m0 + wm + mt * 16 + g + h * 8;
                if (row < M) {
                    if (nt < 10) {
                        __half* cp = g_Ymsg + (size_t)row * NMSG + nt * 128;
#pragma unroll
                        for (int j = 0; j < 8; j++) {
                            int col = wn + j * 8 + 2 * t;
                            __half2 hv = __floats2half2_rn(c[mt][j][h * 2], c[mt][j][h * 2 + 1]);
                            *(__half2*)(cp + col) = hv;
                        }
                    } else {
                        float* cp = g_Yroot + (size_t)row * 128;
#pragma unroll
                        for (int j = 0; j < 8; j++) {
                            int col = wn + j * 8 + 2 * t;
                            *(float2*)(cp + col) =
                                make_float2(c[mt][j][h * 2], c[mt][j][h * 2 + 1]);
                        }
                    }
                }
            }
        }
        __syncthreads();
    }
}

// ---------------- pred strip: out = xh[1024,128] @ Eh[N,128]^T ----------------
// B (Eh) tile resident; loop 8 A (xh) tiles double-buffered.
__global__ __launch_bounds__(256, 2)
void pred_strip(const __half* __restrict__ Ah, const __half* __restrict__ Bt,
                float* __restrict__ C, int N) {
    extern __shared__ __half sm[];
    htile_t* Bs = (htile_t*)sm;
    htile_t* As0 = (htile_t*)(sm + 128 * SPAD);
    htile_t* As1 = (htile_t*)(sm + 2 * 128 * SPAD);
    const int tid = threadIdx.x, lane = tid & 31, warp = tid >> 5;
    const int g = lane >> 2, t = lane & 3;
    const int wm = (warp >> 1) * 32, wn = (warp & 1) * 64;
    const int n0 = blockIdx.x * 128;
    const int brows = (N - n0 < 128) ? (N - n0) : 128;

    {
        uint4 rr[8];
        ldg_h_tile(rr, Bt, n0, brows, tid);
        sts_h_tile(Bs, rr, tid);
    }
    uint4 ar[8];
    ldg_h_tile(ar, Ah, 0, 128, tid);
    sts_h_tile(As0, ar, tid);
    __syncthreads();

    const int MT = NB / 128;  // 8
    for (int mt = 0; mt < MT; mt++) {
        htile_t* Acur = (mt & 1) ? As1 : As0;
        htile_t* Anext = (mt & 1) ? As0 : As1;
        if (mt + 1 < MT) ldg_h_tile(ar, Ah, (mt + 1) * 128, 128, tid);

        float c[2][8][4];
#pragma unroll
        for (int i = 0; i < 2; i++)
#pragma unroll
            for (int j = 0; j < 8; j++)
#pragma unroll
                for (int l = 0; l < 4; l++) c[i][j][l] = 0.f;
        compute_k128(Acur, Bs, c, wm, wn, g, t);

        if (mt + 1 < MT) sts_h_tile(Anext, ar, tid);

#pragma unroll
        for (int mi = 0; mi < 2; mi++) {
#pragma unroll
            for (int h = 0; h < 2; h++) {
                int row = mt * 128 + wm + mi * 16 + g + h * 8;
#pragma unroll
                for (int j = 0; j < 8; j++) {
                    int col = n0 + wn + j * 8 + 2 * t;
                    if (col < N)
                        *(float2*)&C[(size_t)row * N + col] =
                            make_float2(c[mi][j][h * 2], c[mi][j][h * 2 + 1]);
                }
            }
        }
        __syncthreads();
    }
}

// ---------------- tf32 mma GEMM (metapath GEMMs, K=768) ----------------------
__global__ __launch_bounds__(256)
void gemm_tf32(const float* __restrict__ A, int lda, const float* __restrict__ B, int ldb,
               const float* __restrict__ bias, float* __restrict__ C, int ldc,
               int M, int N, int K, int act) {
    __shared__ float As[2][128][20];
    __shared__ float Bs[2][16][136];
    const int bm = blockIdx.x * 128;
    const int bn = blockIdx.y * 128;
    const int tid = threadIdx.x;
    const int lane = tid & 31;
    const int warp = tid >> 5;
    const int g = lane >> 2, t = lane & 3;
    const int wm = (warp >> 1) * 32;
    const int wn = (warp & 1) * 64;

    float c[2][8][4];
#pragma unroll
    for (int i = 0; i < 2; i++)
#pragma unroll
        for (int j = 0; j < 8; j++)
#pragma unroll
            for (int l = 0; l < 4; l++) c[i][j][l] = 0.f;

    float4 ar[2], br[2];
    const float4 z4 = make_float4(0.f, 0.f, 0.f, 0.f);

    auto ldg = [&](int k0) {
#pragma unroll
        for (int l = 0; l < 2; l++) {
            int e = tid + l * 256;
            int m = e >> 2, k4 = (e & 3) * 4;
            int gm = bm + m;
            ar[l] = (gm < M) ? *(const float4*)&A[(size_t)gm * lda + k0 + k4] : z4;
            int kr = e >> 5, nc = (e & 31) * 4;
            int gc = bn + nc;
            br[l] = (gc < N) ? *(const float4*)&B[(size_t)(k0 + kr) * ldb + gc] : z4;
        }
    };
    auto sts = [&](int buf) {
#pragma unroll
        for (int l = 0; l < 2; l++) {
            int e = tid + l * 256;
            int m = e >> 2, k4 = (e & 3) * 4;
            float4 a4 = cvt_tf32_4(ar[l]);
            As[buf][m][k4 + 0] = a4.x;
            As[buf][m][k4 + 1] = a4.y;
            As[buf][m][k4 + 2] = a4.z;
            As[buf][m][k4 + 3] = a4.w;
            int kr = e >> 5, nc = (e & 31) * 4;
            *(float4*)&Bs[buf][kr][nc] = cvt_tf32_4(br[l]);
        }
    };
    auto compute = [&](int buf) {
#pragma unroll
        for (int kk = 0; kk < 2; kk++) {
            const int kb = kk * 8;
            unsigned a[2][4], b[8][2];
#pragma unroll
            for (int mt = 0; mt < 2; mt++) {
                int row = wm + mt * 16 + g;
                a[mt][0] = __float_as_uint(As[buf][row][kb + t]);
                a[mt][1] = __float_as_uint(As[buf][row + 8][kb + t]);
                a[mt][2] = __float_as_uint(As[buf][row][kb + t + 4]);
                a[mt][3] = __float_as_uint(As[buf][row + 8][kb + t + 4]);
            }
#pragma unroll
            for (int nt = 0; nt < 8; nt++) {
                int col = wn + nt * 8 + g;
                b[nt][0] = __float_as_uint(Bs[buf][kb + t][col]);
                b[nt][1] = __float_as_uint(Bs[buf][kb + t + 4][col]);
            }
#pragma unroll
            for (int mt = 0; mt < 2; mt++)
#pragma unroll
                for (int nt = 0; nt < 8; nt++) mma8(c[mt][nt], a[mt], b[nt]);
        }
    };

    const int iters = K >> 4;
    ldg(0);
    sts(0);
    __syncthreads();
    for (int it = 0; it < iters; it++) {
        int buf = it & 1;
        if (it + 1 < iters) ldg((it + 1) << 4);
        compute(buf);
        if (it + 1 < iters) sts(buf ^ 1);
        __syncthreads();
    }

#pragma unroll
    for (int mt = 0; mt < 2; mt++) {
#pragma unroll
        for (int h = 0; h < 2; h++) {
            int row = bm + wm + mt * 16 + g + h * 8;
            if (row >= M) continue;
#pragma unroll
            for (int nt = 0; nt < 8; nt++) {
                int col = bn + wn + nt * 8 + 2 * t;
                if (col >= N) continue;
                float v0 = c[mt][nt][h * 2 + 0];
                float v1 = c[mt][nt][h * 2 + 1];
                if (bias) { v0 += bias[col]; v1 += bias[col + 1]; }
                if (act == 2) { v0 = fmaxf(v0, 0.f); v1 = fmaxf(v1, 0.f); }
                *(float2*)&C[(size_t)row * ldc + col] = make_float2(v0, v1);
            }
        }
    }
}

// ---------------- stage 1 aux -------------------------------------------------
__global__ void build_BmainTh(const float* __restrict__ W, const float* __restrict__ Wroot) {
    int i = blockIdx.x * blockDim.x + threadIdx.x;  // over 1408*128
    if (i >= (NMSG + EDIM) * EDIM) return;
    int n = i >> 7, k = i & 127;
    int r = n >> 7, o = n & 127;
    float v = (r < NR) ? W[((size_t)r * EDIM + k) * EDIM + o] : Wroot[(size_t)k * EDIM + o];
    g_BmainTh[i] = __float2half_rn(v);
}

__global__ void scatter_main(const int* __restrict__ ei, const int* __restrict__ et) {
    int w = (blockIdx.x * blockDim.x + threadIdx.x) >> 5;
    int lane = threadIdx.x & 31;
    if (w >= NKG) return;
    int src = ei[w], dst = ei[NKG + w], r = et[w];
    uint2 u = *(const uint2*)(g_Ymsg + (size_t)src * NMSG + r * EDIM + lane * 4);
    float2 f0 = __half22float2(*(__half2*)&u.x);
    float2 f1 = __half22float2(*(__half2*)&u.y);
    red_add_v4(g_Yroot + (size_t)dst * EDIM + lane * 4, make_float4(f0.x, f0.y, f1.x, f1.y));
}

__global__ void tanh_root(const float* __restrict__ b) {
    int i = blockIdx.x * blockDim.x + threadIdx.x;  // float4 units
    if (i >= NE * (EDIM / 4)) return;
    int n = i >> 5, j = (i & 31) * 4;
    float4 v = *(const float4*)&g_Yroot[(size_t)n * EDIM + j];
    float4 bb = *(const float4*)&b[j];
    v.x = tanhf(v.x + bb.x);
    v.y = tanhf(v.y + bb.y);
    v.z = tanhf(v.z + bb.z);
    v.w = tanhf(v.w + bb.w);
    *(float4*)&g_E[(size_t)n * EDIM + j] = v;
    __half2* eh = (__half2*)&g_Eh[(size_t)n * EDIM + j];
    eh[0] = __floats2half2_rn(v.x, v.y);
    eh[1] = __floats2half2_rn(v.z, v.w);
}

// ---------------- stage 2 aux ---------------------------------------------------
__global__ void build_x(const int* __restrict__ h_idx, const int* __restrict__ r_idx,
                        const float* __restrict__ R) {
    int b = blockIdx.x, i = threadIdx.x;
    float v = g_E[(size_t)h_idx[b] * EDIM + i] * R[(size_t)r_idx[b] * EDIM + i];
    g_xh[b * EDIM + i] = __float2half_rn(v);
}

// ---------------- stage 3: metapath RGCNs (fp32 scratch aliases g_Ymsg) --------
__global__ void init_mp(float* __restrict__ mp, int m, const int* __restrict__ eids) {
    int n = blockIdx.x;
    float* row = mp + (size_t)m * NREG * KMP + (size_t)n * KMP;
    const float4* er = (const float4*)(g_E + (size_t)eids[n] * EDIM);
    const float4 z = make_float4(0.f, 0.f, 0.f, 0.f);
    for (int j = threadIdx.x; j < KMP / 4; j += blockDim.x)
        ((float4*)row)[j] = (j < (KMP - EDIM) / 4) ? z : er[j - (KMP - EDIM) / 4];
    if (blockIdx.x == 0 && threadIdx.x < 2) g_w[threadIdx.x] = 0.f;
}

__global__ void scatter_mp(float* __restrict__ mp, int m, const int* __restrict__ ei,
                           const int* __restrict__ et, const int* __restrict__ eids) {
    int w = (blockIdx.x * blockDim.x + threadIdx.x) >> 5;
    int lane = threadIdx.x & 31;
    if (w >= NMP_E) return;
    int dst = ei[NMP_E + w];
    if (dst >= NREG) return;  // output sliced [:NREG]
    int src = ei[w];
    int r = et[w];
    float4 v = *(const float4*)(g_E + (size_t)eids[src] * EDIM + lane * 4);
    red_add_v4(mp + (size_t)m * NREG * KMP + (size_t)dst * KMP + r * EDIM + lane * 4, v);
}

// ---------------- stage 4: semantic attention + head ---------------------------
__global__ void attn(const float* __restrict__ w1, const float* __restrict__ b1,
                     const float* __restrict__ w2) {
    int n = blockIdx.x, m = blockIdx.y, tid = threadIdx.x;
    __shared__ float z[HID];
    __shared__ float red[ATT];
    const float* zp = &g_sem[m][(size_t)n * HID];
    z[tid] = zp[tid];
    z[tid + 128] = zp[tid + 128];
    __syncthreads();
    float acc = b1[tid];
#pragma unroll 8
    for (int k = 0; k < HID; k++) acc = fmaf(z[k], w1[k * ATT + tid], acc);
    red[tid] = tanhf(acc) * w2[tid];
    __syncthreads();
    for (int s = 64; s > 0; s >>= 1) {
        if (tid < s) red[tid] += red[tid + s];
        __syncthreads();
    }
    if (tid == 0) atomicAdd(&g_w[m], red[0] * (1.0f / NREG));
}

__global__ void finalk(const float* __restrict__ predW, const float* __restrict__ predb,
                       float* __restrict__ out) {
    int n = blockIdx.x, tid = threadIdx.x;
    __shared__ float h[HID];
    float w0 = g_w[0], w1v = g_w[1];
    float mx = fmaxf(w0, w1v);
    float e0 = expf(w0 - mx), e1 = expf(w1v - mx);
    float inv = 1.f / (e0 + e1);
    float b0 = e0 * inv, b1 = e1 * inv;
    h[tid] = b0 * g_sem[0][(size_t)n * HID + tid] + b1 * g_sem[1][(size_t)n * HID + tid];
    h[tid + 128] =
        b0 * g_sem[0][(size_t)n * HID + tid + 128] + b1 * g_sem[1][(size_t)n * HID + tid + 128];
    __syncthreads();
    float acc = predb[tid] + g_E[(size_t)n * EDIM + tid];
#pragma unroll 8
    for (int k = 0; k < HID; k++) acc = fmaf(h[k], predW[k * EDIM + tid], acc);
    out[(size_t)n * EDIM + tid] = acc;
}

// ---------------- launch ------------------------------------------------------
extern "C" void kernel_launch(void* const* d_in, const int* in_sizes, int n_in,
                              void* d_out, int out_size) {
    const float* E_weight = (const float*)d_in[0];
    const float* R_weight = (const float*)d_in[1];
    const float* rgcn_W = (const float*)d_in[2];
    const float* rgcn_Wroot = (const float*)d_in[3];
    const float* rgcn_b = (const float*)d_in[4];
    const float* mp0_W = (const float*)d_in[5];
    const float* mp0_Wroot = (const float*)d_in[6];
    const float* mp0_b = (const float*)d_in[7];
    const float* mp1_W = (const float*)d_in[8];
    const float* mp1_Wroot = (const float*)d_in[9];
    const float* mp1_b = (const float*)d_in[10];
    const float* sa_w1 = (const float*)d_in[11];
    const float* sa_b1 = (const float*)d_in[12];
    const float* sa_w2 = (const float*)d_in[13];
    const float* pred_W = (const float*)d_in[14];
    const float* pred_b = (const float*)d_in[15];
    const int* h_idx = (const int*)d_in[16];
    const int* r_idx = (const int*)d_in[17];
    const int* edge_index = (const int*)d_in[18];
    const int* edge_type = (const int*)d_in[19];
    const int* mp0_ei = (const int*)d_in[20];
    const int* mp0_et = (const int*)d_in[21];
    const int* mp0_eids = (const int*)d_in[22];
    const int* mp1_ei = (const int*)d_in[23];
    const int* mp1_et = (const int*)d_in[24];
    const int* mp1_eids = (const int*)d_in[25];
    float* out = (float*)d_out;  // [E_reg 2000*128 | pred 1024*100000]

    float *pBmp, *psem;
    __half *pYmsg, *pEh, *pBmTh, *pxh;
    cudaGetSymbolAddress((void**)&pYmsg, g_Ymsg);
    cudaGetSymbolAddress((void**)&pBmp, g_Bmp);
    cudaGetSymbolAddress((void**)&psem, g_sem);
    cudaGetSymbolAddress((void**)&pEh, g_Eh);
    cudaGetSymbolAddress((void**)&pBmTh, g_BmainTh);
    cudaGetSymbolAddress((void**)&pxh, g_xh);
    float* pMp = (float*)pYmsg;  // fp32 metapath scratch aliases message buffer

    const int SMEM_STRIP = 3 * 128 * SPAD * (int)sizeof(__half);  // 104,448 B
    cudaFuncSetAttribute(gemm1_strip, cudaFuncAttributeMaxDynamicSharedMemorySize, SMEM_STRIP);
    cudaFuncSetAttribute(pred_strip, cudaFuncAttributeMaxDynamicSharedMemorySize, SMEM_STRIP);

    // --- main RGCN: strip GEMM -> fp16 msgs + fp32 root; scatter; tanh ---
    build_BmainTh<<<((NMSG + EDIM) * EDIM + 255) / 256, 256>>>(rgcn_W, rgcn_Wroot);
    gemm1_strip<<<(NE + 127) / 128, 256, SMEM_STRIP>>>(E_weight, pBmTh, NE);
    scatter_main<<<NKG / 8, 256>>>(edge_index, edge_type);
    tanh_root<<<(NE * (EDIM / 4) + 255) / 256, 256>>>(rgcn_b);

    // --- KGE pred = (E[h]*R[r]) @ E^T  (Eh tile resident per CTA) ---
    build_x<<<NB, EDIM>>>(h_idx, r_idx, R_weight);
    pred_strip<<<(NE + 127) / 128, 256, SMEM_STRIP>>>(pxh, pEh, out + NREG * EDIM, NE);

    // --- metapath RGCNs (rows < NREG) + relu ---
    init_mp<<<NREG, 128>>>(pMp, 0, mp0_eids);
    init_mp<<<NREG, 128>>>(pMp, 1, mp1_eids);
    cudaMemcpyAsync(pBmp, mp0_W, (size_t)NMP_REL * EDIM * HID * 4, cudaMemcpyDeviceToDevice);
    cudaMemcpyAsync(pBmp + NMP_REL * EDIM * HID, mp0_Wroot, (size_t)EDIM * HID * 4,
                    cudaMemcpyDeviceToDevice);
    cudaMemcpyAsync(pBmp + KMP * HID, mp1_W, (size_t)NMP_REL * EDIM * HID * 4,
                    cudaMemcpyDeviceToDevice);
    cudaMemcpyAsync(pBmp + KMP * HID + NMP_REL * EDIM * HID, mp1_Wroot, (size_t)EDIM * HID * 4,
                    cudaMemcpyDeviceToDevice);
    scatter_mp<<<NMP_E / 8, 256>>>(pMp, 0, mp0_ei, mp0_et, mp0_eids);
    scatter_mp<<<NMP_E / 8, 256>>>(pMp, 1, mp1_ei, mp1_et, mp1_eids);
    gemm_tf32<<<dim3((NREG + 127) / 128, HID / 128), 256>>>(
        pMp, KMP, pBmp, HID, mp0_b, psem, HID, NREG, HID, KMP, 2);
    gemm_tf32<<<dim3((NREG + 127) / 128, HID / 128), 256>>>(
        pMp + (size_t)NREG * KMP, KMP, pBmp + (size_t)KMP * HID, HID, mp1_b,
        psem + (size_t)NREG * HID, HID, NREG, HID, KMP, 2);

    // --- semantic attention + prediction head ---
    attn<<<dim3(NREG, 2), ATT>>>(sa_w1, sa_b1, sa_w2);
    finalk<<<NREG, EDIM>>>(pred_W, pred_b, out);
}

// round 6
// speedup vs baseline: 1.0413x; 1.0413x over previous
#include <cuda_runtime.h>
#include <cuda_fp16.h>
#include <math.h>
#include <stdint.h>

#define NE 100000
#define NR 10
#define EDIM 128
#define HID 256
#define NREG 2000
#define NKG 600000
#define NMP_REL 5
#define NMP_E 300000
#define NB 1024
#define ATT 128

#define NMSG (NR * EDIM)            /* 1280 message columns */
#define KMP (NMP_REL * EDIM + EDIM) /* 768 */

// ---------------- scratch ----------------------------------------------------
__device__ __half g_Ymsg[(size_t)NE * NMSG];  // fp16 messages (256MB); fp32 mp scratch alias
__device__ float g_Yroot[(size_t)NE * EDIM];  // fp32 root term + atomic accumulator
__device__ float g_E[(size_t)NE * EDIM];
__device__ __half g_Eh[(size_t)NE * EDIM];    // E fp16 (pred B operand)
__device__ __half g_BmainTh[(NMSG + EDIM) * EDIM];  // [n][k] fp16
__device__ float g_Bmp[2][KMP * HID];
__device__ __half g_xh[NB * EDIM];            // (E[h]*R[r]) fp16
__device__ float g_sem[2][NREG * HID];
__device__ float g_w[2];

// ---------------- primitives -------------------------------------------------
__device__ __forceinline__ void red_add_v4(float* addr, float4 v) {
    asm volatile("red.global.add.v4.f32 [%0], {%1, %2, %3, %4};"
                 :: "l"(addr), "f"(v.x), "f"(v.y), "f"(v.z), "f"(v.w) : "memory");
}
__device__ __forceinline__ void mma16816(float* c, const uint32_t* a, const uint32_t* b) {
    asm volatile(
        "mma.sync.aligned.m16n8k16.row.col.f32.f16.f16.f32 "
        "{%0,%1,%2,%3}, {%4,%5,%6,%7}, {%8,%9}, {%0,%1,%2,%3};"
        : "+f"(c[0]), "+f"(c[1]), "+f"(c[2]), "+f"(c[3])
        : "r"(a[0]), "r"(a[1]), "r"(a[2]), "r"(a[3]), "r"(b[0]), "r"(b[1]));
}
__device__ __forceinline__ float cvt_tf32(float x) {
    unsigned u;
    asm("cvt.rna.tf32.f32 %0, %1;" : "=r"(u) : "f"(x));
    return __uint_as_float(u);
}
__device__ __forceinline__ float4 cvt_tf32_4(float4 v) {
    return make_float4(cvt_tf32(v.x), cvt_tf32(v.y), cvt_tf32(v.z), cvt_tf32(v.w));
}
__device__ __forceinline__ void mma8(float* c, const unsigned* a, const unsigned* b) {
    asm volatile(
        "mma.sync.aligned.m16n8k8.row.col.f32.tf32.tf32.f32 "
        "{%0,%1,%2,%3}, {%4,%5,%6,%7}, {%8,%9}, {%0,%1,%2,%3};"
        : "+f"(c[0]), "+f"(c[1]), "+f"(c[2]), "+f"(c[3])
        : "r"(a[0]), "r"(a[1]), "r"(a[2]), "r"(a[3]), "r"(b[0]), "r"(b[1]));
}

// ---------------- fp16 K=128 MMA core -----------------------------------------
#define SPAD 136
typedef __half htile_t[SPAD];

__device__ __forceinline__ void compute_k128(const htile_t* As, const htile_t* Bs,
                                             float c[2][8][4], int wm, int wn, int g, int t) {
#pragma unroll
    for (int kb = 0; kb < 128; kb += 16) {
        uint32_t a[2][4], b[8][2];
#pragma unroll
        for (int mt = 0; mt < 2; mt++) {
            int row = wm + mt * 16 + g;
            a[mt][0] = *(const uint32_t*)&As[row][kb + 2 * t];
            a[mt][1] = *(const uint32_t*)&As[row + 8][kb + 2 * t];
            a[mt][2] = *(const uint32_t*)&As[row][kb + 2 * t + 8];
            a[mt][3] = *(const uint32_t*)&As[row + 8][kb + 2 * t + 8];
        }
#pragma unroll
        for (int nt = 0; nt < 8; nt++) {
            int col = wn + nt * 8 + g;
            b[nt][0] = *(const uint32_t*)&Bs[col][kb + 2 * t];
            b[nt][1] = *(const uint32_t*)&Bs[col][kb + 2 * t + 8];
        }
#pragma unroll
        for (int mt = 0; mt < 2; mt++)
#pragma unroll
            for (int nt = 0; nt < 8; nt++) mma16816(c[mt][nt], a[mt], b[nt]);
    }
}

// ---------------- GEMM1 (2D grid): Y = X[M,128](fp32) @ BmainTh[1408,128]^T ----
// blockIdx.y < 10 -> fp16 out to g_Ymsg; blockIdx.y == 10 -> fp32 out to g_Yroot
__global__ __launch_bounds__(256, 2)
void gemm1_k128(const float* __restrict__ A, const __half* __restrict__ Bt, int M) {
    extern __shared__ __half sm[];
    htile_t* As = (htile_t*)sm;
    htile_t* Bs = (htile_t*)(sm + 128 * SPAD);
    const int tid = threadIdx.x, lane = tid & 31, warp = tid >> 5;
    const int g = lane >> 2, t = lane & 3;
    const int wm = (warp >> 1) * 32, wn = (warp & 1) * 64;
    const int m0 = blockIdx.x * 128;
    const int by = blockIdx.y;
    const int arows = (M - m0 < 128) ? (M - m0) : 128;

    // A tile: fp32 -> fp16 into SMEM
    {
        const float4 zf = make_float4(0.f, 0.f, 0.f, 0.f);
#pragma unroll
        for (int l = 0; l < 16; l++) {
            int e = l * 256 + tid;
            int r = e >> 5, c4 = (e & 31) * 4;
            float4 v = (r < arows) ? *(const float4*)&A[(size_t)(m0 + r) * 128 + c4] : zf;
            __half2 h0 = __floats2half2_rn(v.x, v.y);
            __half2 h1 = __floats2half2_rn(v.z, v.w);
            *(uint2*)&As[r][c4] = make_uint2(*(uint32_t*)&h0, *(uint32_t*)&h1);
        }
    }
    // B tile: fp16
    {
#pragma unroll
        for (int l = 0; l < 8; l++) {
            int e = l * 256 + tid;
            int r = e >> 4, c8 = (e & 15) * 8;
            *(uint4*)&Bs[r][c8] = *(const uint4*)&Bt[(size_t)(by * 128 + r) * 128 + c8];
        }
    }
    __syncthreads();

    float c[2][8][4];
#pragma unroll
    for (int i = 0; i < 2; i++)
#pragma unroll
        for (int j = 0; j < 8; j++)
#pragma unroll
            for (int l = 0; l < 4; l++) c[i][j][l] = 0.f;
    compute_k128(As, Bs, c, wm, wn, g, t);

#pragma unroll
    for (int mt = 0; mt < 2; mt++) {
#pragma unroll
        for (int h = 0; h < 2; h++) {
            int row = m0 + wm + mt * 16 + g + h * 8;
            if (row >= M) continue;
            if (by < 10) {
                __half* cp = g_Ymsg + (size_t)row * NMSG + by * 128;
#pragma unroll
                for (int j = 0; j < 8; j++) {
                    int col = wn + j * 8 + 2 * t;
                    *(__half2*)(cp + col) =
                        __floats2half2_rn(c[mt][j][h * 2], c[mt][j][h * 2 + 1]);
                }
            } else {
                float* cp = g_Yroot + (size_t)row * 128;
#pragma unroll
                for (int j = 0; j < 8; j++) {
                    int col = wn + j * 8 + 2 * t;
                    *(float2*)(cp + col) = make_float2(c[mt][j][h * 2], c[mt][j][h * 2 + 1]);
                }
            }
        }
    }
}

// ---------------- pred (2D grid): C = Ah[M,128] @ Bt[N,128]^T (fp32 out) -------
__global__ __launch_bounds__(256, 2)
void gemm_f16_k128(const __half* __restrict__ A, const __half* __restrict__ Bt,
                   float* __restrict__ C, int M, int N, size_t ldc) {
    extern __shared__ __half sm[];
    htile_t* As = (htile_t*)sm;
    htile_t* Bs = (htile_t*)(sm + 128 * SPAD);
    const int tid = threadIdx.x, lane = tid & 31, warp = tid >> 5;
    const int g = lane >> 2, t = lane & 3;
    const int wm = (warp >> 1) * 32, wn = (warp & 1) * 64;
    const int m0 = blockIdx.x * 128, n0 = blockIdx.y * 128;

    const uint4 z = make_uint4(0, 0, 0, 0);
#pragma unroll
    for (int l = 0; l < 8; l++) {
        int e = l * 256 + tid;
        int r = e >> 4, c8 = (e & 15) * 8;
        uint4 va = z, vb = z;
        if (m0 + r < M) va = *(const uint4*)&A[(size_t)(m0 + r) * 128 + c8];
        if (n0 + r < N) vb = *(const uint4*)&Bt[(size_t)(n0 + r) * 128 + c8];
        *(uint4*)&As[r][c8] = va;
        *(uint4*)&Bs[r][c8] = vb;
    }
    __syncthreads();

    float c[2][8][4];
#pragma unroll
    for (int i = 0; i < 2; i++)
#pragma unroll
        for (int j = 0; j < 8; j++)
#pragma unroll
            for (int l = 0; l < 4; l++) c[i][j][l] = 0.f;
    compute_k128(As, Bs, c, wm, wn, g, t);

#pragma unroll
    for (int mt = 0; mt < 2; mt++) {
#pragma unroll
        for (int h = 0; h < 2; h++) {
            int row = m0 + wm + mt * 16 + g + h * 8;
            if (row >= M) continue;
#pragma unroll
            for (int nt = 0; nt < 8; nt++) {
                int col = n0 + wn + nt * 8 + 2 * t;
                if (col >= N) continue;
                *(float2*)&C[(size_t)row * ldc + col] =
                    make_float2(c[mt][nt][h * 2 + 0], c[mt][nt][h * 2 + 1]);
            }
        }
    }
}

// ---------------- tf32 mma GEMM (metapath GEMMs, K=768) ----------------------
__global__ __launch_bounds__(256)
void gemm_tf32(const float* __restrict__ A, int lda, const float* __restrict__ B, int ldb,
               const float* __restrict__ bias, float* __restrict__ C, int ldc,
               int M, int N, int K, int act) {
    __shared__ float As[2][128][20];
    __shared__ float Bs[2][16][136];
    const int bm = blockIdx.x * 128;
    const int bn = blockIdx.y * 128;
    const int tid = threadIdx.x;
    const int lane = tid & 31;
    const int warp = tid >> 5;
    const int g = lane >> 2, t = lane & 3;
    const int wm = (warp >> 1) * 32;
    const int wn = (warp & 1) * 64;

    float c[2][8][4];
#pragma unroll
    for (int i = 0; i < 2; i++)
#pragma unroll
        for (int j = 0; j < 8; j++)
#pragma unroll
            for (int l = 0; l < 4; l++) c[i][j][l] = 0.f;

    float4 ar[2], br[2];
    const float4 z4 = make_float4(0.f, 0.f, 0.f, 0.f);

    auto ldg = [&](int k0) {
#pragma unroll
        for (int l = 0; l < 2; l++) {
            int e = tid + l * 256;
            int m = e >> 2, k4 = (e & 3) * 4;
            int gm = bm + m;
            ar[l] = (gm < M) ? *(const float4*)&A[(size_t)gm * lda + k0 + k4] : z4;
            int kr = e >> 5, nc = (e & 31) * 4;
            int gc = bn + nc;
            br[l] = (gc < N) ? *(const float4*)&B[(size_t)(k0 + kr) * ldb + gc] : z4;
        }
    };
    auto sts = [&](int buf) {
#pragma unroll
        for (int l = 0; l < 2; l++) {
            int e = tid + l * 256;
            int m = e >> 2, k4 = (e & 3) * 4;
            float4 a4 = cvt_tf32_4(ar[l]);
            As[buf][m][k4 + 0] = a4.x;
            As[buf][m][k4 + 1] = a4.y;
            As[buf][m][k4 + 2] = a4.z;
            As[buf][m][k4 + 3] = a4.w;
            int kr = e >> 5, nc = (e & 31) * 4;
            *(float4*)&Bs[buf][kr][nc] = cvt_tf32_4(br[l]);
        }
    };
    auto compute = [&](int buf) {
#pragma unroll
        for (int kk = 0; kk < 2; kk++) {
            const int kb = kk * 8;
            unsigned a[2][4], b[8][2];
#pragma unroll
            for (int mt = 0; mt < 2; mt++) {
                int row = wm + mt * 16 + g;
                a[mt][0] = __float_as_uint(As[buf][row][kb + t]);
                a[mt][1] = __float_as_uint(As[buf][row + 8][kb + t]);
                a[mt][2] = __float_as_uint(As[buf][row][kb + t + 4]);
                a[mt][3] = __float_as_uint(As[buf][row + 8][kb + t + 4]);
            }
#pragma unroll
            for (int nt = 0; nt < 8; nt++) {
                int col = wn + nt * 8 + g;
                b[nt][0] = __float_as_uint(Bs[buf][kb + t][col]);
                b[nt][1] = __float_as_uint(Bs[buf][kb + t + 4][col]);
            }
#pragma unroll
            for (int mt = 0; mt < 2; mt++)
#pragma unroll
                for (int nt = 0; nt < 8; nt++) mma8(c[mt][nt], a[mt], b[nt]);
        }
    };

    const int iters = K >> 4;
    ldg(0);
    sts(0);
    __syncthreads();
    for (int it = 0; it < iters; it++) {
        int buf = it & 1;
        if (it + 1 < iters) ldg((it + 1) << 4);
        compute(buf);
        if (it + 1 < iters) sts(buf ^ 1);
        __syncthreads();
    }

#pragma unroll
    for (int mt = 0; mt < 2; mt++) {
#pragma unroll
        for (int h = 0; h < 2; h++) {
            int row = bm + wm + mt * 16 + g + h * 8;
            if (row >= M) continue;
#pragma unroll
            for (int nt = 0; nt < 8; nt++) {
                int col = bn + wn + nt * 8 + 2 * t;
                if (col >= N) continue;
                float v0 = c[mt][nt][h * 2 + 0];
                float v1 = c[mt][nt][h * 2 + 1];
                if (bias) { v0 += bias[col]; v1 += bias[col + 1]; }
                if (act == 2) { v0 = fmaxf(v0, 0.f); v1 = fmaxf(v1, 0.f); }
                *(float2*)&C[(size_t)row * ldc + col] = make_float2(v0, v1);
            }
        }
    }
}

// ---------------- stage 1 aux -------------------------------------------------
__global__ void build_BmainTh(const float* __restrict__ W, const float* __restrict__ Wroot) {
    int i = blockIdx.x * blockDim.x + threadIdx.x;  // over 1408*128
    if (i >= (NMSG + EDIM) * EDIM) return;
    int n = i >> 7, k = i & 127;
    int r = n >> 7, o = n & 127;
    float v = (r < NR) ? W[((size_t)r * EDIM + k) * EDIM + o] : Wroot[(size_t)k * EDIM + o];
    g_BmainTh[i] = __float2half_rn(v);
}

__global__ void scatter_main(const int* __restrict__ ei, const int* __restrict__ et) {
    int w = (blockIdx.x * blockDim.x + threadIdx.x) >> 5;
    int lane = threadIdx.x & 31;
    if (w >= NKG) return;
    int src = ei[w], dst = ei[NKG + w], r = et[w];
    uint2 u = *(const uint2*)(g_Ymsg + (size_t)src * NMSG + r * EDIM + lane * 4);
    float2 f0 = __half22float2(*(__half2*)&u.x);
    float2 f1 = __half22float2(*(__half2*)&u.y);
    red_add_v4(g_Yroot + (size_t)dst * EDIM + lane * 4, make_float4(f0.x, f0.y, f1.x, f1.y));
}

__global__ void tanh_root(const float* __restrict__ b) {
    int i = blockIdx.x * blockDim.x + threadIdx.x;  // float4 units
    if (i >= NE * (EDIM / 4)) return;
    int n = i >> 5, j = (i & 31) * 4;
    float4 v = *(const float4*)&g_Yroot[(size_t)n * EDIM + j];
    float4 bb = *(const float4*)&b[j];
    v.x = tanhf(v.x + bb.x);
    v.y = tanhf(v.y + bb.y);
    v.z = tanhf(v.z + bb.z);
    v.w = tanhf(v.w + bb.w);
    *(float4*)&g_E[(size_t)n * EDIM + j] = v;
    __half2* eh = (__half2*)&g_Eh[(size_t)n * EDIM + j];
    eh[0] = __floats2half2_rn(v.x, v.y);
    eh[1] = __floats2half2_rn(v.z, v.w);
}

// ---------------- stage 2 aux ---------------------------------------------------
__global__ void build_x(const int* __restrict__ h_idx, const int* __restrict__ r_idx,
                        const float* __restrict__ R) {
    int b = blockIdx.x, i = threadIdx.x;
    float v = g_E[(size_t)h_idx[b] * EDIM + i] * R[(size_t)r_idx[b] * EDIM + i];
    g_xh[b * EDIM + i] = __float2half_rn(v);
}

// ---------------- stage 3: metapath RGCNs (fp32 scratch aliases g_Ymsg) --------
__global__ void init_mp(float* __restrict__ mp, int m, const int* __restrict__ eids) {
    int n = blockIdx.x;
    float* row = mp + (size_t)m * NREG * KMP + (size_t)n * KMP;
    const float4* er = (const float4*)(g_E + (size_t)eids[n] * EDIM);
    const float4 z = make_float4(0.f, 0.f, 0.f, 0.f);
    for (int j = threadIdx.x; j < KMP / 4; j += blockDim.x)
        ((float4*)row)[j] = (j < (KMP - EDIM) / 4) ? z : er[j - (KMP - EDIM) / 4];
    if (blockIdx.x == 0 && threadIdx.x < 2) g_w[threadIdx.x] = 0.f;
}

__global__ void scatter_mp(float* __restrict__ mp, int m, const int* __restrict__ ei,
                           const int* __restrict__ et, const int* __restrict__ eids) {
    int w = (blockIdx.x * blockDim.x + threadIdx.x) >> 5;
    int lane = threadIdx.x & 31;
    if (w >= NMP_E) return;
    int dst = ei[NMP_E + w];
    if (dst >= NREG) return;  // output sliced [:NREG]
    int src = ei[w];
    int r = et[w];
    float4 v = *(const float4*)(g_E + (size_t)eids[src] * EDIM + lane * 4);
    red_add_v4(mp + (size_t)m * NREG * KMP + (size_t)dst * KMP + r * EDIM + lane * 4, v);
}

// ---------------- stage 4: semantic attention + head ---------------------------
__global__ void attn(const float* __restrict__ w1, const float* __restrict__ b1,
                     const float* __restrict__ w2) {
    int n = blockIdx.x, m = blockIdx.y, tid = threadIdx.x;
    __shared__ float z[HID];
    __shared__ float red[ATT];
    const float* zp = &g_sem[m][(size_t)n * HID];
    z[tid] = zp[tid];
    z[tid + 128] = zp[tid + 128];
    __syncthreads();
    float acc = b1[tid];
#pragma unroll 8
    for (int k = 0; k < HID; k++) acc = fmaf(z[k], w1[k * ATT + tid], acc);
    red[tid] = tanhf(acc) * w2[tid];
    __syncthreads();
    for (int s = 64; s > 0; s >>= 1) {
        if (tid < s) red[tid] += red[tid + s];
        __syncthreads();
    }
    if (tid == 0) atomicAdd(&g_w[m], red[0] * (1.0f / NREG));
}

__global__ void finalk(const float* __restrict__ predW, const float* __restrict__ predb,
                       float* __restrict__ out) {
    int n = blockIdx.x, tid = threadIdx.x;
    __shared__ float h[HID];
    float w0 = g_w[0], w1v = g_w[1];
    float mx = fmaxf(w0, w1v);
    float e0 = expf(w0 - mx), e1 = expf(w1v - mx);
    float inv = 1.f / (e0 + e1);
    float b0 = e0 * inv, b1 = e1 * inv;
    h[tid] = b0 * g_sem[0][(size_t)n * HID + tid] + b1 * g_sem[1][(size_t)n * HID + tid];
    h[tid + 128] =
        b0 * g_sem[0][(size_t)n * HID + tid + 128] + b1 * g_sem[1][(size_t)n * HID + tid + 128];
    __syncthreads();
    float acc = predb[tid] + g_E[(size_t)n * EDIM + tid];
#pragma unroll 8
    for (int k = 0; k < HID; k++) acc = fmaf(h[k], predW[k * EDIM + tid], acc);
    out[(size_t)n * EDIM + tid] = acc;
}

// ---------------- launch ------------------------------------------------------
extern "C" void kernel_launch(void* const* d_in, const int* in_sizes, int n_in,
                              void* d_out, int out_size) {
    const float* E_weight = (const float*)d_in[0];
    const float* R_weight = (const float*)d_in[1];
    const float* rgcn_W = (const float*)d_in[2];
    const float* rgcn_Wroot = (const float*)d_in[3];
    const float* rgcn_b = (const float*)d_in[4];
    const float* mp0_W = (const float*)d_in[5];
    const float* mp0_Wroot = (const float*)d_in[6];
    const float* mp0_b = (const float*)d_in[7];
    const float* mp1_W = (const float*)d_in[8];
    const float* mp1_Wroot = (const float*)d_in[9];
    const float* mp1_b = (const float*)d_in[10];
    const float* sa_w1 = (const float*)d_in[11];
    const float* sa_b1 = (const float*)d_in[12];
    const float* sa_w2 = (const float*)d_in[13];
    const float* pred_W = (const float*)d_in[14];
    const float* pred_b = (const float*)d_in[15];
    const int* h_idx = (const int*)d_in[16];
    const int* r_idx = (const int*)d_in[17];
    const int* edge_index = (const int*)d_in[18];
    const int* edge_type = (const int*)d_in[19];
    const int* mp0_ei = (const int*)d_in[20];
    const int* mp0_et = (const int*)d_in[21];
    const int* mp0_eids = (const int*)d_in[22];
    const int* mp1_ei = (const int*)d_in[23];
    const int* mp1_et = (const int*)d_in[24];
    const int* mp1_eids = (const int*)d_in[25];
    float* out = (float*)d_out;  // [E_reg 2000*128 | pred 1024*100000]

    float *pBmp, *psem;
    __half *pYmsg, *pEh, *pBmTh, *pxh;
    cudaGetSymbolAddress((void**)&pYmsg, g_Ymsg);
    cudaGetSymbolAddress((void**)&pBmp, g_Bmp);
    cudaGetSymbolAddress((void**)&psem, g_sem);
    cudaGetSymbolAddress((void**)&pEh, g_Eh);
    cudaGetSymbolAddress((void**)&pBmTh, g_BmainTh);
    cudaGetSymbolAddress((void**)&pxh, g_xh);
    float* pMp = (float*)pYmsg;  // fp32 metapath scratch aliases message buffer

    const int SMEM_F16 = 2 * 128 * SPAD * (int)sizeof(__half);  // 69,632 B
    cudaFuncSetAttribute(gemm1_k128, cudaFuncAttributeMaxDynamicSharedMemorySize, SMEM_F16);
    cudaFuncSetAttribute(gemm_f16_k128, cudaFuncAttributeMaxDynamicSharedMemorySize, SMEM_F16);

    // --- main RGCN: 2D GEMM (fp32 A converted in-kernel) -> fp16 msgs + fp32 root ---
    build_BmainTh<<<((NMSG + EDIM) * EDIM + 255) / 256, 256>>>(rgcn_W, rgcn_Wroot);
    gemm1_k128<<<dim3((NE + 127) / 128, 11), 256, SMEM_F16>>>(E_weight, pBmTh, NE);
    scatter_main<<<NKG / 8, 256>>>(edge_index, edge_type);
    tanh_root<<<(NE * (EDIM / 4) + 255) / 256, 256>>>(rgcn_b);

    // --- KGE pred = (E[h]*R[r]) @ E^T ---
    build_x<<<NB, EDIM>>>(h_idx, r_idx, R_weight);
    gemm_f16_k128<<<dim3(NB / 128, (NE + 127) / 128), 256, SMEM_F16>>>(
        pxh, pEh, out + NREG * EDIM, NB, NE, NE);

    // --- metapath RGCNs (rows < NREG) + relu ---
    init_mp<<<NREG, 128>>>(pMp, 0, mp0_eids);
    init_mp<<<NREG, 128>>>(pMp, 1, mp1_eids);
    cudaMemcpyAsync(pBmp, mp0_W, (size_t)NMP_REL * EDIM * HID * 4, cudaMemcpyDeviceToDevice);
    cudaMemcpyAsync(pBmp + NMP_REL * EDIM * HID, mp0_Wroot, (size_t)EDIM * HID * 4,
                    cudaMemcpyDeviceToDevice);
    cudaMemcpyAsync(pBmp + KMP * HID, mp1_W, (size_t)NMP_REL * EDIM * HID * 4,
                    cudaMemcpyDeviceToDevice);
    cudaMemcpyAsync(pBmp + KMP * HID + NMP_REL * EDIM * HID, mp1_Wroot, (size_t)EDIM * HID * 4,
                    cudaMemcpyDeviceToDevice);
    scatter_mp<<<NMP_E / 8, 256>>>(pMp, 0, mp0_ei, mp0_et, mp0_eids);
    scatter_mp<<<NMP_E / 8, 256>>>(pMp, 1, mp1_ei, mp1_et, mp1_eids);
    gemm_tf32<<<dim3((NREG + 127) / 128, HID / 128), 256>>>(
        pMp, KMP, pBmp, HID, mp0_b, psem, HID, NREG, HID, KMP, 2);
    gemm_tf32<<<dim3((NREG + 127) / 128, HID / 128), 256>>>(
        pMp + (size_t)NREG * KMP, KMP, pBmp + (size_t)KMP * HID, HID, mp1_b,
        psem + (size_t)NREG * HID, HID, NREG, HID, KMP, 2);

    // --- semantic attention + prediction head ---
    attn<<<dim3(NREG, 2), ATT>>>(sa_w1, sa_b1, sa_w2);
    finalk<<<NREG, EDIM>>>(pred_W, pred_b, out);
}

// round 7
// speedup vs baseline: 1.0465x; 1.0051x over previous
#include <cuda_runtime.h>
#include <cuda_fp16.h>
#include <math.h>
#include <stdint.h>

#define NE 100000
#define NR 10
#define EDIM 128
#define HID 256
#define NREG 2000
#define NKG 600000
#define NMP_REL 5
#define NMP_E 300000
#define NB 1024
#define ATT 128

#define NMSG (NR * EDIM)            /* 1280 message columns */
#define KMP (NMP_REL * EDIM + EDIM) /* 768 */

// ---------------- scratch ----------------------------------------------------
__device__ __half g_Ymsg[(size_t)NE * NMSG];  // fp16 messages (256MB); fp32 mp scratch alias
__device__ float g_Yroot[(size_t)NE * EDIM];  // fp32 root term + atomic accumulator
__device__ float g_E[(size_t)NE * EDIM];
__device__ __half g_Eh[(size_t)NE * EDIM];    // E fp16 (pred B operand)
__device__ __half g_BmainTh[(NMSG + EDIM) * EDIM];  // [n][k] fp16
__device__ float g_Bmp[2][KMP * HID];
__device__ __half g_xh[NB * EDIM];            // (E[h]*R[r]) fp16
__device__ float g_sem[2][NREG * HID];
__device__ float g_w[2];

// ---------------- primitives -------------------------------------------------
__device__ __forceinline__ void red_add_v4(float* addr, float4 v) {
    asm volatile("red.global.add.v4.f32 [%0], {%1, %2, %3, %4};"
                 :: "l"(addr), "f"(v.x), "f"(v.y), "f"(v.z), "f"(v.w) : "memory");
}
__device__ __forceinline__ void mma16816(float* c, const uint32_t* a, const uint32_t* b) {
    asm volatile(
        "mma.sync.aligned.m16n8k16.row.col.f32.f16.f16.f32 "
        "{%0,%1,%2,%3}, {%4,%5,%6,%7}, {%8,%9}, {%0,%1,%2,%3};"
        : "+f"(c[0]), "+f"(c[1]), "+f"(c[2]), "+f"(c[3])
        : "r"(a[0]), "r"(a[1]), "r"(a[2]), "r"(a[3]), "r"(b[0]), "r"(b[1]));
}
__device__ __forceinline__ void ldsm_x4(uint32_t& r0, uint32_t& r1, uint32_t& r2, uint32_t& r3,
                                        uint32_t addr) {
    asm volatile("ldmatrix.sync.aligned.m8n8.x4.shared.b16 {%0,%1,%2,%3}, [%4];"
                 : "=r"(r0), "=r"(r1), "=r"(r2), "=r"(r3) : "r"(addr));
}
__device__ __forceinline__ float cvt_tf32(float x) {
    unsigned u;
    asm("cvt.rna.tf32.f32 %0, %1;" : "=r"(u) : "f"(x));
    return __uint_as_float(u);
}
__device__ __forceinline__ float4 cvt_tf32_4(float4 v) {
    return make_float4(cvt_tf32(v.x), cvt_tf32(v.y), cvt_tf32(v.z), cvt_tf32(v.w));
}
__device__ __forceinline__ void mma8(float* c, const unsigned* a, const unsigned* b) {
    asm volatile(
        "mma.sync.aligned.m16n8k8.row.col.f32.tf32.tf32.f32 "
        "{%0,%1,%2,%3}, {%4,%5,%6,%7}, {%8,%9}, {%0,%1,%2,%3};"
        : "+f"(c[0]), "+f"(c[1]), "+f"(c[2]), "+f"(c[3])
        : "r"(a[0]), "r"(a[1]), "r"(a[2]), "r"(a[3]), "r"(b[0]), "r"(b[1]));
}

// ---------------- fp16 K=128 MMA core (ldmatrix-fed) ---------------------------
#define SPAD 136
typedef __half htile_t[SPAD];

// Per-k-step: 2 LDSM.x4 for A (2 m16k16 frags), 4 LDSM.x4 for B (8 n8k16 frags).
// Row stride 272B -> bank = 4*row mod 32 -> each 8-addr ldmatrix phase is
// conflict-free (banks 4r..4r+3 cover all 32 exactly once).
__device__ __forceinline__ void compute_k128(const htile_t* As, const htile_t* Bs,
                                             float c[2][8][4], int wm, int wn, int lane) {
    const int quad = lane >> 3, r = lane & 7;
    uint32_t aAddr[2], bAddr[4];
#pragma unroll
    for (int mt = 0; mt < 2; mt++)
        aAddr[mt] =
            (uint32_t)__cvta_generic_to_shared(&As[wm + mt * 16 + r + (quad & 1) * 8][(quad >> 1) * 8]);
#pragma unroll
    for (int p = 0; p < 4; p++)
        bAddr[p] =
            (uint32_t)__cvta_generic_to_shared(&Bs[wn + p * 16 + (quad >> 1) * 8 + r][(quad & 1) * 8]);

#pragma unroll
    for (int kb = 0; kb < 128; kb += 16) {
        uint32_t a[2][4], b[8][2];
#pragma unroll
        for (int mt = 0; mt < 2; mt++)
            ldsm_x4(a[mt][0], a[mt][1], a[mt][2], a[mt][3], aAddr[mt] + kb * 2);
#pragma unroll
        for (int p = 0; p < 4; p++)
            ldsm_x4(b[2 * p][0], b[2 * p][1], b[2 * p + 1][0], b[2 * p + 1][1], bAddr[p] + kb * 2);
#pragma unroll
        for (int mt = 0; mt < 2; mt++)
#pragma unroll
            for (int nt = 0; nt < 8; nt++) mma16816(c[mt][nt], a[mt], b[nt]);
    }
}

// ---------------- GEMM1 (2D grid): Y = X[M,128](fp32) @ BmainTh[1408,128]^T ----
// blockIdx.y < 10 -> fp16 out to g_Ymsg; blockIdx.y == 10 -> fp32 out to g_Yroot
__global__ __launch_bounds__(256, 2)
void gemm1_k128(const float* __restrict__ A, const __half* __restrict__ Bt, int M) {
    extern __shared__ __half sm[];
    htile_t* As = (htile_t*)sm;
    htile_t* Bs = (htile_t*)(sm + 128 * SPAD);
    const int tid = threadIdx.x, lane = tid & 31, warp = tid >> 5;
    const int g = lane >> 2, t = lane & 3;
    const int wm = (warp >> 1) * 32, wn = (warp & 1) * 64;
    const int m0 = blockIdx.x * 128;
    const int by = blockIdx.y;
    const int arows = (M - m0 < 128) ? (M - m0) : 128;

    // A tile: fp32 -> fp16 into SMEM
    {
        const float4 zf = make_float4(0.f, 0.f, 0.f, 0.f);
#pragma unroll
        for (int l = 0; l < 16; l++) {
            int e = l * 256 + tid;
            int r = e >> 5, c4 = (e & 31) * 4;
            float4 v = (r < arows) ? *(const float4*)&A[(size_t)(m0 + r) * 128 + c4] : zf;
            __half2 h0 = __floats2half2_rn(v.x, v.y);
            __half2 h1 = __floats2half2_rn(v.z, v.w);
            *(uint2*)&As[r][c4] = make_uint2(*(uint32_t*)&h0, *(uint32_t*)&h1);
        }
    }
    // B tile: fp16
    {
#pragma unroll
        for (int l = 0; l < 8; l++) {
            int e = l * 256 + tid;
            int r = e >> 4, c8 = (e & 15) * 8;
            *(uint4*)&Bs[r][c8] = *(const uint4*)&Bt[(size_t)(by * 128 + r) * 128 + c8];
        }
    }
    __syncthreads();

    float c[2][8][4];
#pragma unroll
    for (int i = 0; i < 2; i++)
#pragma unroll
        for (int j = 0; j < 8; j++)
#pragma unroll
            for (int l = 0; l < 4; l++) c[i][j][l] = 0.f;
    compute_k128(As, Bs, c, wm, wn, lane);

#pragma unroll
    for (int mt = 0; mt < 2; mt++) {
#pragma unroll
        for (int h = 0; h < 2; h++) {
            int row = m0 + wm + mt * 16 + g + h * 8;
            if (row >= M) continue;
            if (by < 10) {
                __half* cp = g_Ymsg + (size_t)row * NMSG + by * 128;
#pragma unroll
                for (int j = 0; j < 8; j++) {
                    int col = wn + j * 8 + 2 * t;
                    *(__half2*)(cp + col) =
                        __floats2half2_rn(c[mt][j][h * 2], c[mt][j][h * 2 + 1]);
                }
            } else {
                float* cp = g_Yroot + (size_t)row * 128;
#pragma unroll
                for (int j = 0; j < 8; j++) {
                    int col = wn + j * 8 + 2 * t;
                    *(float2*)(cp + col) = make_float2(c[mt][j][h * 2], c[mt][j][h * 2 + 1]);
                }
            }
        }
    }
}

// ---------------- pred (2D grid): C = Ah[M,128] @ Bt[N,128]^T (fp32 out) -------
__global__ __launch_bounds__(256, 2)
void gemm_f16_k128(const __half* __restrict__ A, const __half* __restrict__ Bt,
                   float* __restrict__ C, int M, int N, size_t ldc) {
    extern __shared__ __half sm[];
    htile_t* As = (htile_t*)sm;
    htile_t* Bs = (htile_t*)(sm + 128 * SPAD);
    const int tid = threadIdx.x, lane = tid & 31, warp = tid >> 5;
    const int g = lane >> 2, t = lane & 3;
    const int wm = (warp >> 1) * 32, wn = (warp & 1) * 64;
    const int m0 = blockIdx.x * 128, n0 = blockIdx.y * 128;

    const uint4 z = make_uint4(0, 0, 0, 0);
#pragma unroll
    for (int l = 0; l < 8; l++) {
        int e = l * 256 + tid;
        int r = e >> 4, c8 = (e & 15) * 8;
        uint4 va = z, vb = z;
        if (m0 + r < M) va = *(const uint4*)&A[(size_t)(m0 + r) * 128 + c8];
        if (n0 + r < N) vb = *(const uint4*)&Bt[(size_t)(n0 + r) * 128 + c8];
        *(uint4*)&As[r][c8] = va;
        *(uint4*)&Bs[r][c8] = vb;
    }
    __syncthreads();

    float c[2][8][4];
#pragma unroll
    for (int i = 0; i < 2; i++)
#pragma unroll
        for (int j = 0; j < 8; j++)
#pragma unroll
            for (int l = 0; l < 4; l++) c[i][j][l] = 0.f;
    compute_k128(As, Bs, c, wm, wn, lane);

#pragma unroll
    for (int mt = 0; mt < 2; mt++) {
#pragma unroll
        for (int h = 0; h < 2; h++) {
            int row = m0 + wm + mt * 16 + g + h * 8;
            if (row >= M) continue;
#pragma unroll
            for (int nt = 0; nt < 8; nt++) {
                int col = n0 + wn + nt * 8 + 2 * t;
                if (col >= N) continue;
                *(float2*)&C[(size_t)row * ldc + col] =
                    make_float2(c[mt][nt][h * 2 + 0], c[mt][nt][h * 2 + 1]);
            }
        }
    }
}

// ---------------- tf32 mma GEMM (metapath GEMMs, K=768) ----------------------
__global__ __launch_bounds__(256)
void gemm_tf32(const float* __restrict__ A, int lda, const float* __restrict__ B, int ldb,
               const float* __restrict__ bias, float* __restrict__ C, int ldc,
               int M, int N, int K, int act) {
    __shared__ float As[2][128][20];
    __shared__ float Bs[2][16][136];
    const int bm = blockIdx.x * 128;
    const int bn = blockIdx.y * 128;
    const int tid = threadIdx.x;
    const int lane = tid & 31;
    const int warp = tid >> 5;
    const int g = lane >> 2, t = lane & 3;
    const int wm = (warp >> 1) * 32;
    const int wn = (warp & 1) * 64;

    float c[2][8][4];
#pragma unroll
    for (int i = 0; i < 2; i++)
#pragma unroll
        for (int j = 0; j < 8; j++)
#pragma unroll
            for (int l = 0; l < 4; l++) c[i][j][l] = 0.f;

    float4 ar[2], br[2];
    const float4 z4 = make_float4(0.f, 0.f, 0.f, 0.f);

    auto ldg = [&](int k0) {
#pragma unroll
        for (int l = 0; l < 2; l++) {
            int e = tid + l * 256;
            int m = e >> 2, k4 = (e & 3) * 4;
            int gm = bm + m;
            ar[l] = (gm < M) ? *(const float4*)&A[(size_t)gm * lda + k0 + k4] : z4;
            int kr = e >> 5, nc = (e & 31) * 4;
            int gc = bn + nc;
            br[l] = (gc < N) ? *(const float4*)&B[(size_t)(k0 + kr) * ldb + gc] : z4;
        }
    };
    auto sts = [&](int buf) {
#pragma unroll
        for (int l = 0; l < 2; l++) {
            int e = tid + l * 256;
            int m = e >> 2, k4 = (e & 3) * 4;
            float4 a4 = cvt_tf32_4(ar[l]);
            As[buf][m][k4 + 0] = a4.x;
            As[buf][m][k4 + 1] = a4.y;
            As[buf][m][k4 + 2] = a4.z;
            As[buf][m][k4 + 3] = a4.w;
            int kr = e >> 5, nc = (e & 31) * 4;
            *(float4*)&Bs[buf][kr][nc] = cvt_tf32_4(br[l]);
        }
    };
    auto compute = [&](int buf) {
#pragma unroll
        for (int kk = 0; kk < 2; kk++) {
            const int kb = kk * 8;
            unsigned a[2][4], b[8][2];
#pragma unroll
            for (int mt = 0; mt < 2; mt++) {
                int row = wm + mt * 16 + g;
                a[mt][0] = __float_as_uint(As[buf][row][kb + t]);
                a[mt][1] = __float_as_uint(As[buf][row + 8][kb + t]);
                a[mt][2] = __float_as_uint(As[buf][row][kb + t + 4]);
                a[mt][3] = __float_as_uint(As[buf][row + 8][kb + t + 4]);
            }
#pragma unroll
            for (int nt = 0; nt < 8; nt++) {
                int col = wn + nt * 8 + g;
                b[nt][0] = __float_as_uint(Bs[buf][kb + t][col]);
                b[nt][1] = __float_as_uint(Bs[buf][kb + t + 4][col]);
            }
#pragma unroll
            for (int mt = 0; mt < 2; mt++)
#pragma unroll
                for (int nt = 0; nt < 8; nt++) mma8(c[mt][nt], a[mt], b[nt]);
        }
    };

    const int iters = K >> 4;
    ldg(0);
    sts(0);
    __syncthreads();
    for (int it = 0; it < iters; it++) {
        int buf = it & 1;
        if (it + 1 < iters) ldg((it + 1) << 4);
        compute(buf);
        if (it + 1 < iters) sts(buf ^ 1);
        __syncthreads();
    }

#pragma unroll
    for (int mt = 0; mt < 2; mt++) {
#pragma unroll
        for (int h = 0; h < 2; h++) {
            int row = bm + wm + mt * 16 + g + h * 8;
            if (row >= M) continue;
#pragma unroll
            for (int nt = 0; nt < 8; nt++) {
                int col = bn + wn + nt * 8 + 2 * t;
                if (col >= N) continue;
                float v0 = c[mt][nt][h * 2 + 0];
                float v1 = c[mt][nt][h * 2 + 1];
                if (bias) { v0 += bias[col]; v1 += bias[col + 1]; }
                if (act == 2) { v0 = fmaxf(v0, 0.f); v1 = fmaxf(v1, 0.f); }
                *(float2*)&C[(size_t)row * ldc + col] = make_float2(v0, v1);
            }
        }
    }
}

// ---------------- stage 1 aux -------------------------------------------------
__global__ void build_BmainTh(const float* __restrict__ W, const float* __restrict__ Wroot) {
    int i = blockIdx.x * blockDim.x + threadIdx.x;  // over 1408*128
    if (i >= (NMSG + EDIM) * EDIM) return;
    int n = i >> 7, k = i & 127;
    int r = n >> 7, o = n & 127;
    float v = (r < NR) ? W[((size_t)r * EDIM + k) * EDIM + o] : Wroot[(size_t)k * EDIM + o];
    g_BmainTh[i] = __float2half_rn(v);
}

__global__ void scatter_main(const int* __restrict__ ei, const int* __restrict__ et) {
    int w = (blockIdx.x * blockDim.x + threadIdx.x) >> 5;
    int lane = threadIdx.x & 31;
    if (w >= NKG) return;
    int src = ei[w], dst = ei[NKG + w], r = et[w];
    uint2 u = *(const uint2*)(g_Ymsg + (size_t)src * NMSG + r * EDIM + lane * 4);
    float2 f0 = __half22float2(*(__half2*)&u.x);
    float2 f1 = __half22float2(*(__half2*)&u.y);
    red_add_v4(g_Yroot + (size_t)dst * EDIM + lane * 4, make_float4(f0.x, f0.y, f1.x, f1.y));
}

__global__ void tanh_root(const float* __restrict__ b) {
    int i = blockIdx.x * blockDim.x + threadIdx.x;  // float4 units
    if (i >= NE * (EDIM / 4)) return;
    int n = i >> 5, j = (i & 31) * 4;
    float4 v = *(const float4*)&g_Yroot[(size_t)n * EDIM + j];
    float4 bb = *(const float4*)&b[j];
    v.x = tanhf(v.x + bb.x);
    v.y = tanhf(v.y + bb.y);
    v.z = tanhf(v.z + bb.z);
    v.w = tanhf(v.w + bb.w);
    *(float4*)&g_E[(size_t)n * EDIM + j] = v;
    __half2* eh = (__half2*)&g_Eh[(size_t)n * EDIM + j];
    eh[0] = __floats2half2_rn(v.x, v.y);
    eh[1] = __floats2half2_rn(v.z, v.w);
}

// ---------------- stage 2 aux ---------------------------------------------------
__global__ void build_x(const int* __restrict__ h_idx, const int* __restrict__ r_idx,
                        const float* __restrict__ R) {
    int b = blockIdx.x, i = threadIdx.x;
    float v = g_E[(size_t)h_idx[b] * EDIM + i] * R[(size_t)r_idx[b] * EDIM + i];
    g_xh[b * EDIM + i] = __float2half_rn(v);
}

// ---------------- stage 3: metapath RGCNs (fp32 scratch aliases g_Ymsg) --------
__global__ void init_mp(float* __restrict__ mp, int m, const int* __restrict__ eids) {
    int n = blockIdx.x;
    float* row = mp + (size_t)m * NREG * KMP + (size_t)n * KMP;
    const float4* er = (const float4*)(g_E + (size_t)eids[n] * EDIM);
    const float4 z = make_float4(0.f, 0.f, 0.f, 0.f);
    for (int j = threadIdx.x; j < KMP / 4; j += blockDim.x)
        ((float4*)row)[j] = (j < (KMP - EDIM) / 4) ? z : er[j - (KMP - EDIM) / 4];
    if (blockIdx.x == 0 && threadIdx.x < 2) g_w[threadIdx.x] = 0.f;
}

__global__ void scatter_mp(float* __restrict__ mp, int m, const int* __restrict__ ei,
                           const int* __restrict__ et, const int* __restrict__ eids) {
    int w = (blockIdx.x * blockDim.x + threadIdx.x) >> 5;
    int lane = threadIdx.x & 31;
    if (w >= NMP_E) return;
    int dst = ei[NMP_E + w];
    if (dst >= NREG) return;  // output sliced [:NREG]
    int src = ei[w];
    int r = et[w];
    float4 v = *(const float4*)(g_E + (size_t)eids[src] * EDIM + lane * 4);
    red_add_v4(mp + (size_t)m * NREG * KMP + (size_t)dst * KMP + r * EDIM + lane * 4, v);
}

// ---------------- stage 4: semantic attention + head ---------------------------
__global__ void attn(const float* __restrict__ w1, const float* __restrict__ b1,
                     const float* __restrict__ w2) {
    int n = blockIdx.x, m = blockIdx.y, tid = threadIdx.x;
    __shared__ float z[HID];
    __shared__ float red[ATT];
    const float* zp = &g_sem[m][(size_t)n * HID];
    z[tid] = zp[tid];
    z[tid + 128] = zp[tid + 128];
    __syncthreads();
    float acc = b1[tid];
#pragma unroll 8
    for (int k = 0; k < HID; k++) acc = fmaf(z[k], w1[k * ATT + tid], acc);
    red[tid] = tanhf(acc) * w2[tid];
    __syncthreads();
    for (int s = 64; s > 0; s >>= 1) {
        if (tid < s) red[tid] += red[tid + s];
        __syncthreads();
    }
    if (tid == 0) atomicAdd(&g_w[m], red[0] * (1.0f / NREG));
}

__global__ void finalk(const float* __restrict__ predW, const float* __restrict__ predb,
                       float* __restrict__ out) {
    int n = blockIdx.x, tid = threadIdx.x;
    __shared__ float h[HID];
    float w0 = g_w[0], w1v = g_w[1];
    float mx = fmaxf(w0, w1v);
    float e0 = expf(w0 - mx), e1 = expf(w1v - mx);
    float inv = 1.f / (e0 + e1);
    float b0 = e0 * inv, b1 = e1 * inv;
    h[tid] = b0 * g_sem[0][(size_t)n * HID + tid] + b1 * g_sem[1][(size_t)n * HID + tid];
    h[tid + 128] =
        b0 * g_sem[0][(size_t)n * HID + tid + 128] + b1 * g_sem[1][(size_t)n * HID + tid + 128];
    __syncthreads();
    float acc = predb[tid] + g_E[(size_t)n * EDIM + tid];
#pragma unroll 8
    for (int k = 0; k < HID; k++) acc = fmaf(h[k], predW[k * EDIM + tid], acc);
    out[(size_t)n * EDIM + tid] = acc;
}

// ---------------- launch ------------------------------------------------------
extern "C" void kernel_launch(void* const* d_in, const int* in_sizes, int n_in,
                              void* d_out, int out_size) {
    const float* E_weight = (const float*)d_in[0];
    const float* R_weight = (const float*)d_in[1];
    const float* rgcn_W = (const float*)d_in[2];
    const float* rgcn_Wroot = (const float*)d_in[3];
    const float* rgcn_b = (const float*)d_in[4];
    const float* mp0_W = (const float*)d_in[5];
    const float* mp0_Wroot = (const float*)d_in[6];
    const float* mp0_b = (const float*)d_in[7];
    const float* mp1_W = (const float*)d_in[8];
    const float* mp1_Wroot = (const float*)d_in[9];
    const float* mp1_b = (const float*)d_in[10];
    const float* sa_w1 = (const float*)d_in[11];
    const float* sa_b1 = (const float*)d_in[12];
    const float* sa_w2 = (const float*)d_in[13];
    const float* pred_W = (const float*)d_in[14];
    const float* pred_b = (const float*)d_in[15];
    const int* h_idx = (const int*)d_in[16];
    const int* r_idx = (const int*)d_in[17];
    const int* edge_index = (const int*)d_in[18];
    const int* edge_type = (const int*)d_in[19];
    const int* mp0_ei = (const int*)d_in[20];
    const int* mp0_et = (const int*)d_in[21];
    const int* mp0_eids = (const int*)d_in[22];
    const int* mp1_ei = (const int*)d_in[23];
    const int* mp1_et = (const int*)d_in[24];
    const int* mp1_eids = (const int*)d_in[25];
    float* out = (float*)d_out;  // [E_reg 2000*128 | pred 1024*100000]

    float *pBmp, *psem;
    __half *pYmsg, *pEh, *pBmTh, *pxh;
    cudaGetSymbolAddress((void**)&pYmsg, g_Ymsg);
    cudaGetSymbolAddress((void**)&pBmp, g_Bmp);
    cudaGetSymbolAddress((void**)&psem, g_sem);
    cudaGetSymbolAddress((void**)&pEh, g_Eh);
    cudaGetSymbolAddress((void**)&pBmTh, g_BmainTh);
    cudaGetSymbolAddress((void**)&pxh, g_xh);
    float* pMp = (float*)pYmsg;  // fp32 metapath scratch aliases message buffer

    const int SMEM_F16 = 2 * 128 * SPAD * (int)sizeof(__half);  // 69,632 B
    cudaFuncSetAttribute(gemm1_k128, cudaFuncAttributeMaxDynamicSharedMemorySize, SMEM_F16);
    cudaFuncSetAttribute(gemm_f16_k128, cudaFuncAttributeMaxDynamicSharedMemorySize, SMEM_F16);

    // --- main RGCN: 2D GEMM (fp32 A converted in-kernel) -> fp16 msgs + fp32 root ---
    build_BmainTh<<<((NMSG + EDIM) * EDIM + 255) / 256, 256>>>(rgcn_W, rgcn_Wroot);
    gemm1_k128<<<dim3((NE + 127) / 128, 11), 256, SMEM_F16>>>(E_weight, pBmTh, NE);
    scatter_main<<<NKG / 8, 256>>>(edge_index, edge_type);
    tanh_root<<<(NE * (EDIM / 4) + 255) / 256, 256>>>(rgcn_b);

    // --- KGE pred = (E[h]*R[r]) @ E^T ---
    build_x<<<NB, EDIM>>>(h_idx, r_idx, R_weight);
    gemm_f16_k128<<<dim3(NB / 128, (NE + 127) / 128), 256, SMEM_F16>>>(
        pxh, pEh, out + NREG * EDIM, NB, NE, NE);

    // --- metapath RGCNs (rows < NREG) + relu ---
    init_mp<<<NREG, 128>>>(pMp, 0, mp0_eids);
    init_mp<<<NREG, 128>>>(pMp, 1, mp1_eids);
    cudaMemcpyAsync(pBmp, mp0_W, (size_t)NMP_REL * EDIM * HID * 4, cudaMemcpyDeviceToDevice);
    cudaMemcpyAsync(pBmp + NMP_REL * EDIM * HID, mp0_Wroot, (size_t)EDIM * HID * 4,
                    cudaMemcpyDeviceToDevice);
    cudaMemcpyAsync(pBmp + KMP * HID, mp1_W, (size_t)NMP_REL * EDIM * HID * 4,
                    cudaMemcpyDeviceToDevice);
    cudaMemcpyAsync(pBmp + KMP * HID + NMP_REL * EDIM * HID, mp1_Wroot, (size_t)EDIM * HID * 4,
                    cudaMemcpyDeviceToDevice);
    scatter_mp<<<NMP_E / 8, 256>>>(pMp, 0, mp0_ei, mp0_et, mp0_eids);
    scatter_mp<<<NMP_E / 8, 256>>>(pMp, 1, mp1_ei, mp1_et, mp1_eids);
    gemm_tf32<<<dim3((NREG + 127) / 128, HID / 128), 256>>>(
        pMp, KMP, pBmp, HID, mp0_b, psem, HID, NREG, HID, KMP, 2);
    gemm_tf32<<<dim3((NREG + 127) / 128, HID / 128), 256>>>(
        pMp + (size_t)NREG * KMP, KMP, pBmp + (size_t)KMP * HID, HID, mp1_b,
        psem + (size_t)NREG * HID, HID, NREG, HID, KMP, 2);

    // --- semantic attention + prediction head ---
    attn<<<dim3(NREG, 2), ATT>>>(sa_w1, sa_b1, sa_w2);
    finalk<<<NREG, EDIM>>>(pred_W, pred_b, out);
}

// round 8
// speedup vs baseline: 1.0738x; 1.0260x over previous
#include <cuda_runtime.h>
#include <cuda_fp16.h>
#include <math.h>
#include <stdint.h>

#define NE 100000
#define NR 10
#define EDIM 128
#define HID 256
#define NREG 2000
#define NKG 600000
#define NMP_REL 5
#define NMP_E 300000
#define NB 1024
#define ATT 128

#define KMP (NMP_REL * EDIM + EDIM) /* 768 */
#define NCTA_E ((NKG + 1023) / 1024) /* 586 histogram CTAs */
#define TILES_CAP 4704               /* >= ceil((NKG + 10*127)/128) */

// ---------------- scratch ----------------------------------------------------
__device__ float g_Yroot[(size_t)(NE + 1) * EDIM];  // fp32 root + atomic accum (+dump row)
__device__ float g_E[(size_t)NE * EDIM];
__device__ __half g_Eh[(size_t)NE * EDIM];          // E fp16 (pred B operand)
__device__ __half g_BmainTh[(NR + 1) * EDIM * EDIM];  // [r][n][k] fp16 (+Wroot block)
__device__ float g_Bmp[2][KMP * HID];
__device__ __half g_xh[NB * EDIM];                  // (E[h]*R[r]) fp16
__device__ float g_mp[2][(size_t)NREG * KMP];       // metapath agg scratch
__device__ float g_sem[2][NREG * HID];
__device__ float g_w[2];
// edge bucketing
__device__ int2 g_esorted[TILES_CAP * 128];
__device__ int g_blockcnt[NCTA_E * 10];
__device__ int g_off[NCTA_E * 10];
__device__ int g_tiler[TILES_CAP];

// ---------------- primitives -------------------------------------------------
__device__ __forceinline__ void red_add_v4(float* addr, float4 v) {
    asm volatile("red.global.add.v4.f32 [%0], {%1, %2, %3, %4};"
                 :: "l"(addr), "f"(v.x), "f"(v.y), "f"(v.z), "f"(v.w) : "memory");
}
__device__ __forceinline__ void red_add_v2(float* addr, float x, float y) {
    asm volatile("red.global.add.v2.f32 [%0], {%1, %2};"
                 :: "l"(addr), "f"(x), "f"(y) : "memory");
}
__device__ __forceinline__ void mma16816(float* c, const uint32_t* a, const uint32_t* b) {
    asm volatile(
        "mma.sync.aligned.m16n8k16.row.col.f32.f16.f16.f32 "
        "{%0,%1,%2,%3}, {%4,%5,%6,%7}, {%8,%9}, {%0,%1,%2,%3};"
        : "+f"(c[0]), "+f"(c[1]), "+f"(c[2]), "+f"(c[3])
        : "r"(a[0]), "r"(a[1]), "r"(a[2]), "r"(a[3]), "r"(b[0]), "r"(b[1]));
}
__device__ __forceinline__ void ldsm_x4(uint32_t& r0, uint32_t& r1, uint32_t& r2, uint32_t& r3,
                                        uint32_t addr) {
    asm volatile("ldmatrix.sync.aligned.m8n8.x4.shared.b16 {%0,%1,%2,%3}, [%4];"
                 : "=r"(r0), "=r"(r1), "=r"(r2), "=r"(r3) : "r"(addr));
}
__device__ __forceinline__ float cvt_tf32(float x) {
    unsigned u;
    asm("cvt.rna.tf32.f32 %0, %1;" : "=r"(u) : "f"(x));
    return __uint_as_float(u);
}
__device__ __forceinline__ float4 cvt_tf32_4(float4 v) {
    return make_float4(cvt_tf32(v.x), cvt_tf32(v.y), cvt_tf32(v.z), cvt_tf32(v.w));
}
__device__ __forceinline__ void mma8(float* c, const unsigned* a, const unsigned* b) {
    asm volatile(
        "mma.sync.aligned.m16n8k8.row.col.f32.tf32.tf32.f32 "
        "{%0,%1,%2,%3}, {%4,%5,%6,%7}, {%8,%9}, {%0,%1,%2,%3};"
        : "+f"(c[0]), "+f"(c[1]), "+f"(c[2]), "+f"(c[3])
        : "r"(a[0]), "r"(a[1]), "r"(a[2]), "r"(a[3]), "r"(b[0]), "r"(b[1]));
}

// ---------------- fp16 K=128 MMA core (ldmatrix-fed) ---------------------------
#define SPAD 136
typedef __half htile_t[SPAD];

__device__ __forceinline__ void compute_k128(const htile_t* As, const htile_t* Bs,
                                             float c[2][8][4], int wm, int wn, int lane) {
    const int quad = lane >> 3, r = lane & 7;
    uint32_t aAddr[2], bAddr[4];
#pragma unroll
    for (int mt = 0; mt < 2; mt++)
        aAddr[mt] =
            (uint32_t)__cvta_generic_to_shared(&As[wm + mt * 16 + r + (quad & 1) * 8][(quad >> 1) * 8]);
#pragma unroll
    for (int p = 0; p < 4; p++)
        bAddr[p] =
            (uint32_t)__cvta_generic_to_shared(&Bs[wn + p * 16 + (quad >> 1) * 8 + r][(quad & 1) * 8]);

#pragma unroll
    for (int kb = 0; kb < 128; kb += 16) {
        uint32_t a[2][4], b[8][2];
#pragma unroll
        for (int mt = 0; mt < 2; mt++)
            ldsm_x4(a[mt][0], a[mt][1], a[mt][2], a[mt][3], aAddr[mt] + kb * 2);
#pragma unroll
        for (int p = 0; p < 4; p++)
            ldsm_x4(b[2 * p][0], b[2 * p][1], b[2 * p + 1][0], b[2 * p + 1][1], bAddr[p] + kb * 2);
#pragma unroll
        for (int mt = 0; mt < 2; mt++)
#pragma unroll
            for (int nt = 0; nt < 8; nt++) mma16816(c[mt][nt], a[mt], b[nt]);
    }
}

// ---------------- edge bucketing ----------------------------------------------
__global__ void edge_prefill() {
    int i = blockIdx.x * blockDim.x + threadIdx.x;
    if (i < TILES_CAP * 128) g_esorted[i] = make_int2(0, NE);
}

__global__ void edge_hist(const int* __restrict__ et) {
    __shared__ int cnt[10];
    int tid = threadIdx.x;
    if (tid < 10) cnt[tid] = 0;
    __syncthreads();
    int base = blockIdx.x * 1024;
    for (int i = tid; i < 1024; i += 256) {
        int e = base + i;
        if (e < NKG) atomicAdd(&cnt[et[e]], 1);
    }
    __syncthreads();
    if (tid < 10) g_blockcnt[blockIdx.x * 10 + tid] = cnt[tid];
}

__global__ void edge_prefix() {
    __shared__ int pc[10], ps[11];
    int tid = threadIdx.x;  // 64 threads
    if (tid < 10) {
        int s = 0;
        for (int c = 0; c < NCTA_E; c++) s += g_blockcnt[c * 10 + tid];
        pc[tid] = s;
    }
    __syncthreads();
    if (tid == 0) {
        int acc = 0;
        for (int r = 0; r < 10; r++) { ps[r] = acc; acc += ((pc[r] + 127) >> 7) << 7; }
        ps[10] = acc;
    }
    __syncthreads();
    if (tid < 10) {
        int acc = ps[tid];
        for (int c = 0; c < NCTA_E; c++) {
            g_off[c * 10 + tid] = acc;
            acc += g_blockcnt[c * 10 + tid];
        }
    }
    __syncthreads();
    for (int tIdx = tid; tIdx < TILES_CAP; tIdx += blockDim.x) {
        int pos = tIdx * 128;
        int r = 9;
        for (int q = 0; q < 10; q++)
            if (pos >= ps[q] && pos < ps[q + 1]) { r = q; break; }
        g_tiler[tIdx] = r;
    }
}

__global__ void edge_reorder(const int* __restrict__ ei, const int* __restrict__ et) {
    __shared__ int cur[10];
    int tid = threadIdx.x;
    if (tid < 10) cur[tid] = g_off[blockIdx.x * 10 + tid];
    __syncthreads();
    int base = blockIdx.x * 1024;
    for (int i = tid; i < 1024; i += 256) {
        int e = base + i;
        if (e < NKG) {
            int slot = atomicAdd(&cur[et[e]], 1);
            g_esorted[slot] = make_int2(ei[e], ei[NKG + e]);
        }
    }
}

// ---------------- gemm_root: Yroot = X[M,128](fp32) @ Wroot^T ------------------
__global__ __launch_bounds__(256, 2)
void gemm_root(const float* __restrict__ A, const __half* __restrict__ Bt, int M) {
    extern __shared__ __half sm[];
    htile_t* As = (htile_t*)sm;
    htile_t* Bs = (htile_t*)(sm + 128 * SPAD);
    const int tid = threadIdx.x, lane = tid & 31, warp = tid >> 5;
    const int g = lane >> 2, t = lane & 3;
    const int wm = (warp >> 1) * 32, wn = (warp & 1) * 64;
    const int m0 = blockIdx.x * 128;
    const int arows = (M - m0 < 128) ? (M - m0) : 128;

    {
        const float4 zf = make_float4(0.f, 0.f, 0.f, 0.f);
#pragma unroll
        for (int l = 0; l < 16; l++) {
            int e = l * 256 + tid;
            int r = e >> 5, c4 = (e & 31) * 4;
            float4 v = (r < arows) ? *(const float4*)&A[(size_t)(m0 + r) * 128 + c4] : zf;
            __half2 h0 = __floats2half2_rn(v.x, v.y);
            __half2 h1 = __floats2half2_rn(v.z, v.w);
            *(uint2*)&As[r][c4] = make_uint2(*(uint32_t*)&h0, *(uint32_t*)&h1);
        }
#pragma unroll
        for (int l = 0; l < 8; l++) {
            int e = l * 256 + tid;
            int r = e >> 4, c8 = (e & 15) * 8;
            *(uint4*)&Bs[r][c8] = *(const uint4*)&Bt[(size_t)(NR * 128 + r) * 128 + c8];
        }
    }
    __syncthreads();

    float c[2][8][4];
#pragma unroll
    for (int i = 0; i < 2; i++)
#pragma unroll
        for (int j = 0; j < 8; j++)
#pragma unroll
            for (int l = 0; l < 4; l++) c[i][j][l] = 0.f;
    compute_k128(As, Bs, c, wm, wn, lane);

#pragma unroll
    for (int mt = 0; mt < 2; mt++) {
#pragma unroll
        for (int h = 0; h < 2; h++) {
            int row = m0 + wm + mt * 16 + g + h * 8;
            if (row >= M) continue;
            float* cp = g_Yroot + (size_t)row * 128;
#pragma unroll
            for (int j = 0; j < 8; j++) {
                int col = wn + j * 8 + 2 * t;
                *(float2*)(cp + col) = make_float2(c[mt][j][h * 2], c[mt][j][h * 2 + 1]);
            }
        }
    }
}

// ---------------- gemm_edge: per 128-edge tile, Yroot[dst] += x[src] @ W_r -----
__global__ __launch_bounds__(256, 2)
void gemm_edge(const float* __restrict__ X, const __half* __restrict__ Bt) {
    extern __shared__ __half sm[];
    htile_t* As = (htile_t*)sm;
    htile_t* Bs = (htile_t*)(sm + 128 * SPAD);
    int* ssrc = (int*)(sm + 2 * 128 * SPAD);
    int* sdst = ssrc + 128;
    const int tid = threadIdx.x, lane = tid & 31, warp = tid >> 5;
    const int g = lane >> 2, t = lane & 3;
    const int wm = (warp >> 1) * 32, wn = (warp & 1) * 64;
    const int tile = blockIdx.x;

    if (tid < 128) {
        int2 rec = g_esorted[tile * 128 + tid];
        ssrc[tid] = rec.x;
        sdst[tid] = rec.y;
    }
    __syncthreads();

    const int r = g_tiler[tile];
    // B = W_r block [128n][128k]
    {
        const __half* Bp = Bt + (size_t)r * 128 * 128;
#pragma unroll
        for (int l = 0; l < 8; l++) {
            int e = l * 256 + tid;
            int rr = e >> 4, c8 = (e & 15) * 8;
            *(uint4*)&Bs[rr][c8] = *(const uint4*)&Bp[(size_t)rr * 128 + c8];
        }
    }
    // A = gathered x[src] rows (fp32 -> fp16)
#pragma unroll
    for (int l = 0; l < 16; l++) {
        int e = l * 256 + tid;
        int row = e >> 5, c4 = (e & 31) * 4;
        float4 v = *(const float4*)&X[(size_t)ssrc[row] * 128 + c4];
        __half2 h0 = __floats2half2_rn(v.x, v.y);
        __half2 h1 = __floats2half2_rn(v.z, v.w);
        *(uint2*)&As[row][c4] = make_uint2(*(uint32_t*)&h0, *(uint32_t*)&h1);
    }
    __syncthreads();

    float c[2][8][4];
#pragma unroll
    for (int i = 0; i < 2; i++)
#pragma unroll
        for (int j = 0; j < 8; j++)
#pragma unroll
            for (int l = 0; l < 4; l++) c[i][j][l] = 0.f;
    compute_k128(As, Bs, c, wm, wn, lane);

    // epilogue: atomic add rows into Yroot[dst]
#pragma unroll
    for (int mt = 0; mt < 2; mt++) {
#pragma unroll
        for (int h = 0; h < 2; h++) {
            int rowi = wm + mt * 16 + g + h * 8;
            float* bp = g_Yroot + (size_t)sdst[rowi] * 128;
#pragma unroll
            for (int nt = 0; nt < 8; nt++) {
                int col = wn + nt * 8 + 2 * t;
                red_add_v2(bp + col, c[mt][nt][h * 2], c[mt][nt][h * 2 + 1]);
            }
        }
    }
}

// ---------------- pred (2D grid): C = Ah[M,128] @ Bt[N,128]^T (fp32 out) -------
__global__ __launch_bounds__(256, 2)
void gemm_f16_k128(const __half* __restrict__ A, const __half* __restrict__ Bt,
                   float* __restrict__ C, int M, int N, size_t ldc) {
    extern __shared__ __half sm[];
    htile_t* As = (htile_t*)sm;
    htile_t* Bs = (htile_t*)(sm + 128 * SPAD);
    const int tid = threadIdx.x, lane = tid & 31, warp = tid >> 5;
    const int g = lane >> 2, t = lane & 3;
    const int wm = (warp >> 1) * 32, wn = (warp & 1) * 64;
    const int m0 = blockIdx.x * 128, n0 = blockIdx.y * 128;

    const uint4 z = make_uint4(0, 0, 0, 0);
#pragma unroll
    for (int l = 0; l < 8; l++) {
        int e = l * 256 + tid;
        int r = e >> 4, c8 = (e & 15) * 8;
        uint4 va = z, vb = z;
        if (m0 + r < M) va = *(const uint4*)&A[(size_t)(m0 + r) * 128 + c8];
        if (n0 + r < N) vb = *(const uint4*)&Bt[(size_t)(n0 + r) * 128 + c8];
        *(uint4*)&As[r][c8] = va;
        *(uint4*)&Bs[r][c8] = vb;
    }
    __syncthreads();

    float c[2][8][4];
#pragma unroll
    for (int i = 0; i < 2; i++)
#pragma unroll
        for (int j = 0; j < 8; j++)
#pragma unroll
            for (int l = 0; l < 4; l++) c[i][j][l] = 0.f;
    compute_k128(As, Bs, c, wm, wn, lane);

#pragma unroll
    for (int mt = 0; mt < 2; mt++) {
#pragma unroll
        for (int h = 0; h < 2; h++) {
            int row = m0 + wm + mt * 16 + g + h * 8;
            if (row >= M) continue;
#pragma unroll
            for (int nt = 0; nt < 8; nt++) {
                int col = n0 + wn + nt * 8 + 2 * t;
                if (col >= N) continue;
                *(float2*)&C[(size_t)row * ldc + col] =
                    make_float2(c[mt][nt][h * 2 + 0], c[mt][nt][h * 2 + 1]);
            }
        }
    }
}

// ---------------- tf32 mma GEMM (metapath GEMMs, K=768) ----------------------
__global__ __launch_bounds__(256)
void gemm_tf32(const float* __restrict__ A, int lda, const float* __restrict__ B, int ldb,
               const float* __restrict__ bias, float* __restrict__ C, int ldc,
               int M, int N, int K, int act) {
    __shared__ float As[2][128][20];
    __shared__ float Bs[2][16][136];
    const int bm = blockIdx.x * 128;
    const int bn = blockIdx.y * 128;
    const int tid = threadIdx.x;
    const int lane = tid & 31;
    const int warp = tid >> 5;
    const int g = lane >> 2, t = lane & 3;
    const int wm = (warp >> 1) * 32;
    const int wn = (warp & 1) * 64;

    float c[2][8][4];
#pragma unroll
    for (int i = 0; i < 2; i++)
#pragma unroll
        for (int j = 0; j < 8; j++)
#pragma unroll
            for (int l = 0; l < 4; l++) c[i][j][l] = 0.f;

    float4 ar[2], br[2];
    const float4 z4 = make_float4(0.f, 0.f, 0.f, 0.f);

    auto ldg = [&](int k0) {
#pragma unroll
        for (int l = 0; l < 2; l++) {
            int e = tid + l * 256;
            int m = e >> 2, k4 = (e & 3) * 4;
            int gm = bm + m;
            ar[l] = (gm < M) ? *(const float4*)&A[(size_t)gm * lda + k0 + k4] : z4;
            int kr = e >> 5, nc = (e & 31) * 4;
            int gc = bn + nc;
            br[l] = (gc < N) ? *(const float4*)&B[(size_t)(k0 + kr) * ldb + gc] : z4;
        }
    };
    auto sts = [&](int buf) {
#pragma unroll
        for (int l = 0; l < 2; l++) {
            int e = tid + l * 256;
            int m = e >> 2, k4 = (e & 3) * 4;
            float4 a4 = cvt_tf32_4(ar[l]);
            As[buf][m][k4 + 0] = a4.x;
            As[buf][m][k4 + 1] = a4.y;
            As[buf][m][k4 + 2] = a4.z;
            As[buf][m][k4 + 3] = a4.w;
            int kr = e >> 5, nc = (e & 31) * 4;
            *(float4*)&Bs[buf][kr][nc] = cvt_tf32_4(br[l]);
        }
    };
    auto compute = [&](int buf) {
#pragma unroll
        for (int kk = 0; kk < 2; kk++) {
            const int kb = kk * 8;
            unsigned a[2][4], b[8][2];
#pragma unroll
            for (int mt = 0; mt < 2; mt++) {
                int row = wm + mt * 16 + g;
                a[mt][0] = __float_as_uint(As[buf][row][kb + t]);
                a[mt][1] = __float_as_uint(As[buf][row + 8][kb + t]);
                a[mt][2] = __float_as_uint(As[buf][row][kb + t + 4]);
                a[mt][3] = __float_as_uint(As[buf][row + 8][kb + t + 4]);
            }
#pragma unroll
            for (int nt = 0; nt < 8; nt++) {
                int col = wn + nt * 8 + g;
                b[nt][0] = __float_as_uint(Bs[buf][kb + t][col]);
                b[nt][1] = __float_as_uint(Bs[buf][kb + t + 4][col]);
            }
#pragma unroll
            for (int mt = 0; mt < 2; mt++)
#pragma unroll
                for (int nt = 0; nt < 8; nt++) mma8(c[mt][nt], a[mt], b[nt]);
        }
    };

    const int iters = K >> 4;
    ldg(0);
    sts(0);
    __syncthreads();
    for (int it = 0; it < iters; it++) {
        int buf = it & 1;
        if (it + 1 < iters) ldg((it + 1) << 4);
        compute(buf);
        if (it + 1 < iters) sts(buf ^ 1);
        __syncthreads();
    }

#pragma unroll
    for (int mt = 0; mt < 2; mt++) {
#pragma unroll
        for (int h = 0; h < 2; h++) {
            int row = bm + wm + mt * 16 + g + h * 8;
            if (row >= M) continue;
#pragma unroll
            for (int nt = 0; nt < 8; nt++) {
                int col = bn + wn + nt * 8 + 2 * t;
                if (col >= N) continue;
                float v0 = c[mt][nt][h * 2 + 0];
                float v1 = c[mt][nt][h * 2 + 1];
                if (bias) { v0 += bias[col]; v1 += bias[col + 1]; }
                if (act == 2) { v0 = fmaxf(v0, 0.f); v1 = fmaxf(v1, 0.f); }
                *(float2*)&C[(size_t)row * ldc + col] = make_float2(v0, v1);
            }
        }
    }
}

// ---------------- stage 1 aux -------------------------------------------------
__global__ void build_BmainTh(const float* __restrict__ W, const float* __restrict__ Wroot) {
    int i = blockIdx.x * blockDim.x + threadIdx.x;  // over 1408*128 (n-major, k minor)
    if (i >= (NR + 1) * EDIM * EDIM) return;
    int n = i >> 7, k = i & 127;
    int r = n >> 7, o = n & 127;
    float v = (r < NR) ? W[((size_t)r * EDIM + k) * EDIM + o] : Wroot[(size_t)k * EDIM + o];
    g_BmainTh[i] = __float2half_rn(v);
}

__global__ void tanh_root(const float* __restrict__ b) {
    int i = blockIdx.x * blockDim.x + threadIdx.x;  // float4 units
    if (i >= NE * (EDIM / 4)) return;
    int n = i >> 5, j = (i & 31) * 4;
    float4 v = *(const float4*)&g_Yroot[(size_t)n * EDIM + j];
    float4 bb = *(const float4*)&b[j];
    v.x = tanhf(v.x + bb.x);
    v.y = tanhf(v.y + bb.y);
    v.z = tanhf(v.z + bb.z);
    v.w = tanhf(v.w + bb.w);
    *(float4*)&g_E[(size_t)n * EDIM + j] = v;
    __half2* eh = (__half2*)&g_Eh[(size_t)n * EDIM + j];
    eh[0] = __floats2half2_rn(v.x, v.y);
    eh[1] = __floats2half2_rn(v.z, v.w);
}

// ---------------- stage 2 aux ---------------------------------------------------
__global__ void build_x(const int* __restrict__ h_idx, const int* __restrict__ r_idx,
                        const float* __restrict__ R) {
    int b = blockIdx.x, i = threadIdx.x;
    float v = g_E[(size_t)h_idx[b] * EDIM + i] * R[(size_t)r_idx[b] * EDIM + i];
    g_xh[b * EDIM + i] = __float2half_rn(v);
}

// ---------------- stage 3: metapath RGCNs --------------------------------------
__global__ void init_mp(int m, const int* __restrict__ eids) {
    int n = blockIdx.x;
    float* row = g_mp[m] + (size_t)n * KMP;
    const float4* er = (const float4*)(g_E + (size_t)eids[n] * EDIM);
    const float4 z = make_float4(0.f, 0.f, 0.f, 0.f);
    for (int j = threadIdx.x; j < KMP / 4; j += blockDim.x)
        ((float4*)row)[j] = (j < (KMP - EDIM) / 4) ? z : er[j - (KMP - EDIM) / 4];
    if (blockIdx.x == 0 && threadIdx.x < 2) g_w[threadIdx.x] = 0.f;
}

__global__ void scatter_mp(int m, const int* __restrict__ ei, const int* __restrict__ et,
                           const int* __restrict__ eids) {
    int w = (blockIdx.x * blockDim.x + threadIdx.x) >> 5;
    int lane = threadIdx.x & 31;
    if (w >= NMP_E) return;
    int dst = ei[NMP_E + w];
    if (dst >= NREG) return;  // output sliced [:NREG]
    int src = ei[w];
    int r = et[w];
    float4 v = *(const float4*)(g_E + (size_t)eids[src] * EDIM + lane * 4);
    red_add_v4(g_mp[m] + (size_t)dst * KMP + r * EDIM + lane * 4, v);
}

// ---------------- stage 4: semantic attention + head ---------------------------
__global__ void attn(const float* __restrict__ w1, const float* __restrict__ b1,
                     const float* __restrict__ w2) {
    int n = blockIdx.x, m = blockIdx.y, tid = threadIdx.x;
    __shared__ float z[HID];
    __shared__ float red[ATT];
    const float* zp = &g_sem[m][(size_t)n * HID];
    z[tid] = zp[tid];
    z[tid + 128] = zp[tid + 128];
    __syncthreads();
    float acc = b1[tid];
#pragma unroll 8
    for (int k = 0; k < HID; k++) acc = fmaf(z[k], w1[k * ATT + tid], acc);
    red[tid] = tanhf(acc) * w2[tid];
    __syncthreads();
    for (int s = 64; s > 0; s >>= 1) {
        if (tid < s) red[tid] += red[tid + s];
        __syncthreads();
    }
    if (tid == 0) atomicAdd(&g_w[m], red[0] * (1.0f / NREG));
}

__global__ void finalk(const float* __restrict__ predW, const float* __restrict__ predb,
                       float* __restrict__ out) {
    int n = blockIdx.x, tid = threadIdx.x;
    __shared__ float h[HID];
    float w0 = g_w[0], w1v = g_w[1];
    float mx = fmaxf(w0, w1v);
    float e0 = expf(w0 - mx), e1 = expf(w1v - mx);
    float inv = 1.f / (e0 + e1);
    float b0 = e0 * inv, b1 = e1 * inv;
    h[tid] = b0 * g_sem[0][(size_t)n * HID + tid] + b1 * g_sem[1][(size_t)n * HID + tid];
    h[tid + 128] =
        b0 * g_sem[0][(size_t)n * HID + tid + 128] + b1 * g_sem[1][(size_t)n * HID + tid + 128];
    __syncthreads();
    float acc = predb[tid] + g_E[(size_t)n * EDIM + tid];
#pragma unroll 8
    for (int k = 0; k < HID; k++) acc = fmaf(h[k], predW[k * EDIM + tid], acc);
    out[(size_t)n * EDIM + tid] = acc;
}

// ---------------- launch ------------------------------------------------------
extern "C" void kernel_launch(void* const* d_in, const int* in_sizes, int n_in,
                              void* d_out, int out_size) {
    const float* E_weight = (const float*)d_in[0];
    const float* R_weight = (const float*)d_in[1];
    const float* rgcn_W = (const float*)d_in[2];
    const float* rgcn_Wroot = (const float*)d_in[3];
    const float* rgcn_b = (const float*)d_in[4];
    const float* mp0_W = (const float*)d_in[5];
    const float* mp0_Wroot = (const float*)d_in[6];
    const float* mp0_b = (const float*)d_in[7];
    const float* mp1_W = (const float*)d_in[8];
    const float* mp1_Wroot = (const float*)d_in[9];
    const float* mp1_b = (const float*)d_in[10];
    const float* sa_w1 = (const float*)d_in[11];
    const float* sa_b1 = (const float*)d_in[12];
    const float* sa_w2 = (const float*)d_in[13];
    const float* pred_W = (const float*)d_in[14];
    const float* pred_b = (const float*)d_in[15];
    const int* h_idx = (const int*)d_in[16];
    const int* r_idx = (const int*)d_in[17];
    const int* edge_index = (const int*)d_in[18];
    const int* edge_type = (const int*)d_in[19];
    const int* mp0_ei = (const int*)d_in[20];
    const int* mp0_et = (const int*)d_in[21];
    const int* mp0_eids = (const int*)d_in[22];
    const int* mp1_ei = (const int*)d_in[23];
    const int* mp1_et = (const int*)d_in[24];
    const int* mp1_eids = (const int*)d_in[25];
    float* out = (float*)d_out;  // [E_reg 2000*128 | pred 1024*100000]

    float *pBmp, *psem, *pmp;
    __half *pEh, *pBmTh, *pxh;
    cudaGetSymbolAddress((void**)&pBmp, g_Bmp);
    cudaGetSymbolAddress((void**)&psem, g_sem);
    cudaGetSymbolAddress((void**)&pmp, g_mp);
    cudaGetSymbolAddress((void**)&pEh, g_Eh);
    cudaGetSymbolAddress((void**)&pBmTh, g_BmainTh);
    cudaGetSymbolAddress((void**)&pxh, g_xh);

    const int SMEM_F16 = 2 * 128 * SPAD * (int)sizeof(__half);           // 69,632 B
    const int SMEM_EDGE = SMEM_F16 + 2 * 128 * (int)sizeof(int);         // + src/dst
    cudaFuncSetAttribute(gemm_root, cudaFuncAttributeMaxDynamicSharedMemorySize, SMEM_F16);
    cudaFuncSetAttribute(gemm_edge, cudaFuncAttributeMaxDynamicSharedMemorySize, SMEM_EDGE);
    cudaFuncSetAttribute(gemm_f16_k128, cudaFuncAttributeMaxDynamicSharedMemorySize, SMEM_F16);

    // --- edge bucketing (by relation, 128-padded segments) ---
    edge_prefill<<<(TILES_CAP * 128 + 255) / 256, 256>>>();
    build_BmainTh<<<((NR + 1) * EDIM * EDIM + 255) / 256, 256>>>(rgcn_W, rgcn_Wroot);
    edge_hist<<<NCTA_E, 256>>>(edge_type);
    edge_prefix<<<1, 64>>>();
    edge_reorder<<<NCTA_E, 256>>>(edge_index, edge_type);

    // --- main RGCN: root GEMM, then fused edge-GEMM with atomic scatter ---
    gemm_root<<<(NE + 127) / 128, 256, SMEM_F16>>>(E_weight, pBmTh, NE);
    gemm_edge<<<TILES_CAP, 256, SMEM_EDGE>>>(E_weight, pBmTh);
    tanh_root<<<(NE * (EDIM / 4) + 255) / 256, 256>>>(rgcn_b);

    // --- KGE pred = (E[h]*R[r]) @ E^T ---
    build_x<<<NB, EDIM>>>(h_idx, r_idx, R_weight);
    gemm_f16_k128<<<dim3(NB / 128, (NE + 127) / 128), 256, SMEM_F16>>>(
        pxh, pEh, out + NREG * EDIM, NB, NE, NE);

    // --- metapath RGCNs (rows < NREG) + relu ---
    init_mp<<<NREG, 128>>>(0, mp0_eids);
    init_mp<<<NREG, 128>>>(1, mp1_eids);
    cudaMemcpyAsync(pBmp, mp0_W, (size_t)NMP_REL * EDIM * HID * 4, cudaMemcpyDeviceToDevice);
    cudaMemcpyAsync(pBmp + NMP_REL * EDIM * HID, mp0_Wroot, (size_t)EDIM * HID * 4,
                    cudaMemcpyDeviceToDevice);
    cudaMemcpyAsync(pBmp + KMP * HID, mp1_W, (size_t)NMP_REL * EDIM * HID * 4,
                    cudaMemcpyDeviceToDevice);
    cudaMemcpyAsync(pBmp + KMP * HID + NMP_REL * EDIM * HID, mp1_Wroot, (size_t)EDIM * HID * 4,
                    cudaMemcpyDeviceToDevice);
    scatter_mp<<<NMP_E / 8, 256>>>(0, mp0_ei, mp0_et, mp0_eids);
    scatter_mp<<<NMP_E / 8, 256>>>(1, mp1_ei, mp1_et, mp1_eids);
    gemm_tf32<<<dim3((NREG + 127) / 128, HID / 128), 256>>>(
        pmp, KMP, pBmp, HID, mp0_b, psem, HID, NREG, HID, KMP, 2);
    gemm_tf32<<<dim3((NREG + 127) / 128, HID / 128), 256>>>(
        pmp + (size_t)NREG * KMP, KMP, pBmp + (size_t)KMP * HID, HID, mp1_b,
        psem + (size_t)NREG * HID, HID, NREG, HID, KMP, 2);

    // --- semantic attention + prediction head ---
    attn<<<dim3(NREG, 2), ATT>>>(sa_w1, sa_b1, sa_w2);
    finalk<<<NREG, EDIM>>>(pred_W, pred_b, out);
}

// round 9
// speedup vs baseline: 1.1139x; 1.0373x over previous
#include <cuda_runtime.h>
#include <cuda_fp16.h>
#include <math.h>
#include <stdint.h>

#define NE 100000
#define NR 10
#define EDIM 128
#define HID 256
#define NREG 2000
#define NKG 600000
#define NMP_REL 5
#define NMP_E 300000
#define NB 1024
#define ATT 128

#define KMP (NMP_REL * EDIM + EDIM) /* 768 */
#define NCTA_E ((NKG + 1023) / 1024) /* 586 histogram CTAs */
#define TILES_CAP 4704               /* >= ceil((NKG + 10*127)/128) */

// ---------------- scratch ----------------------------------------------------
__device__ float g_Yroot[(size_t)(NE + 1) * EDIM];  // fp32 root + atomic accum (+dump row)
__device__ float g_E[(size_t)NE * EDIM];
__device__ __half g_Eh[(size_t)NE * EDIM];          // E fp16 (pred B operand)
__device__ __half g_BmainTh[(NR + 1) * EDIM * EDIM];  // [r][n][k] fp16 (+Wroot block)
__device__ float g_Bmp[2][KMP * HID];
__device__ __half g_xh[NB * EDIM];                  // (E[h]*R[r]) fp16
__device__ float g_mp[2][(size_t)NREG * KMP];       // metapath agg scratch
__device__ float g_sem[2][NREG * HID];
__device__ float g_w[2];
// edge bucketing
__device__ int2 g_esorted[TILES_CAP * 128];
__device__ int g_blockcnt[NCTA_E * 10];
__device__ int g_off[NCTA_E * 10];
__device__ int g_tiler[TILES_CAP];

// ---------------- primitives -------------------------------------------------
__device__ __forceinline__ void red_add_v4(float* addr, float4 v) {
    asm volatile("red.global.add.v4.f32 [%0], {%1, %2, %3, %4};"
                 :: "l"(addr), "f"(v.x), "f"(v.y), "f"(v.z), "f"(v.w) : "memory");
}
__device__ __forceinline__ void red_add_v2(float* addr, float x, float y) {
    asm volatile("red.global.add.v2.f32 [%0], {%1, %2};"
                 :: "l"(addr), "f"(x), "f"(y) : "memory");
}
__device__ __forceinline__ void mma16816(float* c, const uint32_t* a, const uint32_t* b) {
    asm volatile(
        "mma.sync.aligned.m16n8k16.row.col.f32.f16.f16.f32 "
        "{%0,%1,%2,%3}, {%4,%5,%6,%7}, {%8,%9}, {%0,%1,%2,%3};"
        : "+f"(c[0]), "+f"(c[1]), "+f"(c[2]), "+f"(c[3])
        : "r"(a[0]), "r"(a[1]), "r"(a[2]), "r"(a[3]), "r"(b[0]), "r"(b[1]));
}
__device__ __forceinline__ void ldsm_x4(uint32_t& r0, uint32_t& r1, uint32_t& r2, uint32_t& r3,
                                        uint32_t addr) {
    asm volatile("ldmatrix.sync.aligned.m8n8.x4.shared.b16 {%0,%1,%2,%3}, [%4];"
                 : "=r"(r0), "=r"(r1), "=r"(r2), "=r"(r3) : "r"(addr));
}
__device__ __forceinline__ float cvt_tf32(float x) {
    unsigned u;
    asm("cvt.rna.tf32.f32 %0, %1;" : "=r"(u) : "f"(x));
    return __uint_as_float(u);
}
__device__ __forceinline__ float4 cvt_tf32_4(float4 v) {
    return make_float4(cvt_tf32(v.x), cvt_tf32(v.y), cvt_tf32(v.z), cvt_tf32(v.w));
}
__device__ __forceinline__ void mma8(float* c, const unsigned* a, const unsigned* b) {
    asm volatile(
        "mma.sync.aligned.m16n8k8.row.col.f32.tf32.tf32.f32 "
        "{%0,%1,%2,%3}, {%4,%5,%6,%7}, {%8,%9}, {%0,%1,%2,%3};"
        : "+f"(c[0]), "+f"(c[1]), "+f"(c[2]), "+f"(c[3])
        : "r"(a[0]), "r"(a[1]), "r"(a[2]), "r"(a[3]), "r"(b[0]), "r"(b[1]));
}

// ---------------- fp16 K=128 MMA core (ldmatrix-fed) ---------------------------
#define SPAD 136
typedef __half htile_t[SPAD];

__device__ __forceinline__ void compute_k128(const htile_t* As, const htile_t* Bs,
                                             float c[2][8][4], int wm, int wn, int lane) {
    const int quad = lane >> 3, r = lane & 7;
    uint32_t aAddr[2], bAddr[4];
#pragma unroll
    for (int mt = 0; mt < 2; mt++)
        aAddr[mt] =
            (uint32_t)__cvta_generic_to_shared(&As[wm + mt * 16 + r + (quad & 1) * 8][(quad >> 1) * 8]);
#pragma unroll
    for (int p = 0; p < 4; p++)
        bAddr[p] =
            (uint32_t)__cvta_generic_to_shared(&Bs[wn + p * 16 + (quad >> 1) * 8 + r][(quad & 1) * 8]);

#pragma unroll
    for (int kb = 0; kb < 128; kb += 16) {
        uint32_t a[2][4], b[8][2];
#pragma unroll
        for (int mt = 0; mt < 2; mt++)
            ldsm_x4(a[mt][0], a[mt][1], a[mt][2], a[mt][3], aAddr[mt] + kb * 2);
#pragma unroll
        for (int p = 0; p < 4; p++)
            ldsm_x4(b[2 * p][0], b[2 * p][1], b[2 * p + 1][0], b[2 * p + 1][1], bAddr[p] + kb * 2);
#pragma unroll
        for (int mt = 0; mt < 2; mt++)
#pragma unroll
            for (int nt = 0; nt < 8; nt++) mma16816(c[mt][nt], a[mt], b[nt]);
    }
}

// ---------------- edge bucketing ----------------------------------------------
__global__ void edge_prefill() {
    int i = blockIdx.x * blockDim.x + threadIdx.x;
    if (i < TILES_CAP * 128) g_esorted[i] = make_int2(0, NE);
}

__global__ void edge_hist(const int* __restrict__ et) {
    __shared__ int cnt[10];
    int tid = threadIdx.x;
    if (tid < 10) cnt[tid] = 0;
    __syncthreads();
    int base = blockIdx.x * 1024;
    for (int i = tid; i < 1024; i += 256) {
        int e = base + i;
        if (e < NKG) atomicAdd(&cnt[et[e]], 1);
    }
    __syncthreads();
    if (tid < 10) g_blockcnt[blockIdx.x * 10 + tid] = cnt[tid];
}

// 320 threads = 10 warps; warp r handles relation r with warp-parallel scans.
__global__ void edge_prefix() {
    __shared__ int pc[10], ps[11];
    const int warp = threadIdx.x >> 5, lane = threadIdx.x & 31;

    // pass 1: per-relation totals (warp-parallel reduction over 586 counters)
    {
        int r = warp;
        int sum = 0;
        for (int base = 0; base < NCTA_E; base += 32) {
            int cIdx = base + lane;
            sum += (cIdx < NCTA_E) ? g_blockcnt[cIdx * 10 + r] : 0;
        }
#pragma unroll
        for (int o = 16; o; o >>= 1) sum += __shfl_xor_sync(0xFFFFFFFFu, sum, o);
        if (lane == 0) pc[r] = sum;
    }
    __syncthreads();
    if (threadIdx.x == 0) {
        int acc = 0;
        for (int r = 0; r < 10; r++) { ps[r] = acc; acc += ((pc[r] + 127) >> 7) << 7; }
        ps[10] = acc;
    }
    __syncthreads();
    // pass 2: exclusive scan per relation (warp-scan, 19 iterations)
    {
        int r = warp;
        int acc = ps[r];
        for (int base = 0; base < NCTA_E; base += 32) {
            int cIdx = base + lane;
            int v = (cIdx < NCTA_E) ? g_blockcnt[cIdx * 10 + r] : 0;
            int x = v;
#pragma unroll
            for (int o = 1; o < 32; o <<= 1) {
                int y = __shfl_up_sync(0xFFFFFFFFu, x, o);
                if (lane >= o) x += y;
            }
            if (cIdx < NCTA_E) g_off[cIdx * 10 + r] = acc + (x - v);
            acc += __shfl_sync(0xFFFFFFFFu, x, 31);
        }
    }
    __syncthreads();
    // pass 3: tile -> relation map
    for (int tIdx = threadIdx.x; tIdx < TILES_CAP; tIdx += blockDim.x) {
        int pos = tIdx * 128;
        int r = 9;
#pragma unroll
        for (int q = 0; q < 10; q++)
            if (pos >= ps[q] && pos < ps[q + 1]) { r = q; break; }
        g_tiler[tIdx] = r;
    }
}

__global__ void edge_reorder(const int* __restrict__ ei, const int* __restrict__ et) {
    __shared__ int cur[10];
    int tid = threadIdx.x;
    if (tid < 10) cur[tid] = g_off[blockIdx.x * 10 + tid];
    __syncthreads();
    int base = blockIdx.x * 1024;
    for (int i = tid; i < 1024; i += 256) {
        int e = base + i;
        if (e < NKG) {
            int slot = atomicAdd(&cur[et[e]], 1);
            g_esorted[slot] = make_int2(ei[e], ei[NKG + e]);
        }
    }
}

// ---------------- gemm_root: Yroot = X[M,128](fp32) @ Wroot^T ------------------
__global__ __launch_bounds__(256, 2)
void gemm_root(const float* __restrict__ A, const __half* __restrict__ Bt, int M) {
    extern __shared__ __half sm[];
    htile_t* As = (htile_t*)sm;
    htile_t* Bs = (htile_t*)(sm + 128 * SPAD);
    const int tid = threadIdx.x, lane = tid & 31, warp = tid >> 5;
    const int g = lane >> 2, t = lane & 3;
    const int wm = (warp >> 1) * 32, wn = (warp & 1) * 64;
    const int m0 = blockIdx.x * 128;
    const int arows = (M - m0 < 128) ? (M - m0) : 128;

    {
        const float4 zf = make_float4(0.f, 0.f, 0.f, 0.f);
#pragma unroll
        for (int l = 0; l < 16; l++) {
            int e = l * 256 + tid;
            int r = e >> 5, c4 = (e & 31) * 4;
            float4 v = (r < arows) ? *(const float4*)&A[(size_t)(m0 + r) * 128 + c4] : zf;
            __half2 h0 = __floats2half2_rn(v.x, v.y);
            __half2 h1 = __floats2half2_rn(v.z, v.w);
            *(uint2*)&As[r][c4] = make_uint2(*(uint32_t*)&h0, *(uint32_t*)&h1);
        }
#pragma unroll
        for (int l = 0; l < 8; l++) {
            int e = l * 256 + tid;
            int r = e >> 4, c8 = (e & 15) * 8;
            *(uint4*)&Bs[r][c8] = *(const uint4*)&Bt[(size_t)(NR * 128 + r) * 128 + c8];
        }
    }
    __syncthreads();

    float c[2][8][4];
#pragma unroll
    for (int i = 0; i < 2; i++)
#pragma unroll
        for (int j = 0; j < 8; j++)
#pragma unroll
            for (int l = 0; l < 4; l++) c[i][j][l] = 0.f;
    compute_k128(As, Bs, c, wm, wn, lane);

#pragma unroll
    for (int mt = 0; mt < 2; mt++) {
#pragma unroll
        for (int h = 0; h < 2; h++) {
            int row = m0 + wm + mt * 16 + g + h * 8;
            if (row >= M) continue;
            float* cp = g_Yroot + (size_t)row * 128;
#pragma unroll
            for (int j = 0; j < 8; j++) {
                int col = wn + j * 8 + 2 * t;
                *(float2*)(cp + col) = make_float2(c[mt][j][h * 2], c[mt][j][h * 2 + 1]);
            }
        }
    }
}

// ---------------- gemm_edge: per 128-edge tile, Yroot[dst] += x[src] @ W_r -----
__global__ __launch_bounds__(256, 2)
void gemm_edge(const float* __restrict__ X, const __half* __restrict__ Bt) {
    extern __shared__ __half sm[];
    htile_t* As = (htile_t*)sm;
    htile_t* Bs = (htile_t*)(sm + 128 * SPAD);
    int* ssrc = (int*)(sm + 2 * 128 * SPAD);
    int* sdst = ssrc + 128;
    const int tid = threadIdx.x, lane = tid & 31, warp = tid >> 5;
    const int g = lane >> 2, t = lane & 3;
    const int wm = (warp >> 1) * 32, wn = (warp & 1) * 64;
    const int tile = blockIdx.x;

    if (tid < 128) {
        int2 rec = g_esorted[tile * 128 + tid];
        ssrc[tid] = rec.x;
        sdst[tid] = rec.y;
    }
    __syncthreads();

    const int r = g_tiler[tile];
    // B = W_r block [128n][128k]
    {
        const __half* Bp = Bt + (size_t)r * 128 * 128;
#pragma unroll
        for (int l = 0; l < 8; l++) {
            int e = l * 256 + tid;
            int rr = e >> 4, c8 = (e & 15) * 8;
            *(uint4*)&Bs[rr][c8] = *(const uint4*)&Bp[(size_t)rr * 128 + c8];
        }
    }
    // A = gathered x[src] rows (fp32 -> fp16)
#pragma unroll
    for (int l = 0; l < 16; l++) {
        int e = l * 256 + tid;
        int row = e >> 5, c4 = (e & 31) * 4;
        float4 v = *(const float4*)&X[(size_t)ssrc[row] * 128 + c4];
        __half2 h0 = __floats2half2_rn(v.x, v.y);
        __half2 h1 = __floats2half2_rn(v.z, v.w);
        *(uint2*)&As[row][c4] = make_uint2(*(uint32_t*)&h0, *(uint32_t*)&h1);
    }
    __syncthreads();

    float c[2][8][4];
#pragma unroll
    for (int i = 0; i < 2; i++)
#pragma unroll
        for (int j = 0; j < 8; j++)
#pragma unroll
            for (int l = 0; l < 4; l++) c[i][j][l] = 0.f;
    compute_k128(As, Bs, c, wm, wn, lane);

    // epilogue: atomic add rows into Yroot[dst]
#pragma unroll
    for (int mt = 0; mt < 2; mt++) {
#pragma unroll
        for (int h = 0; h < 2; h++) {
            int rowi = wm + mt * 16 + g + h * 8;
            float* bp = g_Yroot + (size_t)sdst[rowi] * 128;
#pragma unroll
            for (int nt = 0; nt < 8; nt++) {
                int col = wn + nt * 8 + 2 * t;
                red_add_v2(bp + col, c[mt][nt][h * 2], c[mt][nt][h * 2 + 1]);
            }
        }
    }
}

// ---------------- pred (2D grid): C = Ah[M,128] @ Bt[N,128]^T (fp32 out) -------
__global__ __launch_bounds__(256, 2)
void gemm_f16_k128(const __half* __restrict__ A, const __half* __restrict__ Bt,
                   float* __restrict__ C, int M, int N, size_t ldc) {
    extern __shared__ __half sm[];
    htile_t* As = (htile_t*)sm;
    htile_t* Bs = (htile_t*)(sm + 128 * SPAD);
    const int tid = threadIdx.x, lane = tid & 31, warp = tid >> 5;
    const int g = lane >> 2, t = lane & 3;
    const int wm = (warp >> 1) * 32, wn = (warp & 1) * 64;
    const int m0 = blockIdx.x * 128, n0 = blockIdx.y * 128;

    const uint4 z = make_uint4(0, 0, 0, 0);
#pragma unroll
    for (int l = 0; l < 8; l++) {
        int e = l * 256 + tid;
        int r = e >> 4, c8 = (e & 15) * 8;
        uint4 va = z, vb = z;
        if (m0 + r < M) va = *(const uint4*)&A[(size_t)(m0 + r) * 128 + c8];
        if (n0 + r < N) vb = *(const uint4*)&Bt[(size_t)(n0 + r) * 128 + c8];
        *(uint4*)&As[r][c8] = va;
        *(uint4*)&Bs[r][c8] = vb;
    }
    __syncthreads();

    float c[2][8][4];
#pragma unroll
    for (int i = 0; i < 2; i++)
#pragma unroll
        for (int j = 0; j < 8; j++)
#pragma unroll
            for (int l = 0; l < 4; l++) c[i][j][l] = 0.f;
    compute_k128(As, Bs, c, wm, wn, lane);

#pragma unroll
    for (int mt = 0; mt < 2; mt++) {
#pragma unroll
        for (int h = 0; h < 2; h++) {
            int row = m0 + wm + mt * 16 + g + h * 8;
            if (row >= M) continue;
#pragma unroll
            for (int nt = 0; nt < 8; nt++) {
                int col = n0 + wn + nt * 8 + 2 * t;
                if (col >= N) continue;
                *(float2*)&C[(size_t)row * ldc + col] =
                    make_float2(c[mt][nt][h * 2 + 0], c[mt][nt][h * 2 + 1]);
            }
        }
    }
}

// ---------------- tf32 mma GEMM (metapath GEMMs, K=768) ----------------------
__global__ __launch_bounds__(256)
void gemm_tf32(const float* __restrict__ A, int lda, const float* __restrict__ B, int ldb,
               const float* __restrict__ bias, float* __restrict__ C, int ldc,
               int M, int N, int K, int act) {
    __shared__ float As[2][128][20];
    __shared__ float Bs[2][16][136];
    const int bm = blockIdx.x * 128;
    const int bn = blockIdx.y * 128;
    const int tid = threadIdx.x;
    const int lane = tid & 31;
    const int warp = tid >> 5;
    const int g = lane >> 2, t = lane & 3;
    const int wm = (warp >> 1) * 32;
    const int wn = (warp & 1) * 64;

    float c[2][8][4];
#pragma unroll
    for (int i = 0; i < 2; i++)
#pragma unroll
        for (int j = 0; j < 8; j++)
#pragma unroll
            for (int l = 0; l < 4; l++) c[i][j][l] = 0.f;

    float4 ar[2], br[2];
    const float4 z4 = make_float4(0.f, 0.f, 0.f, 0.f);

    auto ldg = [&](int k0) {
#pragma unroll
        for (int l = 0; l < 2; l++) {
            int e = tid + l * 256;
            int m = e >> 2, k4 = (e & 3) * 4;
            int gm = bm + m;
            ar[l] = (gm < M) ? *(const float4*)&A[(size_t)gm * lda + k0 + k4] : z4;
            int kr = e >> 5, nc = (e & 31) * 4;
            int gc = bn + nc;
            br[l] = (gc < N) ? *(const float4*)&B[(size_t)(k0 + kr) * ldb + gc] : z4;
        }
    };
    auto sts = [&](int buf) {
#pragma unroll
        for (int l = 0; l < 2; l++) {
            int e = tid + l * 256;
            int m = e >> 2, k4 = (e & 3) * 4;
            float4 a4 = cvt_tf32_4(ar[l]);
            As[buf][m][k4 + 0] = a4.x;
            As[buf][m][k4 + 1] = a4.y;
            As[buf][m][k4 + 2] = a4.z;
            As[buf][m][k4 + 3] = a4.w;
            int kr = e >> 5, nc = (e & 31) * 4;
            *(float4*)&Bs[buf][kr][nc] = cvt_tf32_4(br[l]);
        }
    };
    auto compute = [&](int buf) {
#pragma unroll
        for (int kk = 0; kk < 2; kk++) {
            const int kb = kk * 8;
            unsigned a[2][4], b[8][2];
#pragma unroll
            for (int mt = 0; mt < 2; mt++) {
                int row = wm + mt * 16 + g;
                a[mt][0] = __float_as_uint(As[buf][row][kb + t]);
                a[mt][1] = __float_as_uint(As[buf][row + 8][kb + t]);
                a[mt][2] = __float_as_uint(As[buf][row][kb + t + 4]);
                a[mt][3] = __float_as_uint(As[buf][row + 8][kb + t + 4]);
            }
#pragma unroll
            for (int nt = 0; nt < 8; nt++) {
                int col = wn + nt * 8 + g;
                b[nt][0] = __float_as_uint(Bs[buf][kb + t][col]);
                b[nt][1] = __float_as_uint(Bs[buf][kb + t + 4][col]);
            }
#pragma unroll
            for (int mt = 0; mt < 2; mt++)
#pragma unroll
                for (int nt = 0; nt < 8; nt++) mma8(c[mt][nt], a[mt], b[nt]);
        }
    };

    const int iters = K >> 4;
    ldg(0);
    sts(0);
    __syncthreads();
    for (int it = 0; it < iters; it++) {
        int buf = it & 1;
        if (it + 1 < iters) ldg((it + 1) << 4);
        compute(buf);
        if (it + 1 < iters) sts(buf ^ 1);
        __syncthreads();
    }

#pragma unroll
    for (int mt = 0; mt < 2; mt++) {
#pragma unroll
        for (int h = 0; h < 2; h++) {
            int row = bm + wm + mt * 16 + g + h * 8;
            if (row >= M) continue;
#pragma unroll
            for (int nt = 0; nt < 8; nt++) {
                int col = bn + wn + nt * 8 + 2 * t;
                if (col >= N) continue;
                float v0 = c[mt][nt][h * 2 + 0];
                float v1 = c[mt][nt][h * 2 + 1];
                if (bias) { v0 += bias[col]; v1 += bias[col + 1]; }
                if (act == 2) { v0 = fmaxf(v0, 0.f); v1 = fmaxf(v1, 0.f); }
                *(float2*)&C[(size_t)row * ldc + col] = make_float2(v0, v1);
            }
        }
    }
}

// ---------------- stage 1 aux -------------------------------------------------
__global__ void build_BmainTh(const float* __restrict__ W, const float* __restrict__ Wroot) {
    int i = blockIdx.x * blockDim.x + threadIdx.x;  // over 1408*128 (n-major, k minor)
    if (i >= (NR + 1) * EDIM * EDIM) return;
    int n = i >> 7, k = i & 127;
    int r = n >> 7, o = n & 127;
    float v = (r < NR) ? W[((size_t)r * EDIM + k) * EDIM + o] : Wroot[(size_t)k * EDIM + o];
    g_BmainTh[i] = __float2half_rn(v);
}

__global__ void tanh_root(const float* __restrict__ b) {
    int i = blockIdx.x * blockDim.x + threadIdx.x;  // float4 units
    if (i >= NE * (EDIM / 4)) return;
    int n = i >> 5, j = (i & 31) * 4;
    float4 v = *(const float4*)&g_Yroot[(size_t)n * EDIM + j];
    float4 bb = *(const float4*)&b[j];
    v.x = tanhf(v.x + bb.x);
    v.y = tanhf(v.y + bb.y);
    v.z = tanhf(v.z + bb.z);
    v.w = tanhf(v.w + bb.w);
    *(float4*)&g_E[(size_t)n * EDIM + j] = v;
    __half2* eh = (__half2*)&g_Eh[(size_t)n * EDIM + j];
    eh[0] = __floats2half2_rn(v.x, v.y);
    eh[1] = __floats2half2_rn(v.z, v.w);
}

// ---------------- stage 2 aux ---------------------------------------------------
__global__ void build_x(const int* __restrict__ h_idx, const int* __restrict__ r_idx,
                        const float* __restrict__ R) {
    int b = blockIdx.x, i = threadIdx.x;
    float v = g_E[(size_t)h_idx[b] * EDIM + i] * R[(size_t)r_idx[b] * EDIM + i];
    g_xh[b * EDIM + i] = __float2half_rn(v);
}

// ---------------- stage 3: metapath RGCNs --------------------------------------
__global__ void init_mp(int m, const int* __restrict__ eids) {
    int n = blockIdx.x;
    float* row = g_mp[m] + (size_t)n * KMP;
    const float4* er = (const float4*)(g_E + (size_t)eids[n] * EDIM);
    const float4 z = make_float4(0.f, 0.f, 0.f, 0.f);
    for (int j = threadIdx.x; j < KMP / 4; j += blockDim.x)
        ((float4*)row)[j] = (j < (KMP - EDIM) / 4) ? z : er[j - (KMP - EDIM) / 4];
    if (blockIdx.x == 0 && threadIdx.x < 2) g_w[threadIdx.x] = 0.f;
}

__global__ void scatter_mp(int m, const int* __restrict__ ei, const int* __restrict__ et,
                           const int* __restrict__ eids) {
    int w = (blockIdx.x * blockDim.x + threadIdx.x) >> 5;
    int lane = threadIdx.x & 31;
    if (w >= NMP_E) return;
    int dst = ei[NMP_E + w];
    if (dst >= NREG) return;  // output sliced [:NREG]
    int src = ei[w];
    int r = et[w];
    float4 v = *(const float4*)(g_E + (size_t)eids[src] * EDIM + lane * 4);
    red_add_v4(g_mp[m] + (size_t)dst * KMP + r * EDIM + lane * 4, v);
}

// ---------------- stage 4: semantic attention + head ---------------------------
__global__ void attn(const float* __restrict__ w1, const float* __restrict__ b1,
                     const float* __restrict__ w2) {
    int n = blockIdx.x, m = blockIdx.y, tid = threadIdx.x;
    __shared__ float z[HID];
    __shared__ float red[ATT];
    const float* zp = &g_sem[m][(size_t)n * HID];
    z[tid] = zp[tid];
    z[tid + 128] = zp[tid + 128];
    __syncthreads();
    float acc = b1[tid];
#pragma unroll 8
    for (int k = 0; k < HID; k++) acc = fmaf(z[k], w1[k * ATT + tid], acc);
    red[tid] = tanhf(acc) * w2[tid];
    __syncthreads();
    for (int s = 64; s > 0; s >>= 1) {
        if (tid < s) red[tid] += red[tid + s];
        __syncthreads();
    }
    if (tid == 0) atomicAdd(&g_w[m], red[0] * (1.0f / NREG));
}

__global__ void finalk(const float* __restrict__ predW, const float* __restrict__ predb,
                       float* __restrict__ out) {
    int n = blockIdx.x, tid = threadIdx.x;
    __shared__ float h[HID];
    float w0 = g_w[0], w1v = g_w[1];
    float mx = fmaxf(w0, w1v);
    float e0 = expf(w0 - mx), e1 = expf(w1v - mx);
    float inv = 1.f / (e0 + e1);
    float b0 = e0 * inv, b1 = e1 * inv;
    h[tid] = b0 * g_sem[0][(size_t)n * HID + tid] + b1 * g_sem[1][(size_t)n * HID + tid];
    h[tid + 128] =
        b0 * g_sem[0][(size_t)n * HID + tid + 128] + b1 * g_sem[1][(size_t)n * HID + tid + 128];
    __syncthreads();
    float acc = predb[tid] + g_E[(size_t)n * EDIM + tid];
#pragma unroll 8
    for (int k = 0; k < HID; k++) acc = fmaf(h[k], predW[k * EDIM + tid], acc);
    out[(size_t)n * EDIM + tid] = acc;
}

// ---------------- launch ------------------------------------------------------
extern "C" void kernel_launch(void* const* d_in, const int* in_sizes, int n_in,
                              void* d_out, int out_size) {
    const float* E_weight = (const float*)d_in[0];
    const float* R_weight = (const float*)d_in[1];
    const float* rgcn_W = (const float*)d_in[2];
    const float* rgcn_Wroot = (const float*)d_in[3];
    const float* rgcn_b = (const float*)d_in[4];
    const float* mp0_W = (const float*)d_in[5];
    const float* mp0_Wroot = (const float*)d_in[6];
    const float* mp0_b = (const float*)d_in[7];
    const float* mp1_W = (const float*)d_in[8];
    const float* mp1_Wroot = (const float*)d_in[9];
    const float* mp1_b = (const float*)d_in[10];
    const float* sa_w1 = (const float*)d_in[11];
    const float* sa_b1 = (const float*)d_in[12];
    const float* sa_w2 = (const float*)d_in[13];
    const float* pred_W = (const float*)d_in[14];
    const float* pred_b = (const float*)d_in[15];
    const int* h_idx = (const int*)d_in[16];
    const int* r_idx = (const int*)d_in[17];
    const int* edge_index = (const int*)d_in[18];
    const int* edge_type = (const int*)d_in[19];
    const int* mp0_ei = (const int*)d_in[20];
    const int* mp0_et = (const int*)d_in[21];
    const int* mp0_eids = (const int*)d_in[22];
    const int* mp1_ei = (const int*)d_in[23];
    const int* mp1_et = (const int*)d_in[24];
    const int* mp1_eids = (const int*)d_in[25];
    float* out = (float*)d_out;  // [E_reg 2000*128 | pred 1024*100000]

    float *pBmp, *psem, *pmp;
    __half *pEh, *pBmTh, *pxh;
    cudaGetSymbolAddress((void**)&pBmp, g_Bmp);
    cudaGetSymbolAddress((void**)&psem, g_sem);
    cudaGetSymbolAddress((void**)&pmp, g_mp);
    cudaGetSymbolAddress((void**)&pEh, g_Eh);
    cudaGetSymbolAddress((void**)&pBmTh, g_BmainTh);
    cudaGetSymbolAddress((void**)&pxh, g_xh);

    const int SMEM_F16 = 2 * 128 * SPAD * (int)sizeof(__half);           // 69,632 B
    const int SMEM_EDGE = SMEM_F16 + 2 * 128 * (int)sizeof(int);         // + src/dst
    cudaFuncSetAttribute(gemm_root, cudaFuncAttributeMaxDynamicSharedMemorySize, SMEM_F16);
    cudaFuncSetAttribute(gemm_edge, cudaFuncAttributeMaxDynamicSharedMemorySize, SMEM_EDGE);
    cudaFuncSetAttribute(gemm_f16_k128, cudaFuncAttributeMaxDynamicSharedMemorySize, SMEM_F16);

    // --- edge bucketing (by relation, 128-padded segments) ---
    edge_prefill<<<(TILES_CAP * 128 + 255) / 256, 256>>>();
    build_BmainTh<<<((NR + 1) * EDIM * EDIM + 255) / 256, 256>>>(rgcn_W, rgcn_Wroot);
    edge_hist<<<NCTA_E, 256>>>(edge_type);
    edge_prefix<<<1, 320>>>();
    edge_reorder<<<NCTA_E, 256>>>(edge_index, edge_type);

    // --- main RGCN: root GEMM, then fused edge-GEMM with atomic scatter ---
    gemm_root<<<(NE + 127) / 128, 256, SMEM_F16>>>(E_weight, pBmTh, NE);
    gemm_edge<<<TILES_CAP, 256, SMEM_EDGE>>>(E_weight, pBmTh);
    tanh_root<<<(NE * (EDIM / 4) + 255) / 256, 256>>>(rgcn_b);

    // --- KGE pred = (E[h]*R[r]) @ E^T ---
    build_x<<<NB, EDIM>>>(h_idx, r_idx, R_weight);
    gemm_f16_k128<<<dim3(NB / 128, (NE + 127) / 128), 256, SMEM_F16>>>(
        pxh, pEh, out + NREG * EDIM, NB, NE, NE);

    // --- metapath RGCNs (rows < NREG) + relu ---
    init_mp<<<NREG, 128>>>(0, mp0_eids);
    init_mp<<<NREG, 128>>>(1, mp1_eids);
    cudaMemcpyAsync(pBmp, mp0_W, (size_t)NMP_REL * EDIM * HID * 4, cudaMemcpyDeviceToDevice);
    cudaMemcpyAsync(pBmp + NMP_REL * EDIM * HID, mp0_Wroot, (size_t)EDIM * HID * 4,
                    cudaMemcpyDeviceToDevice);
    cudaMemcpyAsync(pBmp + KMP * HID, mp1_W, (size_t)NMP_REL * EDIM * HID * 4,
                    cudaMemcpyDeviceToDevice);
    cudaMemcpyAsync(pBmp + KMP * HID + NMP_REL * EDIM * HID, mp1_Wroot, (size_t)EDIM * HID * 4,
                    cudaMemcpyDeviceToDevice);
    scatter_mp<<<NMP_E / 8, 256>>>(0, mp0_ei, mp0_et, mp0_eids);
    scatter_mp<<<NMP_E / 8, 256>>>(1, mp1_ei, mp1_et, mp1_eids);
    gemm_tf32<<<dim3((NREG + 127) / 128, HID / 128), 256>>>(
        pmp, KMP, pBmp, HID, mp0_b, psem, HID, NREG, HID, KMP, 2);
    gemm_tf32<<<dim3((NREG + 127) / 128, HID / 128), 256>>>(
        pmp + (size_t)NREG * KMP, KMP, pBmp + (size_t)KMP * HID, HID, mp1_b,
        psem + (size_t)NREG * HID, HID, NREG, HID, KMP, 2);

    // --- semantic attention + prediction head ---
    attn<<<dim3(NREG, 2), ATT>>>(sa_w1, sa_b1, sa_w2);
    finalk<<<NREG, EDIM>>>(pred_W, pred_b, out);
}

// round 10
// speedup vs baseline: 1.1258x; 1.0107x over previous
#include <cuda_runtime.h>
#include <cuda_fp16.h>
#include <math.h>
#include <stdint.h>

#define NE 100000
#define NR 10
#define EDIM 128
#define HID 256
#define NREG 2000
#define NKG 600000
#define NMP_REL 5
#define NMP_E 300000
#define NB 1024
#define ATT 128

#define KMP (NMP_REL * EDIM + EDIM) /* 768 */
#define NCTA_E ((NKG + 1023) / 1024) /* 586 histogram CTAs */
#define TILES_CAP 4704               /* >= ceil((NKG + 10*127)/128) */

// ---------------- scratch ----------------------------------------------------
__device__ float g_Yroot[(size_t)(NE + 1) * EDIM];  // fp32 root + atomic accum (+dump row)
__device__ float g_E[(size_t)NE * EDIM];
__device__ __half g_Eh[(size_t)NE * EDIM];          // E fp16 (pred B operand)
__device__ __half g_BmainTh[(NR + 1) * EDIM * EDIM];  // [r][n][k] fp16 (+Wroot block)
__device__ float g_Bmp[2][KMP * HID];
__device__ __half g_xh[NB * EDIM];                  // (E[h]*R[r]) fp16
__device__ float g_mp[2][(size_t)NREG * KMP];       // metapath agg scratch
__device__ float g_sem[2][NREG * HID];
__device__ float g_w[2];
// edge bucketing
__device__ int2 g_esorted[TILES_CAP * 128];
__device__ int g_blockcnt[NCTA_E * 10];
__device__ int g_off[NCTA_E * 10];
__device__ int g_tiler[TILES_CAP];

// ---------------- side stream + events (created at load; host-side only) ------
namespace {
struct GraphResources {
    cudaStream_t s1;
    cudaEvent_t evF1, evJ1, evF2, evJ2;
    GraphResources() {
        cudaStreamCreateWithFlags(&s1, cudaStreamNonBlocking);
        cudaEventCreateWithFlags(&evF1, cudaEventDisableTiming);
        cudaEventCreateWithFlags(&evJ1, cudaEventDisableTiming);
        cudaEventCreateWithFlags(&evF2, cudaEventDisableTiming);
        cudaEventCreateWithFlags(&evJ2, cudaEventDisableTiming);
    }
};
GraphResources g_res;
}

// ---------------- primitives -------------------------------------------------
__device__ __forceinline__ void red_add_v4(float* addr, float4 v) {
    asm volatile("red.global.add.v4.f32 [%0], {%1, %2, %3, %4};"
                 :: "l"(addr), "f"(v.x), "f"(v.y), "f"(v.z), "f"(v.w) : "memory");
}
__device__ __forceinline__ void red_add_v2(float* addr, float x, float y) {
    asm volatile("red.global.add.v2.f32 [%0], {%1, %2};"
                 :: "l"(addr), "f"(x), "f"(y) : "memory");
}
__device__ __forceinline__ void mma16816(float* c, const uint32_t* a, const uint32_t* b) {
    asm volatile(
        "mma.sync.aligned.m16n8k16.row.col.f32.f16.f16.f32 "
        "{%0,%1,%2,%3}, {%4,%5,%6,%7}, {%8,%9}, {%0,%1,%2,%3};"
        : "+f"(c[0]), "+f"(c[1]), "+f"(c[2]), "+f"(c[3])
        : "r"(a[0]), "r"(a[1]), "r"(a[2]), "r"(a[3]), "r"(b[0]), "r"(b[1]));
}
__device__ __forceinline__ void ldsm_x4(uint32_t& r0, uint32_t& r1, uint32_t& r2, uint32_t& r3,
                                        uint32_t addr) {
    asm volatile("ldmatrix.sync.aligned.m8n8.x4.shared.b16 {%0,%1,%2,%3}, [%4];"
                 : "=r"(r0), "=r"(r1), "=r"(r2), "=r"(r3) : "r"(addr));
}
__device__ __forceinline__ float cvt_tf32(float x) {
    unsigned u;
    asm("cvt.rna.tf32.f32 %0, %1;" : "=r"(u) : "f"(x));
    return __uint_as_float(u);
}
__device__ __forceinline__ float4 cvt_tf32_4(float4 v) {
    return make_float4(cvt_tf32(v.x), cvt_tf32(v.y), cvt_tf32(v.z), cvt_tf32(v.w));
}
__device__ __forceinline__ void mma8(float* c, const unsigned* a, const unsigned* b) {
    asm volatile(
        "mma.sync.aligned.m16n8k8.row.col.f32.tf32.tf32.f32 "
        "{%0,%1,%2,%3}, {%4,%5,%6,%7}, {%8,%9}, {%0,%1,%2,%3};"
        : "+f"(c[0]), "+f"(c[1]), "+f"(c[2]), "+f"(c[3])
        : "r"(a[0]), "r"(a[1]), "r"(a[2]), "r"(a[3]), "r"(b[0]), "r"(b[1]));
}

// ---------------- fp16 K=128 MMA core (ldmatrix-fed) ---------------------------
#define SPAD 136
typedef __half htile_t[SPAD];

__device__ __forceinline__ void compute_k128(const htile_t* As, const htile_t* Bs,
                                             float c[2][8][4], int wm, int wn, int lane) {
    const int quad = lane >> 3, r = lane & 7;
    uint32_t aAddr[2], bAddr[4];
#pragma unroll
    for (int mt = 0; mt < 2; mt++)
        aAddr[mt] =
            (uint32_t)__cvta_generic_to_shared(&As[wm + mt * 16 + r + (quad & 1) * 8][(quad >> 1) * 8]);
#pragma unroll
    for (int p = 0; p < 4; p++)
        bAddr[p] =
            (uint32_t)__cvta_generic_to_shared(&Bs[wn + p * 16 + (quad >> 1) * 8 + r][(quad & 1) * 8]);

#pragma unroll
    for (int kb = 0; kb < 128; kb += 16) {
        uint32_t a[2][4], b[8][2];
#pragma unroll
        for (int mt = 0; mt < 2; mt++)
            ldsm_x4(a[mt][0], a[mt][1], a[mt][2], a[mt][3], aAddr[mt] + kb * 2);
#pragma unroll
        for (int p = 0; p < 4; p++)
            ldsm_x4(b[2 * p][0], b[2 * p][1], b[2 * p + 1][0], b[2 * p + 1][1], bAddr[p] + kb * 2);
#pragma unroll
        for (int mt = 0; mt < 2; mt++)
#pragma unroll
            for (int nt = 0; nt < 8; nt++) mma16816(c[mt][nt], a[mt], b[nt]);
    }
}

// ---------------- edge bucketing ----------------------------------------------
__global__ void edge_prefill() {
    int i = blockIdx.x * blockDim.x + threadIdx.x;
    if (i < TILES_CAP * 128) g_esorted[i] = make_int2(0, NE);
}

__global__ void edge_hist(const int* __restrict__ et) {
    __shared__ int cnt[10];
    int tid = threadIdx.x;
    if (tid < 10) cnt[tid] = 0;
    __syncthreads();
    int base = blockIdx.x * 1024;
    for (int i = tid; i < 1024; i += 256) {
        int e = base + i;
        if (e < NKG) atomicAdd(&cnt[et[e]], 1);
    }
    __syncthreads();
    if (tid < 10) g_blockcnt[blockIdx.x * 10 + tid] = cnt[tid];
}

// 320 threads = 10 warps; warp r handles relation r with warp-parallel scans.
__global__ void edge_prefix() {
    __shared__ int pc[10], ps[11];
    const int warp = threadIdx.x >> 5, lane = threadIdx.x & 31;

    {
        int r = warp;
        int sum = 0;
        for (int base = 0; base < NCTA_E; base += 32) {
            int cIdx = base + lane;
            sum += (cIdx < NCTA_E) ? g_blockcnt[cIdx * 10 + r] : 0;
        }
#pragma unroll
        for (int o = 16; o; o >>= 1) sum += __shfl_xor_sync(0xFFFFFFFFu, sum, o);
        if (lane == 0) pc[r] = sum;
    }
    __syncthreads();
    if (threadIdx.x == 0) {
        int acc = 0;
        for (int r = 0; r < 10; r++) { ps[r] = acc; acc += ((pc[r] + 127) >> 7) << 7; }
        ps[10] = acc;
    }
    __syncthreads();
    {
        int r = warp;
        int acc = ps[r];
        for (int base = 0; base < NCTA_E; base += 32) {
            int cIdx = base + lane;
            int v = (cIdx < NCTA_E) ? g_blockcnt[cIdx * 10 + r] : 0;
            int x = v;
#pragma unroll
            for (int o = 1; o < 32; o <<= 1) {
                int y = __shfl_up_sync(0xFFFFFFFFu, x, o);
                if (lane >= o) x += y;
            }
            if (cIdx < NCTA_E) g_off[cIdx * 10 + r] = acc + (x - v);
            acc += __shfl_sync(0xFFFFFFFFu, x, 31);
        }
    }
    __syncthreads();
    for (int tIdx = threadIdx.x; tIdx < TILES_CAP; tIdx += blockDim.x) {
        int pos = tIdx * 128;
        int r = 9;
#pragma unroll
        for (int q = 0; q < 10; q++)
            if (pos >= ps[q] && pos < ps[q + 1]) { r = q; break; }
        g_tiler[tIdx] = r;
    }
}

__global__ void edge_reorder(const int* __restrict__ ei, const int* __restrict__ et) {
    __shared__ int cur[10];
    int tid = threadIdx.x;
    if (tid < 10) cur[tid] = g_off[blockIdx.x * 10 + tid];
    __syncthreads();
    int base = blockIdx.x * 1024;
    for (int i = tid; i < 1024; i += 256) {
        int e = base + i;
        if (e < NKG) {
            int slot = atomicAdd(&cur[et[e]], 1);
            g_esorted[slot] = make_int2(ei[e], ei[NKG + e]);
        }
    }
}

// ---------------- gemm_root: Yroot = X[M,128](fp32) @ Wroot^T ------------------
__global__ __launch_bounds__(256, 2)
void gemm_root(const float* __restrict__ A, const __half* __restrict__ Bt, int M) {
    extern __shared__ __half sm[];
    htile_t* As = (htile_t*)sm;
    htile_t* Bs = (htile_t*)(sm + 128 * SPAD);
    const int tid = threadIdx.x, lane = tid & 31, warp = tid >> 5;
    const int g = lane >> 2, t = lane & 3;
    const int wm = (warp >> 1) * 32, wn = (warp & 1) * 64;
    const int m0 = blockIdx.x * 128;
    const int arows = (M - m0 < 128) ? (M - m0) : 128;

    {
        const float4 zf = make_float4(0.f, 0.f, 0.f, 0.f);
#pragma unroll
        for (int l = 0; l < 16; l++) {
            int e = l * 256 + tid;
            int r = e >> 5, c4 = (e & 31) * 4;
            float4 v = (r < arows) ? *(const float4*)&A[(size_t)(m0 + r) * 128 + c4] : zf;
            __half2 h0 = __floats2half2_rn(v.x, v.y);
            __half2 h1 = __floats2half2_rn(v.z, v.w);
            *(uint2*)&As[r][c4] = make_uint2(*(uint32_t*)&h0, *(uint32_t*)&h1);
        }
#pragma unroll
        for (int l = 0; l < 8; l++) {
            int e = l * 256 + tid;
            int r = e >> 4, c8 = (e & 15) * 8;
            *(uint4*)&Bs[r][c8] = *(const uint4*)&Bt[(size_t)(NR * 128 + r) * 128 + c8];
        }
    }
    __syncthreads();

    float c[2][8][4];
#pragma unroll
    for (int i = 0; i < 2; i++)
#pragma unroll
        for (int j = 0; j < 8; j++)
#pragma unroll
            for (int l = 0; l < 4; l++) c[i][j][l] = 0.f;
    compute_k128(As, Bs, c, wm, wn, lane);

#pragma unroll
    for (int mt = 0; mt < 2; mt++) {
#pragma unroll
        for (int h = 0; h < 2; h++) {
            int row = m0 + wm + mt * 16 + g + h * 8;
            if (row >= M) continue;
            float* cp = g_Yroot + (size_t)row * 128;
#pragma unroll
            for (int j = 0; j < 8; j++) {
                int col = wn + j * 8 + 2 * t;
                *(float2*)(cp + col) = make_float2(c[mt][j][h * 2], c[mt][j][h * 2 + 1]);
            }
        }
    }
}

// ---------------- gemm_edge: per 128-edge tile, Yroot[dst] += x[src] @ W_r -----
__global__ __launch_bounds__(256, 2)
void gemm_edge(const float* __restrict__ X, const __half* __restrict__ Bt) {
    extern __shared__ __half sm[];
    htile_t* As = (htile_t*)sm;
    htile_t* Bs = (htile_t*)(sm + 128 * SPAD);
    int* ssrc = (int*)(sm + 2 * 128 * SPAD);
    int* sdst = ssrc + 128;
    const int tid = threadIdx.x, lane = tid & 31, warp = tid >> 5;
    const int g = lane >> 2, t = lane & 3;
    const int wm = (warp >> 1) * 32, wn = (warp & 1) * 64;
    const int tile = blockIdx.x;

    if (tid < 128) {
        int2 rec = g_esorted[tile * 128 + tid];
        ssrc[tid] = rec.x;
        sdst[tid] = rec.y;
    }
    __syncthreads();

    const int r = g_tiler[tile];
    {
        const __half* Bp = Bt + (size_t)r * 128 * 128;
#pragma unroll
        for (int l = 0; l < 8; l++) {
            int e = l * 256 + tid;
            int rr = e >> 4, c8 = (e & 15) * 8;
            *(uint4*)&Bs[rr][c8] = *(const uint4*)&Bp[(size_t)rr * 128 + c8];
        }
    }
#pragma unroll
    for (int l = 0; l < 16; l++) {
        int e = l * 256 + tid;
        int row = e >> 5, c4 = (e & 31) * 4;
        float4 v = *(const float4*)&X[(size_t)ssrc[row] * 128 + c4];
        __half2 h0 = __floats2half2_rn(v.x, v.y);
        __half2 h1 = __floats2half2_rn(v.z, v.w);
        *(uint2*)&As[row][c4] = make_uint2(*(uint32_t*)&h0, *(uint32_t*)&h1);
    }
    __syncthreads();

    float c[2][8][4];
#pragma unroll
    for (int i = 0; i < 2; i++)
#pragma unroll
        for (int j = 0; j < 8; j++)
#pragma unroll
            for (int l = 0; l < 4; l++) c[i][j][l] = 0.f;
    compute_k128(As, Bs, c, wm, wn, lane);

#pragma unroll
    for (int mt = 0; mt < 2; mt++) {
#pragma unroll
        for (int h = 0; h < 2; h++) {
            int rowi = wm + mt * 16 + g + h * 8;
            float* bp = g_Yroot + (size_t)sdst[rowi] * 128;
#pragma unroll
            for (int nt = 0; nt < 8; nt++) {
                int col = wn + nt * 8 + 2 * t;
                red_add_v2(bp + col, c[mt][nt][h * 2], c[mt][nt][h * 2 + 1]);
            }
        }
    }
}

// ---------------- pred (2D grid): C = Ah[M,128] @ Bt[N,128]^T (fp32 out) -------
__global__ __launch_bounds__(256, 2)
void gemm_f16_k128(const __half* __restrict__ A, const __half* __restrict__ Bt,
                   float* __restrict__ C, int M, int N, size_t ldc) {
    extern __shared__ __half sm[];
    htile_t* As = (htile_t*)sm;
    htile_t* Bs = (htile_t*)(sm + 128 * SPAD);
    const int tid = threadIdx.x, lane = tid & 31, warp = tid >> 5;
    const int g = lane >> 2, t = lane & 3;
    const int wm = (warp >> 1) * 32, wn = (warp & 1) * 64;
    const int m0 = blockIdx.x * 128, n0 = blockIdx.y * 128;

    const uint4 z = make_uint4(0, 0, 0, 0);
#pragma unroll
    for (int l = 0; l < 8; l++) {
        int e = l * 256 + tid;
        int r = e >> 4, c8 = (e & 15) * 8;
        uint4 va = z, vb = z;
        if (m0 + r < M) va = *(const uint4*)&A[(size_t)(m0 + r) * 128 + c8];
        if (n0 + r < N) vb = *(const uint4*)&Bt[(size_t)(n0 + r) * 128 + c8];
        *(uint4*)&As[r][c8] = va;
        *(uint4*)&Bs[r][c8] = vb;
    }
    __syncthreads();

    float c[2][8][4];
#pragma unroll
    for (int i = 0; i < 2; i++)
#pragma unroll
        for (int j = 0; j < 8; j++)
#pragma unroll
            for (int l = 0; l < 4; l++) c[i][j][l] = 0.f;
    compute_k128(As, Bs, c, wm, wn, lane);

#pragma unroll
    for (int mt = 0; mt < 2; mt++) {
#pragma unroll
        for (int h = 0; h < 2; h++) {
            int row = m0 + wm + mt * 16 + g + h * 8;
            if (row >= M) continue;
#pragma unroll
            for (int nt = 0; nt < 8; nt++) {
                int col = n0 + wn + nt * 8 + 2 * t;
                if (col >= N) continue;
                *(float2*)&C[(size_t)row * ldc + col] =
                    make_float2(c[mt][nt][h * 2 + 0], c[mt][nt][h * 2 + 1]);
            }
        }
    }
}

// ---------------- tf32 mma GEMM (metapath GEMMs, K=768) ----------------------
__global__ __launch_bounds__(256)
void gemm_tf32(const float* __restrict__ A, int lda, const float* __restrict__ B, int ldb,
               const float* __restrict__ bias, float* __restrict__ C, int ldc,
               int M, int N, int K, int act) {
    __shared__ float As[2][128][20];
    __shared__ float Bs[2][16][136];
    const int bm = blockIdx.x * 128;
    const int bn = blockIdx.y * 128;
    const int tid = threadIdx.x;
    const int lane = tid & 31;
    const int warp = tid >> 5;
    const int g = lane >> 2, t = lane & 3;
    const int wm = (warp >> 1) * 32;
    const int wn = (warp & 1) * 64;

    float c[2][8][4];
#pragma unroll
    for (int i = 0; i < 2; i++)
#pragma unroll
        for (int j = 0; j < 8; j++)
#pragma unroll
            for (int l = 0; l < 4; l++) c[i][j][l] = 0.f;

    float4 ar[2], br[2];
    const float4 z4 = make_float4(0.f, 0.f, 0.f, 0.f);

    auto ldg = [&](int k0) {
#pragma unroll
        for (int l = 0; l < 2; l++) {
            int e = tid + l * 256;
            int m = e >> 2, k4 = (e & 3) * 4;
            int gm = bm + m;
            ar[l] = (gm < M) ? *(const float4*)&A[(size_t)gm * lda + k0 + k4] : z4;
            int kr = e >> 5, nc = (e & 31) * 4;
            int gc = bn + nc;
            br[l] = (gc < N) ? *(const float4*)&B[(size_t)(k0 + kr) * ldb + gc] : z4;
        }
    };
    auto sts = [&](int buf) {
#pragma unroll
        for (int l = 0; l < 2; l++) {
            int e = tid + l * 256;
            int m = e >> 2, k4 = (e & 3) * 4;
            float4 a4 = cvt_tf32_4(ar[l]);
            As[buf][m][k4 + 0] = a4.x;
            As[buf][m][k4 + 1] = a4.y;
            As[buf][m][k4 + 2] = a4.z;
            As[buf][m][k4 + 3] = a4.w;
            int kr = e >> 5, nc = (e & 31) * 4;
            *(float4*)&Bs[buf][kr][nc] = cvt_tf32_4(br[l]);
        }
    };
    auto compute = [&](int buf) {
#pragma unroll
        for (int kk = 0; kk < 2; kk++) {
            const int kb = kk * 8;
            unsigned a[2][4], b[8][2];
#pragma unroll
            for (int mt = 0; mt < 2; mt++) {
                int row = wm + mt * 16 + g;
                a[mt][0] = __float_as_uint(As[buf][row][kb + t]);
                a[mt][1] = __float_as_uint(As[buf][row + 8][kb + t]);
                a[mt][2] = __float_as_uint(As[buf][row][kb + t + 4]);
                a[mt][3] = __float_as_uint(As[buf][row + 8][kb + t + 4]);
            }
#pragma unroll
            for (int nt = 0; nt < 8; nt++) {
                int col = wn + nt * 8 + g;
                b[nt][0] = __float_as_uint(Bs[buf][kb + t][col]);
                b[nt][1] = __float_as_uint(Bs[buf][kb + t + 4][col]);
            }
#pragma unroll
            for (int mt = 0; mt < 2; mt++)
#pragma unroll
                for (int nt = 0; nt < 8; nt++) mma8(c[mt][nt], a[mt], b[nt]);
        }
    };

    const int iters = K >> 4;
    ldg(0);
    sts(0);
    __syncthreads();
    for (int it = 0; it < iters; it++) {
        int buf = it & 1;
        if (it + 1 < iters) ldg((it + 1) << 4);
        compute(buf);
        if (it + 1 < iters) sts(buf ^ 1);
        __syncthreads();
    }

#pragma unroll
    for (int mt = 0; mt < 2; mt++) {
#pragma unroll
        for (int h = 0; h < 2; h++) {
            int row = bm + wm + mt * 16 + g + h * 8;
            if (row >= M) continue;
#pragma unroll
            for (int nt = 0; nt < 8; nt++) {
                int col = bn + wn + nt * 8 + 2 * t;
                if (col >= N) continue;
                float v0 = c[mt][nt][h * 2 + 0];
                float v1 = c[mt][nt][h * 2 + 1];
                if (bias) { v0 += bias[col]; v1 += bias[col + 1]; }
                if (act == 2) { v0 = fmaxf(v0, 0.f); v1 = fmaxf(v1, 0.f); }
                *(float2*)&C[(size_t)row * ldc + col] = make_float2(v0, v1);
            }
        }
    }
}

// ---------------- stage 1 aux -------------------------------------------------
__global__ void build_BmainTh(const float* __restrict__ W, const float* __restrict__ Wroot) {
    int i = blockIdx.x * blockDim.x + threadIdx.x;
    if (i >= (NR + 1) * EDIM * EDIM) return;
    int n = i >> 7, k = i & 127;
    int r = n >> 7, o = n & 127;
    float v = (r < NR) ? W[((size_t)r * EDIM + k) * EDIM + o] : Wroot[(size_t)k * EDIM + o];
    g_BmainTh[i] = __float2half_rn(v);
}

__global__ void tanh_root(const float* __restrict__ b) {
    int i = blockIdx.x * blockDim.x + threadIdx.x;
    if (i >= NE * (EDIM / 4)) return;
    int n = i >> 5, j = (i & 31) * 4;
    float4 v = *(const float4*)&g_Yroot[(size_t)n * EDIM + j];
    float4 bb = *(const float4*)&b[j];
    v.x = tanhf(v.x + bb.x);
    v.y = tanhf(v.y + bb.y);
    v.z = tanhf(v.z + bb.z);
    v.w = tanhf(v.w + bb.w);
    *(float4*)&g_E[(size_t)n * EDIM + j] = v;
    __half2* eh = (__half2*)&g_Eh[(size_t)n * EDIM + j];
    eh[0] = __floats2half2_rn(v.x, v.y);
    eh[1] = __floats2half2_rn(v.z, v.w);
}

// ---------------- stage 2 aux ---------------------------------------------------
__global__ void build_x(const int* __restrict__ h_idx, const int* __restrict__ r_idx,
                        const float* __restrict__ R) {
    int b = blockIdx.x, i = threadIdx.x;
    float v = g_E[(size_t)h_idx[b] * EDIM + i] * R[(size_t)r_idx[b] * EDIM + i];
    g_xh[b * EDIM + i] = __float2half_rn(v);
}

// ---------------- stage 3: metapath RGCNs --------------------------------------
__global__ void init_mp(int m, const int* __restrict__ eids) {
    int n = blockIdx.x;
    float* row = g_mp[m] + (size_t)n * KMP;
    const float4* er = (const float4*)(g_E + (size_t)eids[n] * EDIM);
    const float4 z = make_float4(0.f, 0.f, 0.f, 0.f);
    for (int j = threadIdx.x; j < KMP / 4; j += blockDim.x)
        ((float4*)row)[j] = (j < (KMP - EDIM) / 4) ? z : er[j - (KMP - EDIM) / 4];
    if (blockIdx.x == 0 && threadIdx.x < 2) g_w[threadIdx.x] = 0.f;
}

__global__ void scatter_mp(int m, const int* __restrict__ ei, const int* __restrict__ et,
                           const int* __restrict__ eids) {
    int w = (blockIdx.x * blockDim.x + threadIdx.x) >> 5;
    int lane = threadIdx.x & 31;
    if (w >= NMP_E) return;
    int dst = ei[NMP_E + w];
    if (dst >= NREG) return;  // output sliced [:NREG]
    int src = ei[w];
    int r = et[w];
    float4 v = *(const float4*)(g_E + (size_t)eids[src] * EDIM + lane * 4);
    red_add_v4(g_mp[m] + (size_t)dst * KMP + r * EDIM + lane * 4, v);
}

// ---------------- stage 4: semantic attention + head ---------------------------
__global__ void attn(const float* __restrict__ w1, const float* __restrict__ b1,
                     const float* __restrict__ w2) {
    int n = blockIdx.x, m = blockIdx.y, tid = threadIdx.x;
    __shared__ float z[HID];
    __shared__ float red[ATT];
    const float* zp = &g_sem[m][(size_t)n * HID];
    z[tid] = zp[tid];
    z[tid + 128] = zp[tid + 128];
    __syncthreads();
    float acc = b1[tid];
#pragma unroll 8
    for (int k = 0; k < HID; k++) acc = fmaf(z[k], w1[k * ATT + tid], acc);
    red[tid] = tanhf(acc) * w2[tid];
    __syncthreads();
    for (int s = 64; s > 0; s >>= 1) {
        if (tid < s) red[tid] += red[tid + s];
        __syncthreads();
    }
    if (tid == 0) atomicAdd(&g_w[m], red[0] * (1.0f / NREG));
}

__global__ void finalk(const float* __restrict__ predW, const float* __restrict__ predb,
                       float* __restrict__ out) {
    int n = blockIdx.x, tid = threadIdx.x;
    __shared__ float h[HID];
    float w0 = g_w[0], w1v = g_w[1];
    float mx = fmaxf(w0, w1v);
    float e0 = expf(w0 - mx), e1 = expf(w1v - mx);
    float inv = 1.f / (e0 + e1);
    float b0 = e0 * inv, b1 = e1 * inv;
    h[tid] = b0 * g_sem[0][(size_t)n * HID + tid] + b1 * g_sem[1][(size_t)n * HID + tid];
    h[tid + 128] =
        b0 * g_sem[0][(size_t)n * HID + tid + 128] + b1 * g_sem[1][(size_t)n * HID + tid + 128];
    __syncthreads();
    float acc = predb[tid] + g_E[(size_t)n * EDIM + tid];
#pragma unroll 8
    for (int k = 0; k < HID; k++) acc = fmaf(h[k], predW[k * EDIM + tid], acc);
    out[(size_t)n * EDIM + tid] = acc;
}

// ---------------- launch ------------------------------------------------------
extern "C" void kernel_launch(void* const* d_in, const int* in_sizes, int n_in,
                              void* d_out, int out_size) {
    const float* E_weight = (const float*)d_in[0];
    const float* R_weight = (const float*)d_in[1];
    const float* rgcn_W = (const float*)d_in[2];
    const float* rgcn_Wroot = (const float*)d_in[3];
    const float* rgcn_b = (const float*)d_in[4];
    const float* mp0_W = (const float*)d_in[5];
    const float* mp0_Wroot = (const float*)d_in[6];
    const float* mp0_b = (const float*)d_in[7];
    const float* mp1_W = (const float*)d_in[8];
    const float* mp1_Wroot = (const float*)d_in[9];
    const float* mp1_b = (const float*)d_in[10];
    const float* sa_w1 = (const float*)d_in[11];
    const float* sa_b1 = (const float*)d_in[12];
    const float* sa_w2 = (const float*)d_in[13];
    const float* pred_W = (const float*)d_in[14];
    const float* pred_b = (const float*)d_in[15];
    const int* h_idx = (const int*)d_in[16];
    const int* r_idx = (const int*)d_in[17];
    const int* edge_index = (const int*)d_in[18];
    const int* edge_type = (const int*)d_in[19];
    const int* mp0_ei = (const int*)d_in[20];
    const int* mp0_et = (const int*)d_in[21];
    const int* mp0_eids = (const int*)d_in[22];
    const int* mp1_ei = (const int*)d_in[23];
    const int* mp1_et = (const int*)d_in[24];
    const int* mp1_eids = (const int*)d_in[25];
    float* out = (float*)d_out;  // [E_reg 2000*128 | pred 1024*100000]

    float *pBmp, *psem, *pmp;
    __half *pEh, *pBmTh, *pxh;
    cudaGetSymbolAddress((void**)&pBmp, g_Bmp);
    cudaGetSymbolAddress((void**)&psem, g_sem);
    cudaGetSymbolAddress((void**)&pmp, g_mp);
    cudaGetSymbolAddress((void**)&pEh, g_Eh);
    cudaGetSymbolAddress((void**)&pBmTh, g_BmainTh);
    cudaGetSymbolAddress((void**)&pxh, g_xh);

    const int SMEM_F16 = 2 * 128 * SPAD * (int)sizeof(__half);           // 69,632 B
    const int SMEM_EDGE = SMEM_F16 + 2 * 128 * (int)sizeof(int);         // + src/dst
    cudaFuncSetAttribute(gemm_root, cudaFuncAttributeMaxDynamicSharedMemorySize, SMEM_F16);
    cudaFuncSetAttribute(gemm_edge, cudaFuncAttributeMaxDynamicSharedMemorySize, SMEM_EDGE);
    cudaFuncSetAttribute(gemm_f16_k128, cudaFuncAttributeMaxDynamicSharedMemorySize, SMEM_F16);

    cudaStream_t s1 = g_res.s1;

    // ===== fork 1: edge bucketing on s1, weight prep + root GEMM on main =====
    cudaEventRecord(g_res.evF1, 0);
    cudaStreamWaitEvent(s1, g_res.evF1, 0);

    edge_prefill<<<(TILES_CAP * 128 + 255) / 256, 256, 0, s1>>>();
    edge_hist<<<NCTA_E, 256, 0, s1>>>(edge_type);
    edge_prefix<<<1, 320, 0, s1>>>();
    edge_reorder<<<NCTA_E, 256, 0, s1>>>(edge_index, edge_type);

    build_BmainTh<<<((NR + 1) * EDIM * EDIM + 255) / 256, 256>>>(rgcn_W, rgcn_Wroot);
    gemm_root<<<(NE + 127) / 128, 256, SMEM_F16>>>(E_weight, pBmTh, NE);

    cudaEventRecord(g_res.evJ1, s1);
    cudaStreamWaitEvent(0, g_res.evJ1, 0);

    // ===== main: fused edge GEMM + activation =====
    gemm_edge<<<TILES_CAP, 256, SMEM_EDGE>>>(E_weight, pBmTh);
    tanh_root<<<(NE * (EDIM / 4) + 255) / 256, 256>>>(rgcn_b);

    // ===== fork 2: metapath/attention tail on s1, pred GEMM on main =====
    cudaEventRecord(g_res.evF2, 0);
    cudaStreamWaitEvent(s1, g_res.evF2, 0);

    // s1: metapath RGCNs (rows < NREG) + relu + attention + head
    init_mp<<<NREG, 128, 0, s1>>>(0, mp0_eids);
    init_mp<<<NREG, 128, 0, s1>>>(1, mp1_eids);
    cudaMemcpyAsync(pBmp, mp0_W, (size_t)NMP_REL * EDIM * HID * 4,
                    cudaMemcpyDeviceToDevice, s1);
    cudaMemcpyAsync(pBmp + NMP_REL * EDIM * HID, mp0_Wroot, (size_t)EDIM * HID * 4,
                    cudaMemcpyDeviceToDevice, s1);
    cudaMemcpyAsync(pBmp + KMP * HID, mp1_W, (size_t)NMP_REL * EDIM * HID * 4,
                    cudaMemcpyDeviceToDevice, s1);
    cudaMemcpyAsync(pBmp + KMP * HID + NMP_REL * EDIM * HID, mp1_Wroot,
                    (size_t)EDIM * HID * 4, cudaMemcpyDeviceToDevice, s1);
    scatter_mp<<<NMP_E / 8, 256, 0, s1>>>(0, mp0_ei, mp0_et, mp0_eids);
    scatter_mp<<<NMP_E / 8, 256, 0, s1>>>(1, mp1_ei, mp1_et, mp1_eids);
    gemm_tf32<<<dim3((NREG + 127) / 128, HID / 128), 256, 0, s1>>>(
        pmp, KMP, pBmp, HID, mp0_b, psem, HID, NREG, HID, KMP, 2);
    gemm_tf32<<<dim3((NREG + 127) / 128, HID / 128), 256, 0, s1>>>(
        pmp + (size_t)NREG * KMP, KMP, pBmp + (size_t)KMP * HID, HID, mp1_b,
        psem + (size_t)NREG * HID, HID, NREG, HID, KMP, 2);
    attn<<<dim3(NREG, 2), ATT, 0, s1>>>(sa_w1, sa_b1, sa_w2);
    finalk<<<NREG, EDIM, 0, s1>>>(pred_W, pred_b, out);

    // main: KGE pred = (E[h]*R[r]) @ E^T
    build_x<<<NB, EDIM>>>(h_idx, r_idx, R_weight);
    gemm_f16_k128<<<dim3(NB / 128, (NE + 127) / 128), 256, SMEM_F16>>>(
        pxh, pEh, out + NREG * EDIM, NB, NE, NE);

    cudaEventRecord(g_res.evJ2, s1);
    cudaStreamWaitEvent(0, g_res.evJ2, 0);
}

// round 11
// speedup vs baseline: 1.1756x; 1.0442x over previous
#include <cuda_runtime.h>
#include <cuda_fp16.h>
#include <math.h>
#include <stdint.h>

#define NE 100000
#define NR 10
#define EDIM 128
#define HID 256
#define NREG 2000
#define NKG 600000
#define NMP_REL 5
#define NMP_E 300000
#define NB 1024
#define ATT 128

#define KMP (NMP_REL * EDIM + EDIM) /* 768 */
#define NCTA_E ((NKG + 1023) / 1024) /* 586 histogram CTAs */
#define TILES_CAP 4704               /* even; >= ceil((NKG + 10*127)/128) */

// ---------------- scratch ----------------------------------------------------
__device__ float g_Yroot[(size_t)(NE + 1) * EDIM];  // fp32 root + atomic accum (+dump row)
__device__ float g_E[(size_t)NE * EDIM];
__device__ __half g_Eh[(size_t)NE * EDIM];          // E fp16 (pred B operand)
__device__ __half g_BmainTh[(NR + 1) * EDIM * EDIM];  // [r][n][k] fp16 (+Wroot block)
__device__ float g_Bmp[2][KMP * HID];
__device__ __half g_xh[NB * EDIM];                  // (E[h]*R[r]) fp16
__device__ float g_mp[2][(size_t)NREG * KMP];       // metapath agg scratch
__device__ float g_sem[2][NREG * HID];
__device__ float g_w[2];
// edge bucketing
__device__ int2 g_esorted[TILES_CAP * 128];
__device__ int g_blockcnt[NCTA_E * 10];
__device__ int g_off[NCTA_E * 10];
__device__ int g_tiler[TILES_CAP];

// ---------------- side stream + events (host-side, created at load) -----------
namespace {
struct GraphResources {
    cudaStream_t s1;
    cudaEvent_t evF1, evJ1, evF2, evJ2;
    GraphResources() {
        cudaStreamCreateWithFlags(&s1, cudaStreamNonBlocking);
        cudaEventCreateWithFlags(&evF1, cudaEventDisableTiming);
        cudaEventCreateWithFlags(&evJ1, cudaEventDisableTiming);
        cudaEventCreateWithFlags(&evF2, cudaEventDisableTiming);
        cudaEventCreateWithFlags(&evJ2, cudaEventDisableTiming);
    }
};
GraphResources g_res;
}

// ---------------- primitives -------------------------------------------------
__device__ __forceinline__ void red_add_v4(float* addr, float4 v) {
    asm volatile("red.global.add.v4.f32 [%0], {%1, %2, %3, %4};"
                 :: "l"(addr), "f"(v.x), "f"(v.y), "f"(v.z), "f"(v.w) : "memory");
}
__device__ __forceinline__ void red_add_v2(float* addr, float x, float y) {
    asm volatile("red.global.add.v2.f32 [%0], {%1, %2};"
                 :: "l"(addr), "f"(x), "f"(y) : "memory");
}
__device__ __forceinline__ void mma16816(float* c, const uint32_t* a, const uint32_t* b) {
    asm volatile(
        "mma.sync.aligned.m16n8k16.row.col.f32.f16.f16.f32 "
        "{%0,%1,%2,%3}, {%4,%5,%6,%7}, {%8,%9}, {%0,%1,%2,%3};"
        : "+f"(c[0]), "+f"(c[1]), "+f"(c[2]), "+f"(c[3])
        : "r"(a[0]), "r"(a[1]), "r"(a[2]), "r"(a[3]), "r"(b[0]), "r"(b[1]));
}
__device__ __forceinline__ void ldsm_x4(uint32_t& r0, uint32_t& r1, uint32_t& r2, uint32_t& r3,
                                        uint32_t addr) {
    asm volatile("ldmatrix.sync.aligned.m8n8.x4.shared.b16 {%0,%1,%2,%3}, [%4];"
                 : "=r"(r0), "=r"(r1), "=r"(r2), "=r"(r3) : "r"(addr));
}
__device__ __forceinline__ float cvt_tf32(float x) {
    unsigned u;
    asm("cvt.rna.tf32.f32 %0, %1;" : "=r"(u) : "f"(x));
    return __uint_as_float(u);
}
__device__ __forceinline__ float4 cvt_tf32_4(float4 v) {
    return make_float4(cvt_tf32(v.x), cvt_tf32(v.y), cvt_tf32(v.z), cvt_tf32(v.w));
}
__device__ __forceinline__ void mma8(float* c, const unsigned* a, const unsigned* b) {
    asm volatile(
        "mma.sync.aligned.m16n8k8.row.col.f32.tf32.tf32.f32 "
        "{%0,%1,%2,%3}, {%4,%5,%6,%7}, {%8,%9}, {%0,%1,%2,%3};"
        : "+f"(c[0]), "+f"(c[1]), "+f"(c[2]), "+f"(c[3])
        : "r"(a[0]), "r"(a[1]), "r"(a[2]), "r"(a[3]), "r"(b[0]), "r"(b[1]));
}

// ---------------- fp16 K=128 MMA core (ldmatrix-fed) ---------------------------
#define SPAD 136
typedef __half htile_t[SPAD];

__device__ __forceinline__ void compute_k128(const htile_t* As, const htile_t* Bs,
                                             float c[2][8][4], int wm, int wn, int lane) {
    const int quad = lane >> 3, r = lane & 7;
    uint32_t aAddr[2], bAddr[4];
#pragma unroll
    for (int mt = 0; mt < 2; mt++)
        aAddr[mt] =
            (uint32_t)__cvta_generic_to_shared(&As[wm + mt * 16 + r + (quad & 1) * 8][(quad >> 1) * 8]);
#pragma unroll
    for (int p = 0; p < 4; p++)
        bAddr[p] =
            (uint32_t)__cvta_generic_to_shared(&Bs[wn + p * 16 + (quad >> 1) * 8 + r][(quad & 1) * 8]);

#pragma unroll
    for (int kb = 0; kb < 128; kb += 16) {
        uint32_t a[2][4], b[8][2];
#pragma unroll
        for (int mt = 0; mt < 2; mt++)
            ldsm_x4(a[mt][0], a[mt][1], a[mt][2], a[mt][3], aAddr[mt] + kb * 2);
#pragma unroll
        for (int p = 0; p < 4; p++)
            ldsm_x4(b[2 * p][0], b[2 * p][1], b[2 * p + 1][0], b[2 * p + 1][1], bAddr[p] + kb * 2);
#pragma unroll
        for (int mt = 0; mt < 2; mt++)
#pragma unroll
            for (int nt = 0; nt < 8; nt++) mma16816(c[mt][nt], a[mt], b[nt]);
    }
}
#define ZERO_C(c)                                  \
    _Pragma("unroll") for (int _i = 0; _i < 2; _i++) \
    _Pragma("unroll") for (int _j = 0; _j < 8; _j++) \
    _Pragma("unroll") for (int _l = 0; _l < 4; _l++) (c)[_i][_j][_l] = 0.f

// ---------------- edge bucketing ----------------------------------------------
__global__ void edge_prefill() {
    int i = blockIdx.x * blockDim.x + threadIdx.x;
    if (i < TILES_CAP * 128) g_esorted[i] = make_int2(0, NE);
}

__global__ void edge_hist(const int* __restrict__ et) {
    __shared__ int cnt[10];
    int tid = threadIdx.x;
    if (tid < 10) cnt[tid] = 0;
    __syncthreads();
    int base = blockIdx.x * 1024;
    for (int i = tid; i < 1024; i += 256) {
        int e = base + i;
        if (e < NKG) atomicAdd(&cnt[et[e]], 1);
    }
    __syncthreads();
    if (tid < 10) g_blockcnt[blockIdx.x * 10 + tid] = cnt[tid];
}

__global__ void edge_prefix() {
    __shared__ int pc[10], ps[11];
    const int warp = threadIdx.x >> 5, lane = threadIdx.x & 31;
    {
        int r = warp;
        int sum = 0;
        for (int base = 0; base < NCTA_E; base += 32) {
            int cIdx = base + lane;
            sum += (cIdx < NCTA_E) ? g_blockcnt[cIdx * 10 + r] : 0;
        }
#pragma unroll
        for (int o = 16; o; o >>= 1) sum += __shfl_xor_sync(0xFFFFFFFFu, sum, o);
        if (lane == 0) pc[r] = sum;
    }
    __syncthreads();
    if (threadIdx.x == 0) {
        int acc = 0;
        for (int r = 0; r < 10; r++) { ps[r] = acc; acc += ((pc[r] + 127) >> 7) << 7; }
        ps[10] = acc;
    }
    __syncthreads();
    {
        int r = warp;
        int acc = ps[r];
        for (int base = 0; base < NCTA_E; base += 32) {
            int cIdx = base + lane;
            int v = (cIdx < NCTA_E) ? g_blockcnt[cIdx * 10 + r] : 0;
            int x = v;
#pragma unroll
            for (int o = 1; o < 32; o <<= 1) {
                int y = __shfl_up_sync(0xFFFFFFFFu, x, o);
                if (lane >= o) x += y;
            }
            if (cIdx < NCTA_E) g_off[cIdx * 10 + r] = acc + (x - v);
            acc += __shfl_sync(0xFFFFFFFFu, x, 31);
        }
    }
    __syncthreads();
    for (int tIdx = threadIdx.x; tIdx < TILES_CAP; tIdx += blockDim.x) {
        int pos = tIdx * 128;
        int r = 9;
#pragma unroll
        for (int q = 0; q < 10; q++)
            if (pos >= ps[q] && pos < ps[q + 1]) { r = q; break; }
        g_tiler[tIdx] = r;
    }
}

__global__ void edge_reorder(const int* __restrict__ ei, const int* __restrict__ et) {
    __shared__ int cur[10];
    int tid = threadIdx.x;
    if (tid < 10) cur[tid] = g_off[blockIdx.x * 10 + tid];
    __syncthreads();
    int base = blockIdx.x * 1024;
    for (int i = tid; i < 1024; i += 256) {
        int e = base + i;
        if (e < NKG) {
            int slot = atomicAdd(&cur[et[e]], 1);
            g_esorted[slot] = make_int2(ei[e], ei[NKG + e]);
        }
    }
}

// ---------------- gemm_root: Yroot = X[M,128](fp32) @ Wroot^T ------------------
__global__ __launch_bounds__(256, 2)
void gemm_root(const float* __restrict__ A, const __half* __restrict__ Bt, int M) {
    extern __shared__ __half sm[];
    htile_t* As = (htile_t*)sm;
    htile_t* Bs = (htile_t*)(sm + 128 * SPAD);
    const int tid = threadIdx.x, lane = tid & 31, warp = tid >> 5;
    const int g = lane >> 2, t = lane & 3;
    const int wm = (warp >> 1) * 32, wn = (warp & 1) * 64;
    const int m0 = blockIdx.x * 128;
    const int arows = (M - m0 < 128) ? (M - m0) : 128;

    {
        const float4 zf = make_float4(0.f, 0.f, 0.f, 0.f);
#pragma unroll
        for (int l = 0; l < 16; l++) {
            int e = l * 256 + tid;
            int r = e >> 5, c4 = (e & 31) * 4;
            float4 v = (r < arows) ? *(const float4*)&A[(size_t)(m0 + r) * 128 + c4] : zf;
            __half2 h0 = __floats2half2_rn(v.x, v.y);
            __half2 h1 = __floats2half2_rn(v.z, v.w);
            *(uint2*)&As[r][c4] = make_uint2(*(uint32_t*)&h0, *(uint32_t*)&h1);
        }
#pragma unroll
        for (int l = 0; l < 8; l++) {
            int e = l * 256 + tid;
            int r = e >> 4, c8 = (e & 15) * 8;
            *(uint4*)&Bs[r][c8] = *(const uint4*)&Bt[(size_t)(NR * 128 + r) * 128 + c8];
        }
    }
    __syncthreads();

    float c[2][8][4];
    ZERO_C(c);
    compute_k128(As, Bs, c, wm, wn, lane);

#pragma unroll
    for (int mt = 0; mt < 2; mt++) {
#pragma unroll
        for (int h = 0; h < 2; h++) {
            int row = m0 + wm + mt * 16 + g + h * 8;
            if (row >= M) continue;
            float* cp = g_Yroot + (size_t)row * 128;
#pragma unroll
            for (int j = 0; j < 8; j++) {
                int col = wn + j * 8 + 2 * t;
                *(float2*)(cp + col) = make_float2(c[mt][j][h * 2], c[mt][j][h * 2 + 1]);
            }
        }
    }
}

// ---------------- gemm_edge: 2 edge-tiles per CTA, B reused when same rel ------
__global__ __launch_bounds__(256, 2)
void gemm_edge(const float* __restrict__ X, const __half* __restrict__ Bt) {
    extern __shared__ __half sm[];
    htile_t* As = (htile_t*)sm;
    htile_t* Bs = (htile_t*)(sm + 128 * SPAD);
    int* ssrc = (int*)(sm + 2 * 128 * SPAD);  // [2][128]
    int* sdst = ssrc + 256;                    // [2][128]
    const int tid = threadIdx.x, lane = tid & 31, warp = tid >> 5;
    const int g = lane >> 2, t = lane & 3;
    const int wm = (warp >> 1) * 32, wn = (warp & 1) * 64;
    const int tile0 = blockIdx.x * 2;

    // indices for both sub-tiles (256 edges)
    if (tid < 256) {
        int2 rec = g_esorted[(size_t)tile0 * 128 + tid];
        ssrc[tid] = rec.x;
        sdst[tid] = rec.y;
    }
    const int r0 = g_tiler[tile0], r1 = g_tiler[tile0 + 1];
    // B = W_{r0}
    {
        const __half* Bp = Bt + (size_t)r0 * 128 * 128;
#pragma unroll
        for (int l = 0; l < 8; l++) {
            int e = l * 256 + tid;
            int rr = e >> 4, c8 = (e & 15) * 8;
            *(uint4*)&Bs[rr][c8] = *(const uint4*)&Bp[(size_t)rr * 128 + c8];
        }
    }
    __syncthreads();

    // ---- sub-tile 0: gather A0 ----
#pragma unroll
    for (int l = 0; l < 16; l++) {
        int e = l * 256 + tid;
        int row = e >> 5, c4 = (e & 31) * 4;
        float4 v = *(const float4*)&X[(size_t)ssrc[row] * 128 + c4];
        __half2 h0 = __floats2half2_rn(v.x, v.y);
        __half2 h1 = __floats2half2_rn(v.z, v.w);
        *(uint2*)&As[row][c4] = make_uint2(*(uint32_t*)&h0, *(uint32_t*)&h1);
    }
    __syncthreads();

    float c[2][8][4];
    ZERO_C(c);
    compute_k128(As, Bs, c, wm, wn, lane);
    __syncthreads();  // all warps done reading As (and Bs if r1 differs)

    // ---- prep sub-tile 1 (A1 gather; B reload only at relation boundary) ----
#pragma unroll
    for (int l = 0; l < 16; l++) {
        int e = l * 256 + tid;
        int row = e >> 5, c4 = (e & 31) * 4;
        float4 v = *(const float4*)&X[(size_t)ssrc[128 + row] * 128 + c4];
        __half2 h0 = __floats2half2_rn(v.x, v.y);
        __half2 h1 = __floats2half2_rn(v.z, v.w);
        *(uint2*)&As[row][c4] = make_uint2(*(uint32_t*)&h0, *(uint32_t*)&h1);
    }
    if (r1 != r0) {
        const __half* Bp = Bt + (size_t)r1 * 128 * 128;
#pragma unroll
        for (int l = 0; l < 8; l++) {
            int e = l * 256 + tid;
            int rr = e >> 4, c8 = (e & 15) * 8;
            *(uint4*)&Bs[rr][c8] = *(const uint4*)&Bp[(size_t)rr * 128 + c8];
        }
    }
    // epilogue 0 (register/atomic only; overlaps the loads above)
#pragma unroll
    for (int mt = 0; mt < 2; mt++) {
#pragma unroll
        for (int h = 0; h < 2; h++) {
            int rowi = wm + mt * 16 + g + h * 8;
            float* bp = g_Yroot + (size_t)sdst[rowi] * 128;
#pragma unroll
            for (int nt = 0; nt < 8; nt++) {
                int col = wn + nt * 8 + 2 * t;
                red_add_v2(bp + col, c[mt][nt][h * 2], c[mt][nt][h * 2 + 1]);
            }
        }
    }
    __syncthreads();

    // ---- sub-tile 1 ----
    ZERO_C(c);
    compute_k128(As, Bs, c, wm, wn, lane);
#pragma unroll
    for (int mt = 0; mt < 2; mt++) {
#pragma unroll
        for (int h = 0; h < 2; h++) {
            int rowi = wm + mt * 16 + g + h * 8;
            float* bp = g_Yroot + (size_t)sdst[128 + rowi] * 128;
#pragma unroll
            for (int nt = 0; nt < 8; nt++) {
                int col = wn + nt * 8 + 2 * t;
                red_add_v2(bp + col, c[mt][nt][h * 2], c[mt][nt][h * 2 + 1]);
            }
        }
    }
}

// ---------------- pred: 2 M-tiles per CTA sharing the B (Eh) tile --------------
__global__ __launch_bounds__(256, 2)
void gemm_pred(const __half* __restrict__ A, const __half* __restrict__ Bt,
               float* __restrict__ C, int M, int N, size_t ldc) {
    extern __shared__ __half sm[];
    htile_t* As = (htile_t*)sm;
    htile_t* Bs = (htile_t*)(sm + 128 * SPAD);
    const int tid = threadIdx.x, lane = tid & 31, warp = tid >> 5;
    const int g = lane >> 2, t = lane & 3;
    const int wm = (warp >> 1) * 32, wn = (warp & 1) * 64;
    const int mbase = blockIdx.x * 256, n0 = blockIdx.y * 128;

    const uint4 z = make_uint4(0, 0, 0, 0);
    // B tile (loaded once for both M sub-tiles)
#pragma unroll
    for (int l = 0; l < 8; l++) {
        int e = l * 256 + tid;
        int r = e >> 4, c8 = (e & 15) * 8;
        *(uint4*)&Bs[r][c8] = (n0 + r < N) ? *(const uint4*)&Bt[(size_t)(n0 + r) * 128 + c8] : z;
    }
    // A sub-tile 0
#pragma unroll
    for (int l = 0; l < 8; l++) {
        int e = l * 256 + tid;
        int r = e >> 4, c8 = (e & 15) * 8;
        *(uint4*)&As[r][c8] =
            (mbase + r < M) ? *(const uint4*)&A[(size_t)(mbase + r) * 128 + c8] : z;
    }
    __syncthreads();

    float c[2][8][4];
    ZERO_C(c);
    compute_k128(As, Bs, c, wm, wn, lane);
    __syncthreads();

    // A sub-tile 1 load (overlaps epilogue 0)
#pragma unroll
    for (int l = 0; l < 8; l++) {
        int e = l * 256 + tid;
        int r = e >> 4, c8 = (e & 15) * 8;
        int row = mbase + 128 + r;
        *(uint4*)&As[r][c8] = (row < M) ? *(const uint4*)&A[(size_t)row * 128 + c8] : z;
    }
    // epilogue 0
#pragma unroll
    for (int mt = 0; mt < 2; mt++) {
#pragma unroll
        for (int h = 0; h < 2; h++) {
            int row = mbase + wm + mt * 16 + g + h * 8;
            if (row >= M) continue;
#pragma unroll
            for (int nt = 0; nt < 8; nt++) {
                int col = n0 + wn + nt * 8 + 2 * t;
                if (col >= N) continue;
                *(float2*)&C[(size_t)row * ldc + col] =
                    make_float2(c[mt][nt][h * 2 + 0], c[mt][nt][h * 2 + 1]);
            }
        }
    }
    __syncthreads();

    ZERO_C(c);
    compute_k128(As, Bs, c, wm, wn, lane);
#pragma unroll
    for (int mt = 0; mt < 2; mt++) {
#pragma unroll
        for (int h = 0; h < 2; h++) {
            int row = mbase + 128 + wm + mt * 16 + g + h * 8;
            if (row >= M) continue;
#pragma unroll
            for (int nt = 0; nt < 8; nt++) {
                int col = n0 + wn + nt * 8 + 2 * t;
                if (col >= N) continue;
                *(float2*)&C[(size_t)row * ldc + col] =
                    make_float2(c[mt][nt][h * 2 + 0], c[mt][nt][h * 2 + 1]);
            }
        }
    }
}

// ---------------- tf32 mma GEMM (metapath GEMMs, K=768) ----------------------
__global__ __launch_bounds__(256)
void gemm_tf32(const float* __restrict__ A, int lda, const float* __restrict__ B, int ldb,
               const float* __restrict__ bias, float* __restrict__ C, int ldc,
               int M, int N, int K, int act) {
    __shared__ float As[2][128][20];
    __shared__ float Bs[2][16][136];
    const int bm = blockIdx.x * 128;
    const int bn = blockIdx.y * 128;
    const int tid = threadIdx.x;
    const int lane = tid & 31;
    const int warp = tid >> 5;
    const int g = lane >> 2, t = lane & 3;
    const int wm = (warp >> 1) * 32;
    const int wn = (warp & 1) * 64;

    float c[2][8][4];
    ZERO_C(c);

    float4 ar[2], br[2];
    const float4 z4 = make_float4(0.f, 0.f, 0.f, 0.f);

    auto ldg = [&](int k0) {
#pragma unroll
        for (int l = 0; l < 2; l++) {
            int e = tid + l * 256;
            int m = e >> 2, k4 = (e & 3) * 4;
            int gm = bm + m;
            ar[l] = (gm < M) ? *(const float4*)&A[(size_t)gm * lda + k0 + k4] : z4;
            int kr = e >> 5, nc = (e & 31) * 4;
            int gc = bn + nc;
            br[l] = (gc < N) ? *(const float4*)&B[(size_t)(k0 + kr) * ldb + gc] : z4;
        }
    };
    auto sts = [&](int buf) {
#pragma unroll
        for (int l = 0; l < 2; l++) {
            int e = tid + l * 256;
            int m = e >> 2, k4 = (e & 3) * 4;
            float4 a4 = cvt_tf32_4(ar[l]);
            As[buf][m][k4 + 0] = a4.x;
            As[buf][m][k4 + 1] = a4.y;
            As[buf][m][k4 + 2] = a4.z;
            As[buf][m][k4 + 3] = a4.w;
            int kr = e >> 5, nc = (e & 31) * 4;
            *(float4*)&Bs[buf][kr][nc] = cvt_tf32_4(br[l]);
        }
    };
    auto compute = [&](int buf) {
#pragma unroll
        for (int kk = 0; kk < 2; kk++) {
            const int kb = kk * 8;
            unsigned a[2][4], b[8][2];
#pragma unroll
            for (int mt = 0; mt < 2; mt++) {
                int row = wm + mt * 16 + g;
                a[mt][0] = __float_as_uint(As[buf][row][kb + t]);
                a[mt][1] = __float_as_uint(As[buf][row + 8][kb + t]);
                a[mt][2] = __float_as_uint(As[buf][row][kb + t + 4]);
                a[mt][3] = __float_as_uint(As[buf][row + 8][kb + t + 4]);
            }
#pragma unroll
            for (int nt = 0; nt < 8; nt++) {
                int col = wn + nt * 8 + g;
                b[nt][0] = __float_as_uint(Bs[buf][kb + t][col]);
                b[nt][1] = __float_as_uint(Bs[buf][kb + t + 4][col]);
            }
#pragma unroll
            for (int mt = 0; mt < 2; mt++)
#pragma unroll
                for (int nt = 0; nt < 8; nt++) mma8(c[mt][nt], a[mt], b[nt]);
        }
    };

    const int iters = K >> 4;
    ldg(0);
    sts(0);
    __syncthreads();
    for (int it = 0; it < iters; it++) {
        int buf = it & 1;
        if (it + 1 < iters) ldg((it + 1) << 4);
        compute(buf);
        if (it + 1 < iters) sts(buf ^ 1);
        __syncthreads();
    }

#pragma unroll
    for (int mt = 0; mt < 2; mt++) {
#pragma unroll
        for (int h = 0; h < 2; h++) {
            int row = bm + wm + mt * 16 + g + h * 8;
            if (row >= M) continue;
#pragma unroll
            for (int nt = 0; nt < 8; nt++) {
                int col = bn + wn + nt * 8 + 2 * t;
                if (col >= N) continue;
                float v0 = c[mt][nt][h * 2 + 0];
                float v1 = c[mt][nt][h * 2 + 1];
                if (bias) { v0 += bias[col]; v1 += bias[col + 1]; }
                if (act == 2) { v0 = fmaxf(v0, 0.f); v1 = fmaxf(v1, 0.f); }
                *(float2*)&C[(size_t)row * ldc + col] = make_float2(v0, v1);
            }
        }
    }
}

// ---------------- stage 1 aux -------------------------------------------------
__global__ void build_BmainTh(const float* __restrict__ W, const float* __restrict__ Wroot) {
    int i = blockIdx.x * blockDim.x + threadIdx.x;
    if (i >= (NR + 1) * EDIM * EDIM) return;
    int n = i >> 7, k = i & 127;
    int r = n >> 7, o = n & 127;
    float v = (r < NR) ? W[((size_t)r * EDIM + k) * EDIM + o] : Wroot[(size_t)k * EDIM + o];
    g_BmainTh[i] = __float2half_rn(v);
}

__global__ void tanh_root(const float* __restrict__ b) {
    int i = blockIdx.x * blockDim.x + threadIdx.x;
    if (i >= NE * (EDIM / 4)) return;
    int n = i >> 5, j = (i & 31) * 4;
    float4 v = *(const float4*)&g_Yroot[(size_t)n * EDIM + j];
    float4 bb = *(const float4*)&b[j];
    v.x = tanhf(v.x + bb.x);
    v.y = tanhf(v.y + bb.y);
    v.z = tanhf(v.z + bb.z);
    v.w = tanhf(v.w + bb.w);
    *(float4*)&g_E[(size_t)n * EDIM + j] = v;
    __half2* eh = (__half2*)&g_Eh[(size_t)n * EDIM + j];
    eh[0] = __floats2half2_rn(v.x, v.y);
    eh[1] = __floats2half2_rn(v.z, v.w);
}

// ---------------- stage 2 aux ---------------------------------------------------
__global__ void build_x(const int* __restrict__ h_idx, const int* __restrict__ r_idx,
                        const float* __restrict__ R) {
    int b = blockIdx.x, i = threadIdx.x;
    float v = g_E[(size_t)h_idx[b] * EDIM + i] * R[(size_t)r_idx[b] * EDIM + i];
    g_xh[b * EDIM + i] = __float2half_rn(v);
}

// ---------------- stage 3: metapath RGCNs --------------------------------------
__global__ void init_mp(int m, const int* __restrict__ eids) {
    int n = blockIdx.x;
    float* row = g_mp[m] + (size_t)n * KMP;
    const float4* er = (const float4*)(g_E + (size_t)eids[n] * EDIM);
    const float4 z = make_float4(0.f, 0.f, 0.f, 0.f);
    for (int j = threadIdx.x; j < KMP / 4; j += blockDim.x)
        ((float4*)row)[j] = (j < (KMP - EDIM) / 4) ? z : er[j - (KMP - EDIM) / 4];
    if (blockIdx.x == 0 && threadIdx.x < 2) g_w[threadIdx.x] = 0.f;
}

__global__ void scatter_mp(int m, const int* __restrict__ ei, const int* __restrict__ et,
                           const int* __restrict__ eids) {
    int w = (blockIdx.x * blockDim.x + threadIdx.x) >> 5;
    int lane = threadIdx.x & 31;
    if (w >= NMP_E) return;
    int dst = ei[NMP_E + w];
    if (dst >= NREG) return;  // output sliced [:NREG]
    int src = ei[w];
    int r = et[w];
    float4 v = *(const float4*)(g_E + (size_t)eids[src] * EDIM + lane * 4);
    red_add_v4(g_mp[m] + (size_t)dst * KMP + r * EDIM + lane * 4, v);
}

// ---------------- stage 4: semantic attention + head ---------------------------
__global__ void attn(const float* __restrict__ w1, const float* __restrict__ b1,
                     const float* __restrict__ w2) {
    int n = blockIdx.x, m = blockIdx.y, tid = threadIdx.x;
    __shared__ float z[HID];
    __shared__ float red[ATT];
    const float* zp = &g_sem[m][(size_t)n * HID];
    z[tid] = zp[tid];
    z[tid + 128] = zp[tid + 128];
    __syncthreads();
    float acc = b1[tid];
#pragma unroll 8
    for (int k = 0; k < HID; k++) acc = fmaf(z[k], w1[k * ATT + tid], acc);
    red[tid] = tanhf(acc) * w2[tid];
    __syncthreads();
    for (int s = 64; s > 0; s >>= 1) {
        if (tid < s) red[tid] += red[tid + s];
        __syncthreads();
    }
    if (tid == 0) atomicAdd(&g_w[m], red[0] * (1.0f / NREG));
}

__global__ void finalk(const float* __restrict__ predW, const float* __restrict__ predb,
                       float* __restrict__ out) {
    int n = blockIdx.x, tid = threadIdx.x;
    __shared__ float h[HID];
    float w0 = g_w[0], w1v = g_w[1];
    float mx = fmaxf(w0, w1v);
    float e0 = expf(w0 - mx), e1 = expf(w1v - mx);
    float inv = 1.f / (e0 + e1);
    float b0 = e0 * inv, b1 = e1 * inv;
    h[tid] = b0 * g_sem[0][(size_t)n * HID + tid] + b1 * g_sem[1][(size_t)n * HID + tid];
    h[tid + 128] =
        b0 * g_sem[0][(size_t)n * HID + tid + 128] + b1 * g_sem[1][(size_t)n * HID + tid + 128];
    __syncthreads();
    float acc = predb[tid] + g_E[(size_t)n * EDIM + tid];
#pragma unroll 8
    for (int k = 0; k < HID; k++) acc = fmaf(h[k], predW[k * EDIM + tid], acc);
    out[(size_t)n * EDIM + tid] = acc;
}

// ---------------- launch ------------------------------------------------------
extern "C" void kernel_launch(void* const* d_in, const int* in_sizes, int n_in,
                              void* d_out, int out_size) {
    const float* E_weight = (const float*)d_in[0];
    const float* R_weight = (const float*)d_in[1];
    const float* rgcn_W = (const float*)d_in[2];
    const float* rgcn_Wroot = (const float*)d_in[3];
    const float* rgcn_b = (const float*)d_in[4];
    const float* mp0_W = (const float*)d_in[5];
    const float* mp0_Wroot = (const float*)d_in[6];
    const float* mp0_b = (const float*)d_in[7];
    const float* mp1_W = (const float*)d_in[8];
    const float* mp1_Wroot = (const float*)d_in[9];
    const float* mp1_b = (const float*)d_in[10];
    const float* sa_w1 = (const float*)d_in[11];
    const float* sa_b1 = (const float*)d_in[12];
    const float* sa_w2 = (const float*)d_in[13];
    const float* pred_W = (const float*)d_in[14];
    const float* pred_b = (const float*)d_in[15];
    const int* h_idx = (const int*)d_in[16];
    const int* r_idx = (const int*)d_in[17];
    const int* edge_index = (const int*)d_in[18];
    const int* edge_type = (const int*)d_in[19];
    const int* mp0_ei = (const int*)d_in[20];
    const int* mp0_et = (const int*)d_in[21];
    const int* mp0_eids = (const int*)d_in[22];
    const int* mp1_ei = (const int*)d_in[23];
    const int* mp1_et = (const int*)d_in[24];
    const int* mp1_eids = (const int*)d_in[25];
    float* out = (float*)d_out;  // [E_reg 2000*128 | pred 1024*100000]

    float *pBmp, *psem, *pmp;
    __half *pEh, *pBmTh, *pxh;
    cudaGetSymbolAddress((void**)&pBmp, g_Bmp);
    cudaGetSymbolAddress((void**)&psem, g_sem);
    cudaGetSymbolAddress((void**)&pmp, g_mp);
    cudaGetSymbolAddress((void**)&pEh, g_Eh);
    cudaGetSymbolAddress((void**)&pBmTh, g_BmainTh);
    cudaGetSymbolAddress((void**)&pxh, g_xh);

    const int SMEM_F16 = 2 * 128 * SPAD * (int)sizeof(__half);           // 69,632 B
    const int SMEM_EDGE = SMEM_F16 + 4 * 128 * (int)sizeof(int);         // + 2x src/dst
    cudaFuncSetAttribute(gemm_root, cudaFuncAttributeMaxDynamicSharedMemorySize, SMEM_F16);
    cudaFuncSetAttribute(gemm_edge, cudaFuncAttributeMaxDynamicSharedMemorySize, SMEM_EDGE);
    cudaFuncSetAttribute(gemm_pred, cudaFuncAttributeMaxDynamicSharedMemorySize, SMEM_F16);

    cudaStream_t s1 = g_res.s1;

    // ===== fork 1: edge bucketing on s1, weight prep + root GEMM on main =====
    cudaEventRecord(g_res.evF1, 0);
    cudaStreamWaitEvent(s1, g_res.evF1, 0);

    edge_prefill<<<(TILES_CAP * 128 + 255) / 256, 256, 0, s1>>>();
    edge_hist<<<NCTA_E, 256, 0, s1>>>(edge_type);
    edge_prefix<<<1, 320, 0, s1>>>();
    edge_reorder<<<NCTA_E, 256, 0, s1>>>(edge_index, edge_type);

    build_BmainTh<<<((NR + 1) * EDIM * EDIM + 255) / 256, 256>>>(rgcn_W, rgcn_Wroot);
    gemm_root<<<(NE + 127) / 128, 256, SMEM_F16>>>(E_weight, pBmTh, NE);

    cudaEventRecord(g_res.evJ1, s1);
    cudaStreamWaitEvent(0, g_res.evJ1, 0);

    // ===== main: fused edge GEMM (2 tiles/CTA) + activation =====
    gemm_edge<<<TILES_CAP / 2, 256, SMEM_EDGE>>>(E_weight, pBmTh);
    tanh_root<<<(NE * (EDIM / 4) + 255) / 256, 256>>>(rgcn_b);

    // ===== fork 2: metapath/attention tail on s1, pred GEMM on main =====
    cudaEventRecord(g_res.evF2, 0);
    cudaStreamWaitEvent(s1, g_res.evF2, 0);

    init_mp<<<NREG, 128, 0, s1>>>(0, mp0_eids);
    init_mp<<<NREG, 128, 0, s1>>>(1, mp1_eids);
    cudaMemcpyAsync(pBmp, mp0_W, (size_t)NMP_REL * EDIM * HID * 4,
                    cudaMemcpyDeviceToDevice, s1);
    cudaMemcpyAsync(pBmp + NMP_REL * EDIM * HID, mp0_Wroot, (size_t)EDIM * HID * 4,
                    cudaMemcpyDeviceToDevice, s1);
    cudaMemcpyAsync(pBmp + KMP * HID, mp1_W, (size_t)NMP_REL * EDIM * HID * 4,
                    cudaMemcpyDeviceToDevice, s1);
    cudaMemcpyAsync(pBmp + KMP * HID + NMP_REL * EDIM * HID, mp1_Wroot,
                    (size_t)EDIM * HID * 4, cudaMemcpyDeviceToDevice, s1);
    scatter_mp<<<NMP_E / 8, 256, 0, s1>>>(0, mp0_ei, mp0_et, mp0_eids);
    scatter_mp<<<NMP_E / 8, 256, 0, s1>>>(1, mp1_ei, mp1_et, mp1_eids);
    gemm_tf32<<<dim3((NREG + 127) / 128, HID / 128), 256, 0, s1>>>(
        pmp, KMP, pBmp, HID, mp0_b, psem, HID, NREG, HID, KMP, 2);
    gemm_tf32<<<dim3((NREG + 127) / 128, HID / 128), 256, 0, s1>>>(
        pmp + (size_t)NREG * KMP, KMP, pBmp + (size_t)KMP * HID, HID, mp1_b,
        psem + (size_t)NREG * HID, HID, NREG, HID, KMP, 2);
    attn<<<dim3(NREG, 2), ATT, 0, s1>>>(sa_w1, sa_b1, sa_w2);
    finalk<<<NREG, EDIM, 0, s1>>>(pred_W, pred_b, out);

    // main: KGE pred = (E[h]*R[r]) @ E^T (2 M-tiles per CTA)
    build_x<<<NB, EDIM>>>(h_idx, r_idx, R_weight);
    gemm_pred<<<dim3(NB / 256, (NE + 127) / 128), 256, SMEM_F16>>>(
        pxh, pEh, out + NREG * EDIM, NB, NE, NE);

    cudaEventRecord(g_res.evJ2, s1);
    cudaStreamWaitEvent(0, g_res.evJ2, 0);
}

// round 12
// speedup vs baseline: 1.1888x; 1.0113x over previous
#include <cuda_runtime.h>
#include <cuda_fp16.h>
#include <math.h>
#include <stdint.h>

#define NE 100000
#define NR 10
#define EDIM 128
#define HID 256
#define NREG 2000
#define NKG 600000
#define NMP_REL 5
#define NMP_E 300000
#define NB 1024
#define ATT 128

#define KMP (NMP_REL * EDIM + EDIM) /* 768 */
#define NCTA_E ((NKG + 1023) / 1024) /* 586 histogram CTAs */
#define TILES_CAP 4704               /* multiple of 4; >= ceil((NKG + 10*127)/128) */
#define ECHUNK 4                     /* edge tiles per CTA */
#define PCHUNK 4                     /* pred M-tiles per CTA */

// ---------------- scratch ----------------------------------------------------
__device__ float g_Yroot[(size_t)(NE + 1) * EDIM];  // fp32 root + atomic accum (+dump row)
__device__ float g_E[(size_t)NE * EDIM];
__device__ __half g_Eh[(size_t)NE * EDIM];          // E fp16 (pred B operand)
__device__ __half g_BmainTh[(NR + 1) * EDIM * EDIM];  // [r][n][k] fp16 (+Wroot block)
__device__ float g_Bmp[2][KMP * HID];
__device__ __half g_xh[NB * EDIM];                  // (E[h]*R[r]) fp16
__device__ float g_mp[2][(size_t)NREG * KMP];       // metapath agg scratch
__device__ float g_sem[2][NREG * HID];
__device__ float g_w[2];
// edge bucketing
__device__ int2 g_esorted[TILES_CAP * 128];
__device__ int g_blockcnt[NCTA_E * 10];
__device__ int g_off[NCTA_E * 10];
__device__ int g_tiler[TILES_CAP];

// ---------------- side stream + events (host-side, created at load) -----------
namespace {
struct GraphResources {
    cudaStream_t s1;
    cudaEvent_t evF1, evJ1, evF2, evJ2;
    GraphResources() {
        cudaStreamCreateWithFlags(&s1, cudaStreamNonBlocking);
        cudaEventCreateWithFlags(&evF1, cudaEventDisableTiming);
        cudaEventCreateWithFlags(&evJ1, cudaEventDisableTiming);
        cudaEventCreateWithFlags(&evF2, cudaEventDisableTiming);
        cudaEventCreateWithFlags(&evJ2, cudaEventDisableTiming);
    }
};
GraphResources g_res;
}

// ---------------- primitives -------------------------------------------------
__device__ __forceinline__ void red_add_v4(float* addr, float4 v) {
    asm volatile("red.global.add.v4.f32 [%0], {%1, %2, %3, %4};"
                 :: "l"(addr), "f"(v.x), "f"(v.y), "f"(v.z), "f"(v.w) : "memory");
}
__device__ __forceinline__ void red_add_v2(float* addr, float x, float y) {
    asm volatile("red.global.add.v2.f32 [%0], {%1, %2};"
                 :: "l"(addr), "f"(x), "f"(y) : "memory");
}
__device__ __forceinline__ void mma16816(float* c, const uint32_t* a, const uint32_t* b) {
    asm volatile(
        "mma.sync.aligned.m16n8k16.row.col.f32.f16.f16.f32 "
        "{%0,%1,%2,%3}, {%4,%5,%6,%7}, {%8,%9}, {%0,%1,%2,%3};"
        : "+f"(c[0]), "+f"(c[1]), "+f"(c[2]), "+f"(c[3])
        : "r"(a[0]), "r"(a[1]), "r"(a[2]), "r"(a[3]), "r"(b[0]), "r"(b[1]));
}
__device__ __forceinline__ void ldsm_x4(uint32_t& r0, uint32_t& r1, uint32_t& r2, uint32_t& r3,
                                        uint32_t addr) {
    asm volatile("ldmatrix.sync.aligned.m8n8.x4.shared.b16 {%0,%1,%2,%3}, [%4];"
                 : "=r"(r0), "=r"(r1), "=r"(r2), "=r"(r3) : "r"(addr));
}
__device__ __forceinline__ float cvt_tf32(float x) {
    unsigned u;
    asm("cvt.rna.tf32.f32 %0, %1;" : "=r"(u) : "f"(x));
    return __uint_as_float(u);
}
__device__ __forceinline__ float4 cvt_tf32_4(float4 v) {
    return make_float4(cvt_tf32(v.x), cvt_tf32(v.y), cvt_tf32(v.z), cvt_tf32(v.w));
}
__device__ __forceinline__ void mma8(float* c, const unsigned* a, const unsigned* b) {
    asm volatile(
        "mma.sync.aligned.m16n8k8.row.col.f32.tf32.tf32.f32 "
        "{%0,%1,%2,%3}, {%4,%5,%6,%7}, {%8,%9}, {%0,%1,%2,%3};"
        : "+f"(c[0]), "+f"(c[1]), "+f"(c[2]), "+f"(c[3])
        : "r"(a[0]), "r"(a[1]), "r"(a[2]), "r"(a[3]), "r"(b[0]), "r"(b[1]));
}

// ---------------- fp16 K=128 MMA core (ldmatrix-fed) ---------------------------
#define SPAD 136
typedef __half htile_t[SPAD];

__device__ __forceinline__ void compute_k128(const htile_t* As, const htile_t* Bs,
                                             float c[2][8][4], int wm, int wn, int lane) {
    const int quad = lane >> 3, r = lane & 7;
    uint32_t aAddr[2], bAddr[4];
#pragma unroll
    for (int mt = 0; mt < 2; mt++)
        aAddr[mt] =
            (uint32_t)__cvta_generic_to_shared(&As[wm + mt * 16 + r + (quad & 1) * 8][(quad >> 1) * 8]);
#pragma unroll
    for (int p = 0; p < 4; p++)
        bAddr[p] =
            (uint32_t)__cvta_generic_to_shared(&Bs[wn + p * 16 + (quad >> 1) * 8 + r][(quad & 1) * 8]);

#pragma unroll
    for (int kb = 0; kb < 128; kb += 16) {
        uint32_t a[2][4], b[8][2];
#pragma unroll
        for (int mt = 0; mt < 2; mt++)
            ldsm_x4(a[mt][0], a[mt][1], a[mt][2], a[mt][3], aAddr[mt] + kb * 2);
#pragma unroll
        for (int p = 0; p < 4; p++)
            ldsm_x4(b[2 * p][0], b[2 * p][1], b[2 * p + 1][0], b[2 * p + 1][1], bAddr[p] + kb * 2);
#pragma unroll
        for (int mt = 0; mt < 2; mt++)
#pragma unroll
            for (int nt = 0; nt < 8; nt++) mma16816(c[mt][nt], a[mt], b[nt]);
    }
}
#define ZERO_C(c)                                  \
    _Pragma("unroll") for (int _i = 0; _i < 2; _i++) \
    _Pragma("unroll") for (int _j = 0; _j < 8; _j++) \
    _Pragma("unroll") for (int _l = 0; _l < 4; _l++) (c)[_i][_j][_l] = 0.f

// ---------------- edge bucketing ----------------------------------------------
__global__ void edge_prefill() {
    int i = blockIdx.x * blockDim.x + threadIdx.x;
    if (i < TILES_CAP * 128) g_esorted[i] = make_int2(0, NE);
}

__global__ void edge_hist(const int* __restrict__ et) {
    __shared__ int cnt[10];
    int tid = threadIdx.x;
    if (tid < 10) cnt[tid] = 0;
    __syncthreads();
    int base = blockIdx.x * 1024;
    for (int i = tid; i < 1024; i += 256) {
        int e = base + i;
        if (e < NKG) atomicAdd(&cnt[et[e]], 1);
    }
    __syncthreads();
    if (tid < 10) g_blockcnt[blockIdx.x * 10 + tid] = cnt[tid];
}

__global__ void edge_prefix() {
    __shared__ int pc[10], ps[11];
    const int warp = threadIdx.x >> 5, lane = threadIdx.x & 31;
    {
        int r = warp;
        int sum = 0;
        for (int base = 0; base < NCTA_E; base += 32) {
            int cIdx = base + lane;
            sum += (cIdx < NCTA_E) ? g_blockcnt[cIdx * 10 + r] : 0;
        }
#pragma unroll
        for (int o = 16; o; o >>= 1) sum += __shfl_xor_sync(0xFFFFFFFFu, sum, o);
        if (lane == 0) pc[r] = sum;
    }
    __syncthreads();
    if (threadIdx.x == 0) {
        int acc = 0;
        for (int r = 0; r < 10; r++) { ps[r] = acc; acc += ((pc[r] + 127) >> 7) << 7; }
        ps[10] = acc;
    }
    __syncthreads();
    {
        int r = warp;
        int acc = ps[r];
        for (int base = 0; base < NCTA_E; base += 32) {
            int cIdx = base + lane;
            int v = (cIdx < NCTA_E) ? g_blockcnt[cIdx * 10 + r] : 0;
            int x = v;
#pragma unroll
            for (int o = 1; o < 32; o <<= 1) {
                int y = __shfl_up_sync(0xFFFFFFFFu, x, o);
                if (lane >= o) x += y;
            }
            if (cIdx < NCTA_E) g_off[cIdx * 10 + r] = acc + (x - v);
            acc += __shfl_sync(0xFFFFFFFFu, x, 31);
        }
    }
    __syncthreads();
    for (int tIdx = threadIdx.x; tIdx < TILES_CAP; tIdx += blockDim.x) {
        int pos = tIdx * 128;
        int r = 9;
#pragma unroll
        for (int q = 0; q < 10; q++)
            if (pos >= ps[q] && pos < ps[q + 1]) { r = q; break; }
        g_tiler[tIdx] = r;
    }
}

__global__ void edge_reorder(const int* __restrict__ ei, const int* __restrict__ et) {
    __shared__ int cur[10];
    int tid = threadIdx.x;
    if (tid < 10) cur[tid] = g_off[blockIdx.x * 10 + tid];
    __syncthreads();
    int base = blockIdx.x * 1024;
    for (int i = tid; i < 1024; i += 256) {
        int e = base + i;
        if (e < NKG) {
            int slot = atomicAdd(&cur[et[e]], 1);
            g_esorted[slot] = make_int2(ei[e], ei[NKG + e]);
        }
    }
}

// ---------------- gemm_root: Yroot = X[M,128](fp32) @ Wroot^T ------------------
__global__ __launch_bounds__(256, 2)
void gemm_root(const float* __restrict__ A, const __half* __restrict__ Bt, int M) {
    extern __shared__ __half sm[];
    htile_t* As = (htile_t*)sm;
    htile_t* Bs = (htile_t*)(sm + 128 * SPAD);
    const int tid = threadIdx.x, lane = tid & 31, warp = tid >> 5;
    const int g = lane >> 2, t = lane & 3;
    const int wm = (warp >> 1) * 32, wn = (warp & 1) * 64;
    const int m0 = blockIdx.x * 128;
    const int arows = (M - m0 < 128) ? (M - m0) : 128;

    {
        const float4 zf = make_float4(0.f, 0.f, 0.f, 0.f);
#pragma unroll
        for (int l = 0; l < 16; l++) {
            int e = l * 256 + tid;
            int r = e >> 5, c4 = (e & 31) * 4;
            float4 v = (r < arows) ? *(const float4*)&A[(size_t)(m0 + r) * 128 + c4] : zf;
            __half2 h0 = __floats2half2_rn(v.x, v.y);
            __half2 h1 = __floats2half2_rn(v.z, v.w);
            *(uint2*)&As[r][c4] = make_uint2(*(uint32_t*)&h0, *(uint32_t*)&h1);
        }
#pragma unroll
        for (int l = 0; l < 8; l++) {
            int e = l * 256 + tid;
            int r = e >> 4, c8 = (e & 15) * 8;
            *(uint4*)&Bs[r][c8] = *(const uint4*)&Bt[(size_t)(NR * 128 + r) * 128 + c8];
        }
    }
    __syncthreads();

    float c[2][8][4];
    ZERO_C(c);
    compute_k128(As, Bs, c, wm, wn, lane);

#pragma unroll
    for (int mt = 0; mt < 2; mt++) {
#pragma unroll
        for (int h = 0; h < 2; h++) {
            int row = m0 + wm + mt * 16 + g + h * 8;
            if (row >= M) continue;
            float* cp = g_Yroot + (size_t)row * 128;
#pragma unroll
            for (int j = 0; j < 8; j++) {
                int col = wn + j * 8 + 2 * t;
                *(float2*)(cp + col) = make_float2(c[mt][j][h * 2], c[mt][j][h * 2 + 1]);
            }
        }
    }
}

// ---------------- gemm_edge: ECHUNK edge-tiles per CTA, B reused per relation --
__global__ __launch_bounds__(256, 2)
void gemm_edge(const float* __restrict__ X, const __half* __restrict__ Bt) {
    extern __shared__ __half sm[];
    htile_t* As = (htile_t*)sm;
    htile_t* Bs = (htile_t*)(sm + 128 * SPAD);
    int* ssrc = (int*)(sm + 2 * 128 * SPAD);      // [ECHUNK][128]
    int* sdst = ssrc + ECHUNK * 128;               // [ECHUNK][128]
    const int tid = threadIdx.x, lane = tid & 31, warp = tid >> 5;
    const int g = lane >> 2, t = lane & 3;
    const int wm = (warp >> 1) * 32, wn = (warp & 1) * 64;
    const int tile0 = blockIdx.x * ECHUNK;

    // indices for all sub-tiles
    for (int i = tid; i < ECHUNK * 128; i += 256) {
        int2 rec = g_esorted[(size_t)tile0 * 128 + i];
        ssrc[i] = rec.x;
        sdst[i] = rec.y;
    }
    int rels[ECHUNK];
#pragma unroll
    for (int i = 0; i < ECHUNK; i++) rels[i] = g_tiler[tile0 + i];

    // B = W_{r0}
    {
        const __half* Bp = Bt + (size_t)rels[0] * 128 * 128;
#pragma unroll
        for (int l = 0; l < 8; l++) {
            int e = l * 256 + tid;
            int rr = e >> 4, c8 = (e & 15) * 8;
            *(uint4*)&Bs[rr][c8] = *(const uint4*)&Bp[(size_t)rr * 128 + c8];
        }
    }
    __syncthreads();

    // A0 gather
#pragma unroll
    for (int l = 0; l < 16; l++) {
        int e = l * 256 + tid;
        int row = e >> 5, c4 = (e & 31) * 4;
        float4 v = *(const float4*)&X[(size_t)ssrc[row] * 128 + c4];
        __half2 h0 = __floats2half2_rn(v.x, v.y);
        __half2 h1 = __floats2half2_rn(v.z, v.w);
        *(uint2*)&As[row][c4] = make_uint2(*(uint32_t*)&h0, *(uint32_t*)&h1);
    }
    __syncthreads();

    float c[2][8][4];
#pragma unroll
    for (int i = 0; i < ECHUNK; i++) {
        ZERO_C(c);
        compute_k128(As, Bs, c, wm, wn, lane);
        __syncthreads();  // everyone done reading As/Bs

        if (i + 1 < ECHUNK) {
            // A(i+1) gather (+B reload at relation boundary) — overlaps epilogue i
#pragma unroll
            for (int l = 0; l < 16; l++) {
                int e = l * 256 + tid;
                int row = e >> 5, c4 = (e & 31) * 4;
                float4 v = *(const float4*)&X[(size_t)ssrc[(i + 1) * 128 + row] * 128 + c4];
                __half2 h0 = __floats2half2_rn(v.x, v.y);
                __half2 h1 = __floats2half2_rn(v.z, v.w);
                *(uint2*)&As[row][c4] = make_uint2(*(uint32_t*)&h0, *(uint32_t*)&h1);
            }
            if (rels[i + 1] != rels[i]) {
                const __half* Bp = Bt + (size_t)rels[i + 1] * 128 * 128;
#pragma unroll
                for (int l = 0; l < 8; l++) {
                    int e = l * 256 + tid;
                    int rr = e >> 4, c8 = (e & 15) * 8;
                    *(uint4*)&Bs[rr][c8] = *(const uint4*)&Bp[(size_t)rr * 128 + c8];
                }
            }
        }
        // epilogue i (atomics; overlaps the loads above)
        const int* dsti = sdst + i * 128;
#pragma unroll
        for (int mt = 0; mt < 2; mt++) {
#pragma unroll
            for (int h = 0; h < 2; h++) {
                int rowi = wm + mt * 16 + g + h * 8;
                float* bp = g_Yroot + (size_t)dsti[rowi] * 128;
#pragma unroll
                for (int nt = 0; nt < 8; nt++) {
                    int col = wn + nt * 8 + 2 * t;
                    red_add_v2(bp + col, c[mt][nt][h * 2], c[mt][nt][h * 2 + 1]);
                }
            }
        }
        if (i + 1 < ECHUNK) __syncthreads();
    }
}

// ---------------- pred: PCHUNK M-tiles per CTA sharing the B (Eh) tile ---------
__global__ __launch_bounds__(256, 2)
void gemm_pred(const __half* __restrict__ A, const __half* __restrict__ Bt,
               float* __restrict__ C, int M, int N, size_t ldc) {
    extern __shared__ __half sm[];
    htile_t* As = (htile_t*)sm;
    htile_t* Bs = (htile_t*)(sm + 128 * SPAD);
    const int tid = threadIdx.x, lane = tid & 31, warp = tid >> 5;
    const int g = lane >> 2, t = lane & 3;
    const int wm = (warp >> 1) * 32, wn = (warp & 1) * 64;
    const int mbase = blockIdx.x * (128 * PCHUNK), n0 = blockIdx.y * 128;

    const uint4 z = make_uint4(0, 0, 0, 0);
    // B tile once
#pragma unroll
    for (int l = 0; l < 8; l++) {
        int e = l * 256 + tid;
        int r = e >> 4, c8 = (e & 15) * 8;
        *(uint4*)&Bs[r][c8] = (n0 + r < N) ? *(const uint4*)&Bt[(size_t)(n0 + r) * 128 + c8] : z;
    }
    // A sub-tile 0
#pragma unroll
    for (int l = 0; l < 8; l++) {
        int e = l * 256 + tid;
        int r = e >> 4, c8 = (e & 15) * 8;
        *(uint4*)&As[r][c8] =
            (mbase + r < M) ? *(const uint4*)&A[(size_t)(mbase + r) * 128 + c8] : z;
    }
    __syncthreads();

    float c[2][8][4];
#pragma unroll
    for (int i = 0; i < PCHUNK; i++) {
        ZERO_C(c);
        compute_k128(As, Bs, c, wm, wn, lane);
        __syncthreads();

        if (i + 1 < PCHUNK) {
            int m1 = mbase + (i + 1) * 128;
#pragma unroll
            for (int l = 0; l < 8; l++) {
                int e = l * 256 + tid;
                int r = e >> 4, c8 = (e & 15) * 8;
                *(uint4*)&As[r][c8] =
                    (m1 + r < M) ? *(const uint4*)&A[(size_t)(m1 + r) * 128 + c8] : z;
            }
        }
        // epilogue i
        int mi = mbase + i * 128;
#pragma unroll
        for (int mt = 0; mt < 2; mt++) {
#pragma unroll
            for (int h = 0; h < 2; h++) {
                int row = mi + wm + mt * 16 + g + h * 8;
                if (row >= M) continue;
#pragma unroll
                for (int nt = 0; nt < 8; nt++) {
                    int col = n0 + wn + nt * 8 + 2 * t;
                    if (col >= N) continue;
                    *(float2*)&C[(size_t)row * ldc + col] =
                        make_float2(c[mt][nt][h * 2 + 0], c[mt][nt][h * 2 + 1]);
                }
            }
        }
        if (i + 1 < PCHUNK) __syncthreads();
    }
}

// ---------------- tf32 mma GEMM (metapath GEMMs, K=768) ----------------------
__global__ __launch_bounds__(256)
void gemm_tf32(const float* __restrict__ A, int lda, const float* __restrict__ B, int ldb,
               const float* __restrict__ bias, float* __restrict__ C, int ldc,
               int M, int N, int K, int act) {
    __shared__ float As[2][128][20];
    __shared__ float Bs[2][16][136];
    const int bm = blockIdx.x * 128;
    const int bn = blockIdx.y * 128;
    const int tid = threadIdx.x;
    const int lane = tid & 31;
    const int warp = tid >> 5;
    const int g = lane >> 2, t = lane & 3;
    const int wm = (warp >> 1) * 32;
    const int wn = (warp & 1) * 64;

    float c[2][8][4];
    ZERO_C(c);

    float4 ar[2], br[2];
    const float4 z4 = make_float4(0.f, 0.f, 0.f, 0.f);

    auto ldg = [&](int k0) {
#pragma unroll
        for (int l = 0; l < 2; l++) {
            int e = tid + l * 256;
            int m = e >> 2, k4 = (e & 3) * 4;
            int gm = bm + m;
            ar[l] = (gm < M) ? *(const float4*)&A[(size_t)gm * lda + k0 + k4] : z4;
            int kr = e >> 5, nc = (e & 31) * 4;
            int gc = bn + nc;
            br[l] = (gc < N) ? *(const float4*)&B[(size_t)(k0 + kr) * ldb + gc] : z4;
        }
    };
    auto sts = [&](int buf) {
#pragma unroll
        for (int l = 0; l < 2; l++) {
            int e = tid + l * 256;
            int m = e >> 2, k4 = (e & 3) * 4;
            float4 a4 = cvt_tf32_4(ar[l]);
            As[buf][m][k4 + 0] = a4.x;
            As[buf][m][k4 + 1] = a4.y;
            As[buf][m][k4 + 2] = a4.z;
            As[buf][m][k4 + 3] = a4.w;
            int kr = e >> 5, nc = (e & 31) * 4;
            *(float4*)&Bs[buf][kr][nc] = cvt_tf32_4(br[l]);
        }
    };
    auto compute = [&](int buf) {
#pragma unroll
        for (int kk = 0; kk < 2; kk++) {
            const int kb = kk * 8;
            unsigned a[2][4], b[8][2];
#pragma unroll
            for (int mt = 0; mt < 2; mt++) {
                int row = wm + mt * 16 + g;
                a[mt][0] = __float_as_uint(As[buf][row][kb + t]);
                a[mt][1] = __float_as_uint(As[buf][row + 8][kb + t]);
                a[mt][2] = __float_as_uint(As[buf][row][kb + t + 4]);
                a[mt][3] = __float_as_uint(As[buf][row + 8][kb + t + 4]);
            }
#pragma unroll
            for (int nt = 0; nt < 8; nt++) {
                int col = wn + nt * 8 + g;
                b[nt][0] = __float_as_uint(Bs[buf][kb + t][col]);
                b[nt][1] = __float_as_uint(Bs[buf][kb + t + 4][col]);
            }
#pragma unroll
            for (int mt = 0; mt < 2; mt++)
#pragma unroll
                for (int nt = 0; nt < 8; nt++) mma8(c[mt][nt], a[mt], b[nt]);
        }
    };

    const int iters = K >> 4;
    ldg(0);
    sts(0);
    __syncthreads();
    for (int it = 0; it < iters; it++) {
        int buf = it & 1;
        if (it + 1 < iters) ldg((it + 1) << 4);
        compute(buf);
        if (it + 1 < iters) sts(buf ^ 1);
        __syncthreads();
    }

#pragma unroll
    for (int mt = 0; mt < 2; mt++) {
#pragma unroll
        for (int h = 0; h < 2; h++) {
            int row = bm + wm + mt * 16 + g + h * 8;
            if (row >= M) continue;
#pragma unroll
            for (int nt = 0; nt < 8; nt++) {
                int col = bn + wn + nt * 8 + 2 * t;
                if (col >= N) continue;
                float v0 = c[mt][nt][h * 2 + 0];
                float v1 = c[mt][nt][h * 2 + 1];
                if (bias) { v0 += bias[col]; v1 += bias[col + 1]; }
                if (act == 2) { v0 = fmaxf(v0, 0.f); v1 = fmaxf(v1, 0.f); }
                *(float2*)&C[(size_t)row * ldc + col] = make_float2(v0, v1);
            }
        }
    }
}

// ---------------- stage 1 aux -------------------------------------------------
__global__ void build_BmainTh(const float* __restrict__ W, const float* __restrict__ Wroot) {
    int i = blockIdx.x * blockDim.x + threadIdx.x;
    if (i >= (NR + 1) * EDIM * EDIM) return;
    int n = i >> 7, k = i & 127;
    int r = n >> 7, o = n & 127;
    float v = (r < NR) ? W[((size_t)r * EDIM + k) * EDIM + o] : Wroot[(size_t)k * EDIM + o];
    g_BmainTh[i] = __float2half_rn(v);
}

__global__ void tanh_root(const float* __restrict__ b) {
    int i = blockIdx.x * blockDim.x + threadIdx.x;
    if (i >= NE * (EDIM / 4)) return;
    int n = i >> 5, j = (i & 31) * 4;
    float4 v = *(const float4*)&g_Yroot[(size_t)n * EDIM + j];
    float4 bb = *(const float4*)&b[j];
    v.x = tanhf(v.x + bb.x);
    v.y = tanhf(v.y + bb.y);
    v.z = tanhf(v.z + bb.z);
    v.w = tanhf(v.w + bb.w);
    *(float4*)&g_E[(size_t)n * EDIM + j] = v;
    __half2* eh = (__half2*)&g_Eh[(size_t)n * EDIM + j];
    eh[0] = __floats2half2_rn(v.x, v.y);
    eh[1] = __floats2half2_rn(v.z, v.w);
}

// ---------------- stage 2 aux ---------------------------------------------------
__global__ void build_x(const int* __restrict__ h_idx, const int* __restrict__ r_idx,
                        const float* __restrict__ R) {
    int b = blockIdx.x, i = threadIdx.x;
    float v = g_E[(size_t)h_idx[b] * EDIM + i] * R[(size_t)r_idx[b] * EDIM + i];
    g_xh[b * EDIM + i] = __float2half_rn(v);
}

// ---------------- stage 3: metapath RGCNs --------------------------------------
__global__ void init_mp(int m, const int* __restrict__ eids) {
    int n = blockIdx.x;
    float* row = g_mp[m] + (size_t)n * KMP;
    const float4* er = (const float4*)(g_E + (size_t)eids[n] * EDIM);
    const float4 z = make_float4(0.f, 0.f, 0.f, 0.f);
    for (int j = threadIdx.x; j < KMP / 4; j += blockDim.x)
        ((float4*)row)[j] = (j < (KMP - EDIM) / 4) ? z : er[j - (KMP - EDIM) / 4];
    if (blockIdx.x == 0 && threadIdx.x < 2) g_w[threadIdx.x] = 0.f;
}

__global__ void scatter_mp(int m, const int* __restrict__ ei, const int* __restrict__ et,
                           const int* __restrict__ eids) {
    int w = (blockIdx.x * blockDim.x + threadIdx.x) >> 5;
    int lane = threadIdx.x & 31;
    if (w >= NMP_E) return;
    int dst = ei[NMP_E + w];
    if (dst >= NREG) return;  // output sliced [:NREG]
    int src = ei[w];
    int r = et[w];
    float4 v = *(const float4*)(g_E + (size_t)eids[src] * EDIM + lane * 4);
    red_add_v4(g_mp[m] + (size_t)dst * KMP + r * EDIM + lane * 4, v);
}

// ---------------- stage 4: semantic attention + head ---------------------------
__global__ void attn(const float* __restrict__ w1, const float* __restrict__ b1,
                     const float* __restrict__ w2) {
    int n = blockIdx.x, m = blockIdx.y, tid = threadIdx.x;
    __shared__ float z[HID];
    __shared__ float red[ATT];
    const float* zp = &g_sem[m][(size_t)n * HID];
    z[tid] = zp[tid];
    z[tid + 128] = zp[tid + 128];
    __syncthreads();
    float acc = b1[tid];
#pragma unroll 8
    for (int k = 0; k < HID; k++) acc = fmaf(z[k], w1[k * ATT + tid], acc);
    red[tid] = tanhf(acc) * w2[tid];
    __syncthreads();
    for (int s = 64; s > 0; s >>= 1) {
        if (tid < s) red[tid] += red[tid + s];
        __syncthreads();
    }
    if (tid == 0) atomicAdd(&g_w[m], red[0] * (1.0f / NREG));
}

__global__ void finalk(const float* __restrict__ predW, const float* __restrict__ predb,
                       float* __restrict__ out) {
    int n = blockIdx.x, tid = threadIdx.x;
    __shared__ float h[HID];
    float w0 = g_w[0], w1v = g_w[1];
    float mx = fmaxf(w0, w1v);
    float e0 = expf(w0 - mx), e1 = expf(w1v - mx);
    float inv = 1.f / (e0 + e1);
    float b0 = e0 * inv, b1 = e1 * inv;
    h[tid] = b0 * g_sem[0][(size_t)n * HID + tid] + b1 * g_sem[1][(size_t)n * HID + tid];
    h[tid + 128] =
        b0 * g_sem[0][(size_t)n * HID + tid + 128] + b1 * g_sem[1][(size_t)n * HID + tid + 128];
    __syncthreads();
    float acc = predb[tid] + g_E[(size_t)n * EDIM + tid];
#pragma unroll 8
    for (int k = 0; k < HID; k++) acc = fmaf(h[k], predW[k * EDIM + tid], acc);
    out[(size_t)n * EDIM + tid] = acc;
}

// ---------------- launch ------------------------------------------------------
extern "C" void kernel_launch(void* const* d_in, const int* in_sizes, int n_in,
                              void* d_out, int out_size) {
    const float* E_weight = (const float*)d_in[0];
    const float* R_weight = (const float*)d_in[1];
    const float* rgcn_W = (const float*)d_in[2];
    const float* rgcn_Wroot = (const float*)d_in[3];
    const float* rgcn_b = (const float*)d_in[4];
    const float* mp0_W = (const float*)d_in[5];
    const float* mp0_Wroot = (const float*)d_in[6];
    const float* mp0_b = (const float*)d_in[7];
    const float* mp1_W = (const float*)d_in[8];
    const float* mp1_Wroot = (const float*)d_in[9];
    const float* mp1_b = (const float*)d_in[10];
    const float* sa_w1 = (const float*)d_in[11];
    const float* sa_b1 = (const float*)d_in[12];
    const float* sa_w2 = (const float*)d_in[13];
    const float* pred_W = (const float*)d_in[14];
    const float* pred_b = (const float*)d_in[15];
    const int* h_idx = (const int*)d_in[16];
    const int* r_idx = (const int*)d_in[17];
    const int* edge_index = (const int*)d_in[18];
    const int* edge_type = (const int*)d_in[19];
    const int* mp0_ei = (const int*)d_in[20];
    const int* mp0_et = (const int*)d_in[21];
    const int* mp0_eids = (const int*)d_in[22];
    const int* mp1_ei = (const int*)d_in[23];
    const int* mp1_et = (const int*)d_in[24];
    const int* mp1_eids = (const int*)d_in[25];
    float* out = (float*)d_out;  // [E_reg 2000*128 | pred 1024*100000]

    float *pBmp, *psem, *pmp;
    __half *pEh, *pBmTh, *pxh;
    cudaGetSymbolAddress((void**)&pBmp, g_Bmp);
    cudaGetSymbolAddress((void**)&psem, g_sem);
    cudaGetSymbolAddress((void**)&pmp, g_mp);
    cudaGetSymbolAddress((void**)&pEh, g_Eh);
    cudaGetSymbolAddress((void**)&pBmTh, g_BmainTh);
    cudaGetSymbolAddress((void**)&pxh, g_xh);

    const int SMEM_F16 = 2 * 128 * SPAD * (int)sizeof(__half);              // 69,632 B
    const int SMEM_EDGE = SMEM_F16 + 2 * ECHUNK * 128 * (int)sizeof(int);   // + idx
    cudaFuncSetAttribute(gemm_root, cudaFuncAttributeMaxDynamicSharedMemorySize, SMEM_F16);
    cudaFuncSetAttribute(gemm_edge, cudaFuncAttributeMaxDynamicSharedMemorySize, SMEM_EDGE);
    cudaFuncSetAttribute(gemm_pred, cudaFuncAttributeMaxDynamicSharedMemorySize, SMEM_F16);

    cudaStream_t s1 = g_res.s1;

    // ===== fork 1: edge bucketing on s1, weight prep + root GEMM on main =====
    cudaEventRecord(g_res.evF1, 0);
    cudaStreamWaitEvent(s1, g_res.evF1, 0);

    edge_prefill<<<(TILES_CAP * 128 + 255) / 256, 256, 0, s1>>>();
    edge_hist<<<NCTA_E, 256, 0, s1>>>(edge_type);
    edge_prefix<<<1, 320, 0, s1>>>();
    edge_reorder<<<NCTA_E, 256, 0, s1>>>(edge_index, edge_type);

    build_BmainTh<<<((NR + 1) * EDIM * EDIM + 255) / 256, 256>>>(rgcn_W, rgcn_Wroot);
    gemm_root<<<(NE + 127) / 128, 256, SMEM_F16>>>(E_weight, pBmTh, NE);

    cudaEventRecord(g_res.evJ1, s1);
    cudaStreamWaitEvent(0, g_res.evJ1, 0);

    // ===== main: fused edge GEMM (ECHUNK tiles/CTA) + activation =====
    gemm_edge<<<TILES_CAP / ECHUNK, 256, SMEM_EDGE>>>(E_weight, pBmTh);
    tanh_root<<<(NE * (EDIM / 4) + 255) / 256, 256>>>(rgcn_b);

    // ===== fork 2: metapath/attention tail on s1, pred GEMM on main =====
    cudaEventRecord(g_res.evF2, 0);
    cudaStreamWaitEvent(s1, g_res.evF2, 0);

    init_mp<<<NREG, 128, 0, s1>>>(0, mp0_eids);
    init_mp<<<NREG, 128, 0, s1>>>(1, mp1_eids);
    cudaMemcpyAsync(pBmp, mp0_W, (size_t)NMP_REL * EDIM * HID * 4,
                    cudaMemcpyDeviceToDevice, s1);
    cudaMemcpyAsync(pBmp + NMP_REL * EDIM * HID, mp0_Wroot, (size_t)EDIM * HID * 4,
                    cudaMemcpyDeviceToDevice, s1);
    cudaMemcpyAsync(pBmp + KMP * HID, mp1_W, (size_t)NMP_REL * EDIM * HID * 4,
                    cudaMemcpyDeviceToDevice, s1);
    cudaMemcpyAsync(pBmp + KMP * HID + NMP_REL * EDIM * HID, mp1_Wroot,
                    (size_t)EDIM * HID * 4, cudaMemcpyDeviceToDevice, s1);
    scatter_mp<<<NMP_E / 8, 256, 0, s1>>>(0, mp0_ei, mp0_et, mp0_eids);
    scatter_mp<<<NMP_E / 8, 256, 0, s1>>>(1, mp1_ei, mp1_et, mp1_eids);
    gemm_tf32<<<dim3((NREG + 127) / 128, HID / 128), 256, 0, s1>>>(
        pmp, KMP, pBmp, HID, mp0_b, psem, HID, NREG, HID, KMP, 2);
    gemm_tf32<<<dim3((NREG + 127) / 128, HID / 128), 256, 0, s1>>>(
        pmp + (size_t)NREG * KMP, KMP, pBmp + (size_t)KMP * HID, HID, mp1_b,
        psem + (size_t)NREG * HID, HID, NREG, HID, KMP, 2);
    attn<<<dim3(NREG, 2), ATT, 0, s1>>>(sa_w1, sa_b1, sa_w2);
    finalk<<<NREG, EDIM, 0, s1>>>(pred_W, pred_b, out);

    // main: KGE pred = (E[h]*R[r]) @ E^T (PCHUNK M-tiles per CTA)
    build_x<<<NB, EDIM>>>(h_idx, r_idx, R_weight);
    gemm_pred<<<dim3(NB / (128 * PCHUNK), (NE + 127) / 128), 256, SMEM_F16>>>(
        pxh, pEh, out + NREG * EDIM, NB, NE, NE);

    cudaEventRecord(g_res.evJ2, s1);
    cudaStreamWaitEvent(0, g_res.evJ2, 0);
}

// round 13
// speedup vs baseline: 1.2903x; 1.0854x over previous
#include <cuda_runtime.h>
#include <cuda_fp16.h>
#include <math.h>
#include <stdint.h>

#define NE 100000
#define NR 10
#define EDIM 128
#define HID 256
#define NREG 2000
#define NKG 600000
#define NMP_REL 5
#define NMP_E 300000
#define NB 1024
#define ATT 128

#define KMP (NMP_REL * EDIM + EDIM) /* 768 */
#define NCTA_E ((NKG + 1023) / 1024) /* 586 histogram CTAs */
#define TILES_CAP 4704               /* multiple of 8; >= ceil((NKG + 10*127)/128) */
#define ECHUNK 8                     /* edge tiles per CTA */
#define PCHUNK 8                     /* pred M-tiles per CTA */

// ---------------- scratch ----------------------------------------------------
__device__ float g_Yroot[(size_t)(NE + 1) * EDIM];  // fp32 root + atomic accum (+dump row)
__device__ float g_E[(size_t)NE * EDIM];
__device__ __half g_Eh[(size_t)NE * EDIM];          // E fp16 (pred B operand)
__device__ __half g_Xh[(size_t)NE * EDIM];          // E_weight fp16 (stage-1 A operand)
__device__ __half g_BmainTh[(NR + 1) * EDIM * EDIM];  // [r][n][k] fp16 (+Wroot block)
__device__ float g_Bmp[2][KMP * HID];
__device__ __half g_xh[NB * EDIM];                  // (E[h]*R[r]) fp16
__device__ float g_mp[2][(size_t)NREG * KMP];       // metapath agg scratch
__device__ float g_sem[2][NREG * HID];
__device__ float g_w[2];
// edge bucketing
__device__ int2 g_esorted[TILES_CAP * 128];
__device__ int g_blockcnt[NCTA_E * 10];
__device__ int g_off[NCTA_E * 10];
__device__ int g_tiler[TILES_CAP];

// ---------------- side stream + events (host-side, created at load) -----------
namespace {
struct GraphResources {
    cudaStream_t s1;
    cudaEvent_t evF1, evJ1, evF2, evJ2;
    GraphResources() {
        cudaStreamCreateWithFlags(&s1, cudaStreamNonBlocking);
        cudaEventCreateWithFlags(&evF1, cudaEventDisableTiming);
        cudaEventCreateWithFlags(&evJ1, cudaEventDisableTiming);
        cudaEventCreateWithFlags(&evF2, cudaEventDisableTiming);
        cudaEventCreateWithFlags(&evJ2, cudaEventDisableTiming);
    }
};
GraphResources g_res;
}

// ---------------- primitives -------------------------------------------------
__device__ __forceinline__ void red_add_v4(float* addr, float4 v) {
    asm volatile("red.global.add.v4.f32 [%0], {%1, %2, %3, %4};"
                 :: "l"(addr), "f"(v.x), "f"(v.y), "f"(v.z), "f"(v.w) : "memory");
}
__device__ __forceinline__ void red_add_v2(float* addr, float x, float y) {
    asm volatile("red.global.add.v2.f32 [%0], {%1, %2};"
                 :: "l"(addr), "f"(x), "f"(y) : "memory");
}
__device__ __forceinline__ void mma16816(float* c, const uint32_t* a, const uint32_t* b) {
    asm volatile(
        "mma.sync.aligned.m16n8k16.row.col.f32.f16.f16.f32 "
        "{%0,%1,%2,%3}, {%4,%5,%6,%7}, {%8,%9}, {%0,%1,%2,%3};"
        : "+f"(c[0]), "+f"(c[1]), "+f"(c[2]), "+f"(c[3])
        : "r"(a[0]), "r"(a[1]), "r"(a[2]), "r"(a[3]), "r"(b[0]), "r"(b[1]));
}
__device__ __forceinline__ void ldsm_x4(uint32_t& r0, uint32_t& r1, uint32_t& r2, uint32_t& r3,
                                        uint32_t addr) {
    asm volatile("ldmatrix.sync.aligned.m8n8.x4.shared.b16 {%0,%1,%2,%3}, [%4];"
                 : "=r"(r0), "=r"(r1), "=r"(r2), "=r"(r3) : "r"(addr));
}
__device__ __forceinline__ float cvt_tf32(float x) {
    unsigned u;
    asm("cvt.rna.tf32.f32 %0, %1;" : "=r"(u) : "f"(x));
    return __uint_as_float(u);
}
__device__ __forceinline__ float4 cvt_tf32_4(float4 v) {
    return make_float4(cvt_tf32(v.x), cvt_tf32(v.y), cvt_tf32(v.z), cvt_tf32(v.w));
}
__device__ __forceinline__ void mma8(float* c, const unsigned* a, const unsigned* b) {
    asm volatile(
        "mma.sync.aligned.m16n8k8.row.col.f32.tf32.tf32.f32 "
        "{%0,%1,%2,%3}, {%4,%5,%6,%7}, {%8,%9}, {%0,%1,%2,%3};"
        : "+f"(c[0]), "+f"(c[1]), "+f"(c[2]), "+f"(c[3])
        : "r"(a[0]), "r"(a[1]), "r"(a[2]), "r"(a[3]), "r"(b[0]), "r"(b[1]));
}

// ---------------- fp16 K=128 MMA core (ldmatrix-fed) ---------------------------
#define SPAD 136
typedef __half htile_t[SPAD];

__device__ __forceinline__ void compute_k128(const htile_t* As, const htile_t* Bs,
                                             float c[2][8][4], int wm, int wn, int lane) {
    const int quad = lane >> 3, r = lane & 7;
    uint32_t aAddr[2], bAddr[4];
#pragma unroll
    for (int mt = 0; mt < 2; mt++)
        aAddr[mt] =
            (uint32_t)__cvta_generic_to_shared(&As[wm + mt * 16 + r + (quad & 1) * 8][(quad >> 1) * 8]);
#pragma unroll
    for (int p = 0; p < 4; p++)
        bAddr[p] =
            (uint32_t)__cvta_generic_to_shared(&Bs[wn + p * 16 + (quad >> 1) * 8 + r][(quad & 1) * 8]);

#pragma unroll
    for (int kb = 0; kb < 128; kb += 16) {
        uint32_t a[2][4], b[8][2];
#pragma unroll
        for (int mt = 0; mt < 2; mt++)
            ldsm_x4(a[mt][0], a[mt][1], a[mt][2], a[mt][3], aAddr[mt] + kb * 2);
#pragma unroll
        for (int p = 0; p < 4; p++)
            ldsm_x4(b[2 * p][0], b[2 * p][1], b[2 * p + 1][0], b[2 * p + 1][1], bAddr[p] + kb * 2);
#pragma unroll
        for (int mt = 0; mt < 2; mt++)
#pragma unroll
            for (int nt = 0; nt < 8; nt++) mma16816(c[mt][nt], a[mt], b[nt]);
    }
}
#define ZERO_C(c)                                  \
    _Pragma("unroll") for (int _i = 0; _i < 2; _i++) \
    _Pragma("unroll") for (int _j = 0; _j < 8; _j++) \
    _Pragma("unroll") for (int _l = 0; _l < 4; _l++) (c)[_i][_j][_l] = 0.f

// ---------------- conversions ---------------------------------------------------
__global__ void f2h(const float* __restrict__ src, __half* __restrict__ dst, int n4) {
    int i = blockIdx.x * blockDim.x + threadIdx.x;
    if (i >= n4) return;
    float4 v = ((const float4*)src)[i];
    __half2 h0 = __floats2half2_rn(v.x, v.y);
    __half2 h1 = __floats2half2_rn(v.z, v.w);
    ((uint2*)dst)[i] = make_uint2(*(uint32_t*)&h0, *(uint32_t*)&h1);
}

// ---------------- edge bucketing ----------------------------------------------
__global__ void edge_prefill() {
    int i = blockIdx.x * blockDim.x + threadIdx.x;
    if (i < TILES_CAP * 128) g_esorted[i] = make_int2(0, NE);
}

__global__ void edge_hist(const int* __restrict__ et) {
    __shared__ int cnt[10];
    int tid = threadIdx.x;
    if (tid < 10) cnt[tid] = 0;
    __syncthreads();
    int base = blockIdx.x * 1024;
    for (int i = tid; i < 1024; i += 256) {
        int e = base + i;
        if (e < NKG) atomicAdd(&cnt[et[e]], 1);
    }
    __syncthreads();
    if (tid < 10) g_blockcnt[blockIdx.x * 10 + tid] = cnt[tid];
}

__global__ void edge_prefix() {
    __shared__ int pc[10], ps[11];
    const int warp = threadIdx.x >> 5, lane = threadIdx.x & 31;
    {
        int r = warp;
        int sum = 0;
        for (int base = 0; base < NCTA_E; base += 32) {
            int cIdx = base + lane;
            sum += (cIdx < NCTA_E) ? g_blockcnt[cIdx * 10 + r] : 0;
        }
#pragma unroll
        for (int o = 16; o; o >>= 1) sum += __shfl_xor_sync(0xFFFFFFFFu, sum, o);
        if (lane == 0) pc[r] = sum;
    }
    __syncthreads();
    if (threadIdx.x == 0) {
        int acc = 0;
        for (int r = 0; r < 10; r++) { ps[r] = acc; acc += ((pc[r] + 127) >> 7) << 7; }
        ps[10] = acc;
    }
    __syncthreads();
    {
        int r = warp;
        int acc = ps[r];
        for (int base = 0; base < NCTA_E; base += 32) {
            int cIdx = base + lane;
            int v = (cIdx < NCTA_E) ? g_blockcnt[cIdx * 10 + r] : 0;
            int x = v;
#pragma unroll
            for (int o = 1; o < 32; o <<= 1) {
                int y = __shfl_up_sync(0xFFFFFFFFu, x, o);
                if (lane >= o) x += y;
            }
            if (cIdx < NCTA_E) g_off[cIdx * 10 + r] = acc + (x - v);
            acc += __shfl_sync(0xFFFFFFFFu, x, 31);
        }
    }
    __syncthreads();
    for (int tIdx = threadIdx.x; tIdx < TILES_CAP; tIdx += blockDim.x) {
        int pos = tIdx * 128;
        int r = 9;
#pragma unroll
        for (int q = 0; q < 10; q++)
            if (pos >= ps[q] && pos < ps[q + 1]) { r = q; break; }
        g_tiler[tIdx] = r;
    }
}

__global__ void edge_reorder(const int* __restrict__ ei, const int* __restrict__ et) {
    __shared__ int cur[10];
    int tid = threadIdx.x;
    if (tid < 10) cur[tid] = g_off[blockIdx.x * 10 + tid];
    __syncthreads();
    int base = blockIdx.x * 1024;
    for (int i = tid; i < 1024; i += 256) {
        int e = base + i;
        if (e < NKG) {
            int slot = atomicAdd(&cur[et[e]], 1);
            g_esorted[slot] = make_int2(ei[e], ei[NKG + e]);
        }
    }
}

// ---------------- gemm_root: Yroot = Xh[M,128] @ Wroot^T -----------------------
__global__ __launch_bounds__(256, 2)
void gemm_root(const __half* __restrict__ A, const __half* __restrict__ Bt, int M) {
    extern __shared__ __half sm[];
    htile_t* As = (htile_t*)sm;
    htile_t* Bs = (htile_t*)(sm + 128 * SPAD);
    const int tid = threadIdx.x, lane = tid & 31, warp = tid >> 5;
    const int g = lane >> 2, t = lane & 3;
    const int wm = (warp >> 1) * 32, wn = (warp & 1) * 64;
    const int m0 = blockIdx.x * 128;

    const uint4 z = make_uint4(0, 0, 0, 0);
#pragma unroll
    for (int l = 0; l < 8; l++) {
        int e = l * 256 + tid;
        int r = e >> 4, c8 = (e & 15) * 8;
        *(uint4*)&As[r][c8] =
            (m0 + r < M) ? *(const uint4*)&A[(size_t)(m0 + r) * 128 + c8] : z;
        *(uint4*)&Bs[r][c8] = *(const uint4*)&Bt[(size_t)(NR * 128 + r) * 128 + c8];
    }
    __syncthreads();

    float c[2][8][4];
    ZERO_C(c);
    compute_k128(As, Bs, c, wm, wn, lane);

#pragma unroll
    for (int mt = 0; mt < 2; mt++) {
#pragma unroll
        for (int h = 0; h < 2; h++) {
            int row = m0 + wm + mt * 16 + g + h * 8;
            if (row >= M) continue;
            float* cp = g_Yroot + (size_t)row * 128;
#pragma unroll
            for (int j = 0; j < 8; j++) {
                int col = wn + j * 8 + 2 * t;
                *(float2*)(cp + col) = make_float2(c[mt][j][h * 2], c[mt][j][h * 2 + 1]);
            }
        }
    }
}

// ---------------- gemm_edge: ECHUNK edge-tiles per CTA, fp16 gather ------------
__global__ __launch_bounds__(256, 2)
void gemm_edge(const __half* __restrict__ Xh, const __half* __restrict__ Bt) {
    extern __shared__ __half sm[];
    htile_t* As = (htile_t*)sm;
    htile_t* Bs = (htile_t*)(sm + 128 * SPAD);
    int* ssrc = (int*)(sm + 2 * 128 * SPAD);      // [ECHUNK][128]
    int* sdst = ssrc + ECHUNK * 128;               // [ECHUNK][128]
    const int tid = threadIdx.x, lane = tid & 31, warp = tid >> 5;
    const int g = lane >> 2, t = lane & 3;
    const int wm = (warp >> 1) * 32, wn = (warp & 1) * 64;
    const int tile0 = blockIdx.x * ECHUNK;

    for (int i = tid; i < ECHUNK * 128; i += 256) {
        int2 rec = g_esorted[(size_t)tile0 * 128 + i];
        ssrc[i] = rec.x;
        sdst[i] = rec.y;
    }
    int rels[ECHUNK];
#pragma unroll
    for (int i = 0; i < ECHUNK; i++) rels[i] = g_tiler[tile0 + i];

    // B = W_{r0}
    {
        const __half* Bp = Bt + (size_t)rels[0] * 128 * 128;
#pragma unroll
        for (int l = 0; l < 8; l++) {
            int e = l * 256 + tid;
            int rr = e >> 4, c8 = (e & 15) * 8;
            *(uint4*)&Bs[rr][c8] = *(const uint4*)&Bp[(size_t)rr * 128 + c8];
        }
    }
    __syncthreads();

    // A0 gather (fp16 rows)
#pragma unroll
    for (int l = 0; l < 8; l++) {
        int e = l * 256 + tid;
        int row = e >> 4, c8 = (e & 15) * 8;
        *(uint4*)&As[row][c8] = *(const uint4*)&Xh[(size_t)ssrc[row] * 128 + c8];
    }
    __syncthreads();

    float c[2][8][4];
#pragma unroll
    for (int i = 0; i < ECHUNK; i++) {
        ZERO_C(c);
        compute_k128(As, Bs, c, wm, wn, lane);
        __syncthreads();  // everyone done reading As/Bs

        if (i + 1 < ECHUNK) {
            // A(i+1) gather (+B reload at relation boundary) — overlaps epilogue i
#pragma unroll
            for (int l = 0; l < 8; l++) {
                int e = l * 256 + tid;
                int row = e >> 4, c8 = (e & 15) * 8;
                *(uint4*)&As[row][c8] =
                    *(const uint4*)&Xh[(size_t)ssrc[(i + 1) * 128 + row] * 128 + c8];
            }
            if (rels[i + 1] != rels[i]) {
                const __half* Bp = Bt + (size_t)rels[i + 1] * 128 * 128;
#pragma unroll
                for (int l = 0; l < 8; l++) {
                    int e = l * 256 + tid;
                    int rr = e >> 4, c8 = (e & 15) * 8;
                    *(uint4*)&Bs[rr][c8] = *(const uint4*)&Bp[(size_t)rr * 128 + c8];
                }
            }
        }
        // epilogue i (atomics; overlaps the loads above)
        const int* dsti = sdst + i * 128;
#pragma unroll
        for (int mt = 0; mt < 2; mt++) {
#pragma unroll
            for (int h = 0; h < 2; h++) {
                int rowi = wm + mt * 16 + g + h * 8;
                float* bp = g_Yroot + (size_t)dsti[rowi] * 128;
#pragma unroll
                for (int nt = 0; nt < 8; nt++) {
                    int col = wn + nt * 8 + 2 * t;
                    red_add_v2(bp + col, c[mt][nt][h * 2], c[mt][nt][h * 2 + 1]);
                }
            }
        }
        if (i + 1 < ECHUNK) __syncthreads();
    }
}

// ---------------- pred: PCHUNK M-tiles per CTA sharing the B (Eh) tile ---------
__global__ __launch_bounds__(256, 2)
void gemm_pred(const __half* __restrict__ A, const __half* __restrict__ Bt,
               float* __restrict__ C, int M, int N, size_t ldc) {
    extern __shared__ __half sm[];
    htile_t* As = (htile_t*)sm;
    htile_t* Bs = (htile_t*)(sm + 128 * SPAD);
    const int tid = threadIdx.x, lane = tid & 31, warp = tid >> 5;
    const int g = lane >> 2, t = lane & 3;
    const int wm = (warp >> 1) * 32, wn = (warp & 1) * 64;
    const int mbase = blockIdx.x * (128 * PCHUNK), n0 = blockIdx.y * 128;

    const uint4 z = make_uint4(0, 0, 0, 0);
#pragma unroll
    for (int l = 0; l < 8; l++) {
        int e = l * 256 + tid;
        int r = e >> 4, c8 = (e & 15) * 8;
        *(uint4*)&Bs[r][c8] = (n0 + r < N) ? *(const uint4*)&Bt[(size_t)(n0 + r) * 128 + c8] : z;
        *(uint4*)&As[r][c8] =
            (mbase + r < M) ? *(const uint4*)&A[(size_t)(mbase + r) * 128 + c8] : z;
    }
    __syncthreads();

    float c[2][8][4];
#pragma unroll
    for (int i = 0; i < PCHUNK; i++) {
        ZERO_C(c);
        compute_k128(As, Bs, c, wm, wn, lane);
        __syncthreads();

        if (i + 1 < PCHUNK) {
            int m1 = mbase + (i + 1) * 128;
#pragma unroll
            for (int l = 0; l < 8; l++) {
                int e = l * 256 + tid;
                int r = e >> 4, c8 = (e & 15) * 8;
                *(uint4*)&As[r][c8] =
                    (m1 + r < M) ? *(const uint4*)&A[(size_t)(m1 + r) * 128 + c8] : z;
            }
        }
        int mi = mbase + i * 128;
#pragma unroll
        for (int mt = 0; mt < 2; mt++) {
#pragma unroll
            for (int h = 0; h < 2; h++) {
                int row = mi + wm + mt * 16 + g + h * 8;
                if (row >= M) continue;
#pragma unroll
                for (int nt = 0; nt < 8; nt++) {
                    int col = n0 + wn + nt * 8 + 2 * t;
                    if (col >= N) continue;
                    *(float2*)&C[(size_t)row * ldc + col] =
                        make_float2(c[mt][nt][h * 2 + 0], c[mt][nt][h * 2 + 1]);
                }
            }
        }
        if (i + 1 < PCHUNK) __syncthreads();
    }
}

// ---------------- tf32 mma GEMM (metapath GEMMs, K=768) ----------------------
__global__ __launch_bounds__(256)
void gemm_tf32(const float* __restrict__ A, int lda, const float* __restrict__ B, int ldb,
               const float* __restrict__ bias, float* __restrict__ C, int ldc,
               int M, int N, int K, int act) {
    __shared__ float As[2][128][20];
    __shared__ float Bs[2][16][136];
    const int bm = blockIdx.x * 128;
    const int bn = blockIdx.y * 128;
    const int tid = threadIdx.x;
    const int lane = tid & 31;
    const int warp = tid >> 5;
    const int g = lane >> 2, t = lane & 3;
    const int wm = (warp >> 1) * 32;
    const int wn = (warp & 1) * 64;

    float c[2][8][4];
    ZERO_C(c);

    float4 ar[2], br[2];
    const float4 z4 = make_float4(0.f, 0.f, 0.f, 0.f);

    auto ldg = [&](int k0) {
#pragma unroll
        for (int l = 0; l < 2; l++) {
            int e = tid + l * 256;
            int m = e >> 2, k4 = (e & 3) * 4;
            int gm = bm + m;
            ar[l] = (gm < M) ? *(const float4*)&A[(size_t)gm * lda + k0 + k4] : z4;
            int kr = e >> 5, nc = (e & 31) * 4;
            int gc = bn + nc;
            br[l] = (gc < N) ? *(const float4*)&B[(size_t)(k0 + kr) * ldb + gc] : z4;
        }
    };
    auto sts = [&](int buf) {
#pragma unroll
        for (int l = 0; l < 2; l++) {
            int e = tid + l * 256;
            int m = e >> 2, k4 = (e & 3) * 4;
            float4 a4 = cvt_tf32_4(ar[l]);
            As[buf][m][k4 + 0] = a4.x;
            As[buf][m][k4 + 1] = a4.y;
            As[buf][m][k4 + 2] = a4.z;
            As[buf][m][k4 + 3] = a4.w;
            int kr = e >> 5, nc = (e & 31) * 4;
            *(float4*)&Bs[buf][kr][nc] = cvt_tf32_4(br[l]);
        }
    };
    auto compute = [&](int buf) {
#pragma unroll
        for (int kk = 0; kk < 2; kk++) {
            const int kb = kk * 8;
            unsigned a[2][4], b[8][2];
#pragma unroll
            for (int mt = 0; mt < 2; mt++) {
                int row = wm + mt * 16 + g;
                a[mt][0] = __float_as_uint(As[buf][row][kb + t]);
                a[mt][1] = __float_as_uint(As[buf][row + 8][kb + t]);
                a[mt][2] = __float_as_uint(As[buf][row][kb + t + 4]);
                a[mt][3] = __float_as_uint(As[buf][row + 8][kb + t + 4]);
            }
#pragma unroll
            for (int nt = 0; nt < 8; nt++) {
                int col = wn + nt * 8 + g;
                b[nt][0] = __float_as_uint(Bs[buf][kb + t][col]);
                b[nt][1] = __float_as_uint(Bs[buf][kb + t + 4][col]);
            }
#pragma unroll
            for (int mt = 0; mt < 2; mt++)
#pragma unroll
                for (int nt = 0; nt < 8; nt++) mma8(c[mt][nt], a[mt], b[nt]);
        }
    };

    const int iters = K >> 4;
    ldg(0);
    sts(0);
    __syncthreads();
    for (int it = 0; it < iters; it++) {
        int buf = it & 1;
        if (it + 1 < iters) ldg((it + 1) << 4);
        compute(buf);
        if (it + 1 < iters) sts(buf ^ 1);
        __syncthreads();
    }

#pragma unroll
    for (int mt = 0; mt < 2; mt++) {
#pragma unroll
        for (int h = 0; h < 2; h++) {
            int row = bm + wm + mt * 16 + g + h * 8;
            if (row >= M) continue;
#pragma unroll
            for (int nt = 0; nt < 8; nt++) {
                int col = bn + wn + nt * 8 + 2 * t;
                if (col >= N) continue;
                float v0 = c[mt][nt][h * 2 + 0];
                float v1 = c[mt][nt][h * 2 + 1];
                if (bias) { v0 += bias[col]; v1 += bias[col + 1]; }
                if (act == 2) { v0 = fmaxf(v0, 0.f); v1 = fmaxf(v1, 0.f); }
                *(float2*)&C[(size_t)row * ldc + col] = make_float2(v0, v1);
            }
        }
    }
}

// ---------------- stage 1 aux -------------------------------------------------
__global__ void build_BmainTh(const float* __restrict__ W, const float* __restrict__ Wroot) {
    int i = blockIdx.x * blockDim.x + threadIdx.x;
    if (i >= (NR + 1) * EDIM * EDIM) return;
    int n = i >> 7, k = i & 127;
    int r = n >> 7, o = n & 127;
    float v = (r < NR) ? W[((size_t)r * EDIM + k) * EDIM + o] : Wroot[(size_t)k * EDIM + o];
    g_BmainTh[i] = __float2half_rn(v);
}

__global__ void tanh_root(const float* __restrict__ b) {
    int i = blockIdx.x * blockDim.x + threadIdx.x;
    if (i >= NE * (EDIM / 4)) return;
    int n = i >> 5, j = (i & 31) * 4;
    float4 v = *(const float4*)&g_Yroot[(size_t)n * EDIM + j];
    float4 bb = *(const float4*)&b[j];
    v.x = tanhf(v.x + bb.x);
    v.y = tanhf(v.y + bb.y);
    v.z = tanhf(v.z + bb.z);
    v.w = tanhf(v.w + bb.w);
    *(float4*)&g_E[(size_t)n * EDIM + j] = v;
    __half2* eh = (__half2*)&g_Eh[(size_t)n * EDIM + j];
    eh[0] = __floats2half2_rn(v.x, v.y);
    eh[1] = __floats2half2_rn(v.z, v.w);
}

// ---------------- stage 2 aux ---------------------------------------------------
__global__ void build_x(const int* __restrict__ h_idx, const int* __restrict__ r_idx,
                        const float* __restrict__ R) {
    int b = blockIdx.x, i = threadIdx.x;
    float v = g_E[(size_t)h_idx[b] * EDIM + i] * R[(size_t)r_idx[b] * EDIM + i];
    g_xh[b * EDIM + i] = __float2half_rn(v);
}

// ---------------- stage 3: metapath RGCNs --------------------------------------
__global__ void init_mp(int m, const int* __restrict__ eids) {
    int n = blockIdx.x;
    float* row = g_mp[m] + (size_t)n * KMP;
    const float4* er = (const float4*)(g_E + (size_t)eids[n] * EDIM);
    const float4 z = make_float4(0.f, 0.f, 0.f, 0.f);
    for (int j = threadIdx.x; j < KMP / 4; j += blockDim.x)
        ((float4*)row)[j] = (j < (KMP - EDIM) / 4) ? z : er[j - (KMP - EDIM) / 4];
    if (blockIdx.x == 0 && threadIdx.x < 2) g_w[threadIdx.x] = 0.f;
}

__global__ void scatter_mp(int m, const int* __restrict__ ei, const int* __restrict__ et,
                           const int* __restrict__ eids) {
    int w = (blockIdx.x * blockDim.x + threadIdx.x) >> 5;
    int lane = threadIdx.x & 31;
    if (w >= NMP_E) return;
    int dst = ei[NMP_E + w];
    if (dst >= NREG) return;  // output sliced [:NREG]
    int src = ei[w];
    int r = et[w];
    float4 v = *(const float4*)(g_E + (size_t)eids[src] * EDIM + lane * 4);
    red_add_v4(g_mp[m] + (size_t)dst * KMP + r * EDIM + lane * 4, v);
}

// ---------------- stage 4: semantic attention + head ---------------------------
__global__ void attn(const float* __restrict__ w1, const float* __restrict__ b1,
                     const float* __restrict__ w2) {
    int n = blockIdx.x, m = blockIdx.y, tid = threadIdx.x;
    __shared__ float z[HID];
    __shared__ float red[ATT];
    const float* zp = &g_sem[m][(size_t)n * HID];
    z[tid] = zp[tid];
    z[tid + 128] = zp[tid + 128];
    __syncthreads();
    float acc = b1[tid];
#pragma unroll 8
    for (int k = 0; k < HID; k++) acc = fmaf(z[k], w1[k * ATT + tid], acc);
    red[tid] = tanhf(acc) * w2[tid];
    __syncthreads();
    for (int s = 64; s > 0; s >>= 1) {
        if (tid < s) red[tid] += red[tid + s];
        __syncthreads();
    }
    if (tid == 0) atomicAdd(&g_w[m], red[0] * (1.0f / NREG));
}

__global__ void finalk(const float* __restrict__ predW, const float* __restrict__ predb,
                       float* __restrict__ out) {
    int n = blockIdx.x, tid = threadIdx.x;
    __shared__ float h[HID];
    float w0 = g_w[0], w1v = g_w[1];
    float mx = fmaxf(w0, w1v);
    float e0 = expf(w0 - mx), e1 = expf(w1v - mx);
    float inv = 1.f / (e0 + e1);
    float b0 = e0 * inv, b1 = e1 * inv;
    h[tid] = b0 * g_sem[0][(size_t)n * HID + tid] + b1 * g_sem[1][(size_t)n * HID + tid];
    h[tid + 128] =
        b0 * g_sem[0][(size_t)n * HID + tid + 128] + b1 * g_sem[1][(size_t)n * HID + tid + 128];
    __syncthreads();
    float acc = predb[tid] + g_E[(size_t)n * EDIM + tid];
#pragma unroll 8
    for (int k = 0; k < HID; k++) acc = fmaf(h[k], predW[k * EDIM + tid], acc);
    out[(size_t)n * EDIM + tid] = acc;
}

// ---------------- launch ------------------------------------------------------
extern "C" void kernel_launch(void* const* d_in, const int* in_sizes, int n_in,
                              void* d_out, int out_size) {
    const float* E_weight = (const float*)d_in[0];
    const float* R_weight = (const float*)d_in[1];
    const float* rgcn_W = (const float*)d_in[2];
    const float* rgcn_Wroot = (const float*)d_in[3];
    const float* rgcn_b = (const float*)d_in[4];
    const float* mp0_W = (const float*)d_in[5];
    const float* mp0_Wroot = (const float*)d_in[6];
    const float* mp0_b = (const float*)d_in[7];
    const float* mp1_W = (const float*)d_in[8];
    const float* mp1_Wroot = (const float*)d_in[9];
    const float* mp1_b = (const float*)d_in[10];
    const float* sa_w1 = (const float*)d_in[11];
    const float* sa_b1 = (const float*)d_in[12];
    const float* sa_w2 = (const float*)d_in[13];
    const float* pred_W = (const float*)d_in[14];
    const float* pred_b = (const float*)d_in[15];
    const int* h_idx = (const int*)d_in[16];
    const int* r_idx = (const int*)d_in[17];
    const int* edge_index = (const int*)d_in[18];
    const int* edge_type = (const int*)d_in[19];
    const int* mp0_ei = (const int*)d_in[20];
    const int* mp0_et = (const int*)d_in[21];
    const int* mp0_eids = (const int*)d_in[22];
    const int* mp1_ei = (const int*)d_in[23];
    const int* mp1_et = (const int*)d_in[24];
    const int* mp1_eids = (const int*)d_in[25];
    float* out = (float*)d_out;  // [E_reg 2000*128 | pred 1024*100000]

    float *pBmp, *psem, *pmp;
    __half *pEh, *pXh, *pBmTh, *pxh;
    cudaGetSymbolAddress((void**)&pBmp, g_Bmp);
    cudaGetSymbolAddress((void**)&psem, g_sem);
    cudaGetSymbolAddress((void**)&pmp, g_mp);
    cudaGetSymbolAddress((void**)&pEh, g_Eh);
    cudaGetSymbolAddress((void**)&pXh, g_Xh);
    cudaGetSymbolAddress((void**)&pBmTh, g_BmainTh);
    cudaGetSymbolAddress((void**)&pxh, g_xh);

    const int SMEM_F16 = 2 * 128 * SPAD * (int)sizeof(__half);              // 69,632 B
    const int SMEM_EDGE = SMEM_F16 + 2 * ECHUNK * 128 * (int)sizeof(int);   // + idx
    cudaFuncSetAttribute(gemm_root, cudaFuncAttributeMaxDynamicSharedMemorySize, SMEM_F16);
    cudaFuncSetAttribute(gemm_edge, cudaFuncAttributeMaxDynamicSharedMemorySize, SMEM_EDGE);
    cudaFuncSetAttribute(gemm_pred, cudaFuncAttributeMaxDynamicSharedMemorySize, SMEM_F16);

    cudaStream_t s1 = g_res.s1;

    // ===== fork 1: edge bucketing on s1, f2h + weight prep + root GEMM on main =====
    cudaEventRecord(g_res.evF1, 0);
    cudaStreamWaitEvent(s1, g_res.evF1, 0);

    edge_prefill<<<(TILES_CAP * 128 + 255) / 256, 256, 0, s1>>>();
    edge_hist<<<NCTA_E, 256, 0, s1>>>(edge_type);
    edge_prefix<<<1, 320, 0, s1>>>();
    edge_reorder<<<NCTA_E, 256, 0, s1>>>(edge_index, edge_type);

    f2h<<<(NE * EDIM / 4 + 255) / 256, 256>>>(E_weight, pXh, NE * EDIM / 4);
    build_BmainTh<<<((NR + 1) * EDIM * EDIM + 255) / 256, 256>>>(rgcn_W, rgcn_Wroot);
    gemm_root<<<(NE + 127) / 128, 256, SMEM_F16>>>(pXh, pBmTh, NE);

    cudaEventRecord(g_res.evJ1, s1);
    cudaStreamWaitEvent(0, g_res.evJ1, 0);

    // ===== main: fused edge GEMM (ECHUNK tiles/CTA, fp16 gather) + activation =====
    gemm_edge<<<TILES_CAP / ECHUNK, 256, SMEM_EDGE>>>(pXh, pBmTh);
    tanh_root<<<(NE * (EDIM / 4) + 255) / 256, 256>>>(rgcn_b);

    // ===== fork 2: metapath/attention tail on s1, pred GEMM on main =====
    cudaEventRecord(g_res.evF2, 0);
    cudaStreamWaitEvent(s1, g_res.evF2, 0);

    init_mp<<<NREG, 128, 0, s1>>>(0, mp0_eids);
    init_mp<<<NREG, 128, 0, s1>>>(1, mp1_eids);
    cudaMemcpyAsync(pBmp, mp0_W, (size_t)NMP_REL * EDIM * HID * 4,
                    cudaMemcpyDeviceToDevice, s1);
    cudaMemcpyAsync(pBmp + NMP_REL * EDIM * HID, mp0_Wroot, (size_t)EDIM * HID * 4,
                    cudaMemcpyDeviceToDevice, s1);
    cudaMemcpyAsync(pBmp + KMP * HID, mp1_W, (size_t)NMP_REL * EDIM * HID * 4,
                    cudaMemcpyDeviceToDevice, s1);
    cudaMemcpyAsync(pBmp + KMP * HID + NMP_REL * EDIM * HID, mp1_Wroot,
                    (size_t)EDIM * HID * 4, cudaMemcpyDeviceToDevice, s1);
    scatter_mp<<<NMP_E / 8, 256, 0, s1>>>(0, mp0_ei, mp0_et, mp0_eids);
    scatter_mp<<<NMP_E / 8, 256, 0, s1>>>(1, mp1_ei, mp1_et, mp1_eids);
    gemm_tf32<<<dim3((NREG + 127) / 128, HID / 128), 256, 0, s1>>>(
        pmp, KMP, pBmp, HID, mp0_b, psem, HID, NREG, HID, KMP, 2);
    gemm_tf32<<<dim3((NREG + 127) / 128, HID / 128), 256, 0, s1>>>(
        pmp + (size_t)NREG * KMP, KMP, pBmp + (size_t)KMP * HID, HID, mp1_b,
        psem + (size_t)NREG * HID, HID, NREG, HID, KMP, 2);
    attn<<<dim3(NREG, 2), ATT, 0, s1>>>(sa_w1, sa_b1, sa_w2);
    finalk<<<NREG, EDIM, 0, s1>>>(pred_W, pred_b, out);

    // main: KGE pred = (E[h]*R[r]) @ E^T (PCHUNK M-tiles per CTA)
    build_x<<<NB, EDIM>>>(h_idx, r_idx, R_weight);
    gemm_pred<<<dim3(NB / (128 * PCHUNK), (NE + 127) / 128), 256, SMEM_F16>>>(
        pxh, pEh, out + NREG * EDIM, NB, NE, NE);

    cudaEventRecord(g_res.evJ2, s1);
    cudaStreamWaitEvent(0, g_res.evJ2, 0);
}

// round 14
// speedup vs baseline: 1.3280x; 1.0292x over previous
#include <cuda_runtime.h>
#include <cuda_fp16.h>
#include <math.h>
#include <stdint.h>

#define NE 100000
#define NR 10
#define EDIM 128
#define HID 256
#define NREG 2000
#define NKG 600000
#define NMP_REL 5
#define NMP_E 300000
#define NB 1024
#define ATT 128

#define KMP (NMP_REL * EDIM + EDIM) /* 768 */
#define NCTA_E ((NKG + 1023) / 1024) /* 586 histogram CTAs */
#define TILES_CAP 4704               /* multiple of 8 */
#define ECHUNK 8
#define PCHUNK 8

// ---------------- scratch ----------------------------------------------------
__device__ float g_Yroot[(size_t)(NE + 1) * EDIM];
__device__ float g_E[(size_t)NE * EDIM];
__device__ __half g_Eh[(size_t)NE * EDIM];
__device__ __half g_Xh[(size_t)NE * EDIM];
__device__ __half g_BmainTh[(NR + 1) * EDIM * EDIM];
__device__ float g_Bmp[2][KMP * HID];
__device__ __half g_xh[NB * EDIM];
__device__ float g_mp[2][(size_t)NREG * KMP];
__device__ float g_sem[2][NREG * HID];
__device__ float g_w[2];
__device__ int2 g_esorted[TILES_CAP * 128];
__device__ int g_blockcnt[NCTA_E * 10];
__device__ int g_off[NCTA_E * 10];
__device__ int g_tiler[TILES_CAP];

// ---------------- side stream + events -----------------------------------------
namespace {
struct GraphResources {
    cudaStream_t s1;
    cudaEvent_t evF1, evJ1, evF2, evJ2;
    GraphResources() {
        cudaStreamCreateWithFlags(&s1, cudaStreamNonBlocking);
        cudaEventCreateWithFlags(&evF1, cudaEventDisableTiming);
        cudaEventCreateWithFlags(&evJ1, cudaEventDisableTiming);
        cudaEventCreateWithFlags(&evF2, cudaEventDisableTiming);
        cudaEventCreateWithFlags(&evJ2, cudaEventDisableTiming);
    }
};
GraphResources g_res;
}

// ---------------- primitives -------------------------------------------------
__device__ __forceinline__ void red_add_v4(float* addr, float4 v) {
    asm volatile("red.global.add.v4.f32 [%0], {%1, %2, %3, %4};"
                 :: "l"(addr), "f"(v.x), "f"(v.y), "f"(v.z), "f"(v.w) : "memory");
}
__device__ __forceinline__ void red_add_v2(float* addr, float x, float y) {
    asm volatile("red.global.add.v2.f32 [%0], {%1, %2};"
                 :: "l"(addr), "f"(x), "f"(y) : "memory");
}
__device__ __forceinline__ void mma16816(float* c, const uint32_t* a, const uint32_t* b) {
    asm volatile(
        "mma.sync.aligned.m16n8k16.row.col.f32.f16.f16.f32 "
        "{%0,%1,%2,%3}, {%4,%5,%6,%7}, {%8,%9}, {%0,%1,%2,%3};"
        : "+f"(c[0]), "+f"(c[1]), "+f"(c[2]), "+f"(c[3])
        : "r"(a[0]), "r"(a[1]), "r"(a[2]), "r"(a[3]), "r"(b[0]), "r"(b[1]));
}
__device__ __forceinline__ void ldsm_x4(uint32_t& r0, uint32_t& r1, uint32_t& r2, uint32_t& r3,
                                        uint32_t addr) {
    asm volatile("ldmatrix.sync.aligned.m8n8.x4.shared.b16 {%0,%1,%2,%3}, [%4];"
                 : "=r"(r0), "=r"(r1), "=r"(r2), "=r"(r3) : "r"(addr));
}
__device__ __forceinline__ void cp_async16(uint32_t saddr, const void* gptr) {
    asm volatile("cp.async.ca.shared.global [%0], [%1], 16;"
                 :: "r"(saddr), "l"(gptr) : "memory");
}
#define CP_COMMIT() asm volatile("cp.async.commit_group;" ::: "memory")
#define CP_WAIT0() asm volatile("cp.async.wait_group 0;" ::: "memory")
__device__ __forceinline__ float cvt_tf32(float x) {
    unsigned u;
    asm("cvt.rna.tf32.f32 %0, %1;" : "=r"(u) : "f"(x));
    return __uint_as_float(u);
}
__device__ __forceinline__ float4 cvt_tf32_4(float4 v) {
    return make_float4(cvt_tf32(v.x), cvt_tf32(v.y), cvt_tf32(v.z), cvt_tf32(v.w));
}
__device__ __forceinline__ void mma8(float* c, const unsigned* a, const unsigned* b) {
    asm volatile(
        "mma.sync.aligned.m16n8k8.row.col.f32.tf32.tf32.f32 "
        "{%0,%1,%2,%3}, {%4,%5,%6,%7}, {%8,%9}, {%0,%1,%2,%3};"
        : "+f"(c[0]), "+f"(c[1]), "+f"(c[2]), "+f"(c[3])
        : "r"(a[0]), "r"(a[1]), "r"(a[2]), "r"(a[3]), "r"(b[0]), "r"(b[1]));
}

// ---------------- fp16 K=128 MMA core (ldmatrix-fed) ---------------------------
#define SPAD 136
typedef __half htile_t[SPAD];

__device__ __forceinline__ void compute_k128(const htile_t* As, const htile_t* Bs,
                                             float c[2][8][4], int wm, int wn, int lane) {
    const int quad = lane >> 3, r = lane & 7;
    uint32_t aAddr[2], bAddr[4];
#pragma unroll
    for (int mt = 0; mt < 2; mt++)
        aAddr[mt] =
            (uint32_t)__cvta_generic_to_shared(&As[wm + mt * 16 + r + (quad & 1) * 8][(quad >> 1) * 8]);
#pragma unroll
    for (int p = 0; p < 4; p++)
        bAddr[p] =
            (uint32_t)__cvta_generic_to_shared(&Bs[wn + p * 16 + (quad >> 1) * 8 + r][(quad & 1) * 8]);

#pragma unroll
    for (int kb = 0; kb < 128; kb += 16) {
        uint32_t a[2][4], b[8][2];
#pragma unroll
        for (int mt = 0; mt < 2; mt++)
            ldsm_x4(a[mt][0], a[mt][1], a[mt][2], a[mt][3], aAddr[mt] + kb * 2);
#pragma unroll
        for (int p = 0; p < 4; p++)
            ldsm_x4(b[2 * p][0], b[2 * p][1], b[2 * p + 1][0], b[2 * p + 1][1], bAddr[p] + kb * 2);
#pragma unroll
        for (int mt = 0; mt < 2; mt++)
#pragma unroll
            for (int nt = 0; nt < 8; nt++) mma16816(c[mt][nt], a[mt], b[nt]);
    }
}
#define ZERO_C(c)                                  \
    _Pragma("unroll") for (int _i = 0; _i < 2; _i++) \
    _Pragma("unroll") for (int _j = 0; _j < 8; _j++) \
    _Pragma("unroll") for (int _l = 0; _l < 4; _l++) (c)[_i][_j][_l] = 0.f

// ---------------- conversions ---------------------------------------------------
__global__ void f2h(const float* __restrict__ src, __half* __restrict__ dst, int n4) {
    int i = blockIdx.x * blockDim.x + threadIdx.x;
    if (i >= n4) return;
    float4 v = ((const float4*)src)[i];
    __half2 h0 = __floats2half2_rn(v.x, v.y);
    __half2 h1 = __floats2half2_rn(v.z, v.w);
    ((uint2*)dst)[i] = make_uint2(*(uint32_t*)&h0, *(uint32_t*)&h1);
}

// ---------------- edge bucketing ----------------------------------------------
__global__ void edge_prefill() {
    int i = blockIdx.x * blockDim.x + threadIdx.x;
    if (i < TILES_CAP * 128) g_esorted[i] = make_int2(0, NE);
}

__global__ void edge_hist(const int* __restrict__ et) {
    __shared__ int cnt[10];
    int tid = threadIdx.x;
    if (tid < 10) cnt[tid] = 0;
    __syncthreads();
    int base = blockIdx.x * 1024;
    for (int i = tid; i < 1024; i += 256) {
        int e = base + i;
        if (e < NKG) atomicAdd(&cnt[et[e]], 1);
    }
    __syncthreads();
    if (tid < 10) g_blockcnt[blockIdx.x * 10 + tid] = cnt[tid];
}

__global__ void edge_prefix() {
    __shared__ int pc[10], ps[11];
    const int warp = threadIdx.x >> 5, lane = threadIdx.x & 31;
    {
        int r = warp;
        int sum = 0;
        for (int base = 0; base < NCTA_E; base += 32) {
            int cIdx = base + lane;
            sum += (cIdx < NCTA_E) ? g_blockcnt[cIdx * 10 + r] : 0;
        }
#pragma unroll
        for (int o = 16; o; o >>= 1) sum += __shfl_xor_sync(0xFFFFFFFFu, sum, o);
        if (lane == 0) pc[r] = sum;
    }
    __syncthreads();
    if (threadIdx.x == 0) {
        int acc = 0;
        for (int r = 0; r < 10; r++) { ps[r] = acc; acc += ((pc[r] + 127) >> 7) << 7; }
        ps[10] = acc;
    }
    __syncthreads();
    {
        int r = warp;
        int acc = ps[r];
        for (int base = 0; base < NCTA_E; base += 32) {
            int cIdx = base + lane;
            int v = (cIdx < NCTA_E) ? g_blockcnt[cIdx * 10 + r] : 0;
            int x = v;
#pragma unroll
            for (int o = 1; o < 32; o <<= 1) {
                int y = __shfl_up_sync(0xFFFFFFFFu, x, o);
                if (lane >= o) x += y;
            }
            if (cIdx < NCTA_E) g_off[cIdx * 10 + r] = acc + (x - v);
            acc += __shfl_sync(0xFFFFFFFFu, x, 31);
        }
    }
    __syncthreads();
    for (int tIdx = threadIdx.x; tIdx < TILES_CAP; tIdx += blockDim.x) {
        int pos = tIdx * 128;
        int r = 9;
#pragma unroll
        for (int q = 0; q < 10; q++)
            if (pos >= ps[q] && pos < ps[q + 1]) { r = q; break; }
        g_tiler[tIdx] = r;
    }
}

__global__ void edge_reorder(const int* __restrict__ ei, const int* __restrict__ et) {
    __shared__ int cur[10];
    int tid = threadIdx.x;
    if (tid < 10) cur[tid] = g_off[blockIdx.x * 10 + tid];
    __syncthreads();
    int base = blockIdx.x * 1024;
    for (int i = tid; i < 1024; i += 256) {
        int e = base + i;
        if (e < NKG) {
            int slot = atomicAdd(&cur[et[e]], 1);
            g_esorted[slot] = make_int2(ei[e], ei[NKG + e]);
        }
    }
}

// ---------------- gemm_root: Yroot = Xh[M,128] @ Wroot^T -----------------------
__global__ __launch_bounds__(256, 2)
void gemm_root(const __half* __restrict__ A, const __half* __restrict__ Bt, int M) {
    extern __shared__ __half sm[];
    htile_t* As = (htile_t*)sm;
    htile_t* Bs = (htile_t*)(sm + 128 * SPAD);
    const int tid = threadIdx.x, lane = tid & 31, warp = tid >> 5;
    const int g = lane >> 2, t = lane & 3;
    const int wm = (warp >> 1) * 32, wn = (warp & 1) * 64;
    const int m0 = blockIdx.x * 128;

    const uint4 z = make_uint4(0, 0, 0, 0);
#pragma unroll
    for (int l = 0; l < 8; l++) {
        int e = l * 256 + tid;
        int r = e >> 4, c8 = (e & 15) * 8;
        *(uint4*)&As[r][c8] =
            (m0 + r < M) ? *(const uint4*)&A[(size_t)(m0 + r) * 128 + c8] : z;
        *(uint4*)&Bs[r][c8] = *(const uint4*)&Bt[(size_t)(NR * 128 + r) * 128 + c8];
    }
    __syncthreads();

    float c[2][8][4];
    ZERO_C(c);
    compute_k128(As, Bs, c, wm, wn, lane);

#pragma unroll
    for (int mt = 0; mt < 2; mt++) {
#pragma unroll
        for (int h = 0; h < 2; h++) {
            int row = m0 + wm + mt * 16 + g + h * 8;
            if (row >= M) continue;
            float* cp = g_Yroot + (size_t)row * 128;
#pragma unroll
            for (int j = 0; j < 8; j++) {
                int col = wn + j * 8 + 2 * t;
                *(float2*)(cp + col) = make_float2(c[mt][j][h * 2], c[mt][j][h * 2 + 1]);
            }
        }
    }
}

// ---------------- gemm_edge: ECHUNK tiles/CTA, cp.async double-buffered A ------
__global__ __launch_bounds__(256, 2)
void gemm_edge(const __half* __restrict__ Xh, const __half* __restrict__ Bt) {
    extern __shared__ __half sm[];
    htile_t* Abuf[2] = {(htile_t*)sm, (htile_t*)(sm + 128 * SPAD)};
    htile_t* Bs = (htile_t*)(sm + 2 * 128 * SPAD);
    int* ssrc = (int*)(sm + 3 * 128 * SPAD);      // [ECHUNK][128]
    int* sdst = ssrc + ECHUNK * 128;               // [ECHUNK][128]
    const int tid = threadIdx.x, lane = tid & 31, warp = tid >> 5;
    const int g = lane >> 2, t = lane & 3;
    const int wm = (warp >> 1) * 32, wn = (warp & 1) * 64;
    const int tile0 = blockIdx.x * ECHUNK;

    for (int i = tid; i < ECHUNK * 128; i += 256) {
        int2 rec = g_esorted[(size_t)tile0 * 128 + i];
        ssrc[i] = rec.x;
        sdst[i] = rec.y;
    }
    int rels[ECHUNK];
#pragma unroll
    for (int i = 0; i < ECHUNK; i++) rels[i] = g_tiler[tile0 + i];

    // B = W_{r0}
    {
        const __half* Bp = Bt + (size_t)rels[0] * 128 * 128;
#pragma unroll
        for (int l = 0; l < 8; l++) {
            int e = l * 256 + tid;
            int rr = e >> 4, c8 = (e & 15) * 8;
            *(uint4*)&Bs[rr][c8] = *(const uint4*)&Bp[(size_t)rr * 128 + c8];
        }
    }
    __syncthreads();  // ssrc visible to all threads

    auto prefetchA = [&](htile_t* dst, const int* srcIdx) {
#pragma unroll
        for (int l = 0; l < 8; l++) {
            int e = l * 256 + tid;
            int row = e >> 4, c8 = (e & 15) * 8;
            cp_async16((uint32_t)__cvta_generic_to_shared(&dst[row][c8]),
                       &Xh[(size_t)srcIdx[row] * 128 + c8]);
        }
        CP_COMMIT();
    };

    prefetchA(Abuf[0], ssrc);
    CP_WAIT0();
    __syncthreads();

    int cur = 0;
    float c[2][8][4];
#pragma unroll
    for (int i = 0; i < ECHUNK; i++) {
        if (i + 1 < ECHUNK) prefetchA(Abuf[cur ^ 1], ssrc + (i + 1) * 128);

        ZERO_C(c);
        compute_k128(Abuf[cur], Bs, c, wm, wn, lane);

        if (i + 1 < ECHUNK && rels[i + 1] != rels[i]) {
            __syncthreads();  // everyone done reading Bs
            const __half* Bp = Bt + (size_t)rels[i + 1] * 128 * 128;
#pragma unroll
            for (int l = 0; l < 8; l++) {
                int e = l * 256 + tid;
                int rr = e >> 4, c8 = (e & 15) * 8;
                *(uint4*)&Bs[rr][c8] = *(const uint4*)&Bp[(size_t)rr * 128 + c8];
            }
        }
        // epilogue i (atomics, overlaps in-flight cp.async)
        const int* dsti = sdst + i * 128;
#pragma unroll
        for (int mt = 0; mt < 2; mt++) {
#pragma unroll
            for (int h = 0; h < 2; h++) {
                int rowi = wm + mt * 16 + g + h * 8;
                float* bp = g_Yroot + (size_t)dsti[rowi] * 128;
#pragma unroll
                for (int nt = 0; nt < 8; nt++) {
                    int col = wn + nt * 8 + 2 * t;
                    red_add_v2(bp + col, c[mt][nt][h * 2], c[mt][nt][h * 2 + 1]);
                }
            }
        }
        if (i + 1 < ECHUNK) {
            CP_WAIT0();
            __syncthreads();
            cur ^= 1;
        }
    }
}

// ---------------- pred: PCHUNK M-tiles/CTA, cp.async double-buffered A ---------
// NB == PCHUNK*128, so A loads are always in-bounds.
__global__ __launch_bounds__(256, 2)
void gemm_pred(const __half* __restrict__ A, const __half* __restrict__ Bt,
               float* __restrict__ C, int M, int N, size_t ldc) {
    extern __shared__ __half sm[];
    htile_t* Abuf[2] = {(htile_t*)sm, (htile_t*)(sm + 128 * SPAD)};
    htile_t* Bs = (htile_t*)(sm + 2 * 128 * SPAD);
    const int tid = threadIdx.x, lane = tid & 31, warp = tid >> 5;
    const int g = lane >> 2, t = lane & 3;
    const int wm = (warp >> 1) * 32, wn = (warp & 1) * 64;
    const int mbase = blockIdx.x * (128 * PCHUNK), n0 = blockIdx.y * 128;

    const uint4 z = make_uint4(0, 0, 0, 0);
#pragma unroll
    for (int l = 0; l < 8; l++) {
        int e = l * 256 + tid;
        int r = e >> 4, c8 = (e & 15) * 8;
        *(uint4*)&Bs[r][c8] = (n0 + r < N) ? *(const uint4*)&Bt[(size_t)(n0 + r) * 128 + c8] : z;
    }

    auto prefetchA = [&](htile_t* dst, int mrow) {
#pragma unroll
        for (int l = 0; l < 8; l++) {
            int e = l * 256 + tid;
            int row = e >> 4, c8 = (e & 15) * 8;
            cp_async16((uint32_t)__cvta_generic_to_shared(&dst[row][c8]),
                       &A[(size_t)(mrow + row) * 128 + c8]);
        }
        CP_COMMIT();
    };

    prefetchA(Abuf[0], mbase);
    CP_WAIT0();
    __syncthreads();

    int cur = 0;
    float c[2][8][4];
#pragma unroll
    for (int i = 0; i < PCHUNK; i++) {
        if (i + 1 < PCHUNK) prefetchA(Abuf[cur ^ 1], mbase + (i + 1) * 128);

        ZERO_C(c);
        compute_k128(Abuf[cur], Bs, c, wm, wn, lane);

        int mi = mbase + i * 128;
#pragma unroll
        for (int mt = 0; mt < 2; mt++) {
#pragma unroll
            for (int h = 0; h < 2; h++) {
                int row = mi + wm + mt * 16 + g + h * 8;
#pragma unroll
                for (int nt = 0; nt < 8; nt++) {
                    int col = n0 + wn + nt * 8 + 2 * t;
                    if (col >= N) continue;
                    *(float2*)&C[(size_t)row * ldc + col] =
                        make_float2(c[mt][nt][h * 2 + 0], c[mt][nt][h * 2 + 1]);
                }
            }
        }
        if (i + 1 < PCHUNK) {
            CP_WAIT0();
            __syncthreads();
            cur ^= 1;
        }
    }
}

// ---------------- tf32 mma GEMM (metapath GEMMs, K=768) ----------------------
__global__ __launch_bounds__(256)
void gemm_tf32(const float* __restrict__ A, int lda, const float* __restrict__ B, int ldb,
               const float* __restrict__ bias, float* __restrict__ C, int ldc,
               int M, int N, int K, int act) {
    __shared__ float As[2][128][20];
    __shared__ float Bs[2][16][136];
    const int bm = blockIdx.x * 128;
    const int bn = blockIdx.y * 128;
    const int tid = threadIdx.x;
    const int lane = tid & 31;
    const int warp = tid >> 5;
    const int g = lane >> 2, t = lane & 3;
    const int wm = (warp >> 1) * 32;
    const int wn = (warp & 1) * 64;

    float c[2][8][4];
    ZERO_C(c);

    float4 ar[2], br[2];
    const float4 z4 = make_float4(0.f, 0.f, 0.f, 0.f);

    auto ldg = [&](int k0) {
#pragma unroll
        for (int l = 0; l < 2; l++) {
            int e = tid + l * 256;
            int m = e >> 2, k4 = (e & 3) * 4;
            int gm = bm + m;
            ar[l] = (gm < M) ? *(const float4*)&A[(size_t)gm * lda + k0 + k4] : z4;
            int kr = e >> 5, nc = (e & 31) * 4;
            int gc = bn + nc;
            br[l] = (gc < N) ? *(const float4*)&B[(size_t)(k0 + kr) * ldb + gc] : z4;
        }
    };
    auto sts = [&](int buf) {
#pragma unroll
        for (int l = 0; l < 2; l++) {
            int e = tid + l * 256;
            int m = e >> 2, k4 = (e & 3) * 4;
            float4 a4 = cvt_tf32_4(ar[l]);
            As[buf][m][k4 + 0] = a4.x;
            As[buf][m][k4 + 1] = a4.y;
            As[buf][m][k4 + 2] = a4.z;
            As[buf][m][k4 + 3] = a4.w;
            int kr = e >> 5, nc = (e & 31) * 4;
            *(float4*)&Bs[buf][kr][nc] = cvt_tf32_4(br[l]);
        }
    };
    auto compute = [&](int buf) {
#pragma unroll
        for (int kk = 0; kk < 2; kk++) {
            const int kb = kk * 8;
            unsigned a[2][4], b[8][2];
#pragma unroll
            for (int mt = 0; mt < 2; mt++) {
                int row = wm + mt * 16 + g;
                a[mt][0] = __float_as_uint(As[buf][row][kb + t]);
                a[mt][1] = __float_as_uint(As[buf][row + 8][kb + t]);
                a[mt][2] = __float_as_uint(As[buf][row][kb + t + 4]);
                a[mt][3] = __float_as_uint(As[buf][row + 8][kb + t + 4]);
            }
#pragma unroll
            for (int nt = 0; nt < 8; nt++) {
                int col = wn + nt * 8 + g;
                b[nt][0] = __float_as_uint(Bs[buf][kb + t][col]);
                b[nt][1] = __float_as_uint(Bs[buf][kb + t + 4][col]);
            }
#pragma unroll
            for (int mt = 0; mt < 2; mt++)
#pragma unroll
                for (int nt = 0; nt < 8; nt++) mma8(c[mt][nt], a[mt], b[nt]);
        }
    };

    const int iters = K >> 4;
    ldg(0);
    sts(0);
    __syncthreads();
    for (int it = 0; it < iters; it++) {
        int buf = it & 1;
        if (it + 1 < iters) ldg((it + 1) << 4);
        compute(buf);
        if (it + 1 < iters) sts(buf ^ 1);
        __syncthreads();
    }

#pragma unroll
    for (int mt = 0; mt < 2; mt++) {
#pragma unroll
        for (int h = 0; h < 2; h++) {
            int row = bm + wm + mt * 16 + g + h * 8;
            if (row >= M) continue;
#pragma unroll
            for (int nt = 0; nt < 8; nt++) {
                int col = bn + wn + nt * 8 + 2 * t;
                if (col >= N) continue;
                float v0 = c[mt][nt][h * 2 + 0];
                float v1 = c[mt][nt][h * 2 + 1];
                if (bias) { v0 += bias[col]; v1 += bias[col + 1]; }
                if (act == 2) { v0 = fmaxf(v0, 0.f); v1 = fmaxf(v1, 0.f); }
                *(float2*)&C[(size_t)row * ldc + col] = make_float2(v0, v1);
            }
        }
    }
}

// ---------------- stage 1 aux -------------------------------------------------
__global__ void build_BmainTh(const float* __restrict__ W, const float* __restrict__ Wroot) {
    int i = blockIdx.x * blockDim.x + threadIdx.x;
    if (i >= (NR + 1) * EDIM * EDIM) return;
    int n = i >> 7, k = i & 127;
    int r = n >> 7, o = n & 127;
    float v = (r < NR) ? W[((size_t)r * EDIM + k) * EDIM + o] : Wroot[(size_t)k * EDIM + o];
    g_BmainTh[i] = __float2half_rn(v);
}

__global__ void tanh_root(const float* __restrict__ b) {
    int i = blockIdx.x * blockDim.x + threadIdx.x;
    if (i >= NE * (EDIM / 4)) return;
    int n = i >> 5, j = (i & 31) * 4;
    float4 v = *(const float4*)&g_Yroot[(size_t)n * EDIM + j];
    float4 bb = *(const float4*)&b[j];
    v.x = tanhf(v.x + bb.x);
    v.y = tanhf(v.y + bb.y);
    v.z = tanhf(v.z + bb.z);
    v.w = tanhf(v.w + bb.w);
    *(float4*)&g_E[(size_t)n * EDIM + j] = v;
    __half2* eh = (__half2*)&g_Eh[(size_t)n * EDIM + j];
    eh[0] = __floats2half2_rn(v.x, v.y);
    eh[1] = __floats2half2_rn(v.z, v.w);
}

// ---------------- stage 2 aux ---------------------------------------------------
__global__ void build_x(const int* __restrict__ h_idx, const int* __restrict__ r_idx,
                        const float* __restrict__ R) {
    int b = blockIdx.x, i = threadIdx.x;
    float v = g_E[(size_t)h_idx[b] * EDIM + i] * R[(size_t)r_idx[b] * EDIM + i];
    g_xh[b * EDIM + i] = __float2half_rn(v);
}

// ---------------- stage 3: metapath RGCNs --------------------------------------
__global__ void init_mp(int m, const int* __restrict__ eids) {
    int n = blockIdx.x;
    float* row = g_mp[m] + (size_t)n * KMP;
    const float4* er = (const float4*)(g_E + (size_t)eids[n] * EDIM);
    const float4 z = make_float4(0.f, 0.f, 0.f, 0.f);
    for (int j = threadIdx.x; j < KMP / 4; j += blockDim.x)
        ((float4*)row)[j] = (j < (KMP - EDIM) / 4) ? z : er[j - (KMP - EDIM) / 4];
    if (blockIdx.x == 0 && threadIdx.x < 2) g_w[threadIdx.x] = 0.f;
}

__global__ void scatter_mp(int m, const int* __restrict__ ei, const int* __restrict__ et,
                           const int* __restrict__ eids) {
    int w = (blockIdx.x * blockDim.x + threadIdx.x) >> 5;
    int lane = threadIdx.x & 31;
    if (w >= NMP_E) return;
    int dst = ei[NMP_E + w];
    if (dst >= NREG) return;
    int src = ei[w];
    int r = et[w];
    float4 v = *(const float4*)(g_E + (size_t)eids[src] * EDIM + lane * 4);
    red_add_v4(g_mp[m] + (size_t)dst * KMP + r * EDIM + lane * 4, v);
}

// ---------------- stage 4: semantic attention + head ---------------------------
__global__ void attn(const float* __restrict__ w1, const float* __restrict__ b1,
                     const float* __restrict__ w2) {
    int n = blockIdx.x, m = blockIdx.y, tid = threadIdx.x;
    __shared__ float z[HID];
    __shared__ float red[ATT];
    const float* zp = &g_sem[m][(size_t)n * HID];
    z[tid] = zp[tid];
    z[tid + 128] = zp[tid + 128];
    __syncthreads();
    float acc = b1[tid];
#pragma unroll 8
    for (int k = 0; k < HID; k++) acc = fmaf(z[k], w1[k * ATT + tid], acc);
    red[tid] = tanhf(acc) * w2[tid];
    __syncthreads();
    for (int s = 64; s > 0; s >>= 1) {
        if (tid < s) red[tid] += red[tid + s];
        __syncthreads();
    }
    if (tid == 0) atomicAdd(&g_w[m], red[0] * (1.0f / NREG));
}

__global__ void finalk(const float* __restrict__ predW, const float* __restrict__ predb,
                       float* __restrict__ out) {
    int n = blockIdx.x, tid = threadIdx.x;
    __shared__ float h[HID];
    float w0 = g_w[0], w1v = g_w[1];
    float mx = fmaxf(w0, w1v);
    float e0 = expf(w0 - mx), e1 = expf(w1v - mx);
    float inv = 1.f / (e0 + e1);
    float b0 = e0 * inv, b1 = e1 * inv;
    h[tid] = b0 * g_sem[0][(size_t)n * HID + tid] + b1 * g_sem[1][(size_t)n * HID + tid];
    h[tid + 128] =
        b0 * g_sem[0][(size_t)n * HID + tid + 128] + b1 * g_sem[1][(size_t)n * HID + tid + 128];
    __syncthreads();
    float acc = predb[tid] + g_E[(size_t)n * EDIM + tid];
#pragma unroll 8
    for (int k = 0; k < HID; k++) acc = fmaf(h[k], predW[k * EDIM + tid], acc);
    out[(size_t)n * EDIM + tid] = acc;
}

// ---------------- launch ------------------------------------------------------
extern "C" void kernel_launch(void* const* d_in, const int* in_sizes, int n_in,
                              void* d_out, int out_size) {
    const float* E_weight = (const float*)d_in[0];
    const float* R_weight = (const float*)d_in[1];
    const float* rgcn_W = (const float*)d_in[2];
    const float* rgcn_Wroot = (const float*)d_in[3];
    const float* rgcn_b = (const float*)d_in[4];
    const float* mp0_W = (const float*)d_in[5];
    const float* mp0_Wroot = (const float*)d_in[6];
    const float* mp0_b = (const float*)d_in[7];
    const float* mp1_W = (const float*)d_in[8];
    const float* mp1_Wroot = (const float*)d_in[9];
    const float* mp1_b = (const float*)d_in[10];
    const float* sa_w1 = (const float*)d_in[11];
    const float* sa_b1 = (const float*)d_in[12];
    const float* sa_w2 = (const float*)d_in[13];
    const float* pred_W = (const float*)d_in[14];
    const float* pred_b = (const float*)d_in[15];
    const int* h_idx = (const int*)d_in[16];
    const int* r_idx = (const int*)d_in[17];
    const int* edge_index = (const int*)d_in[18];
    const int* edge_type = (const int*)d_in[19];
    const int* mp0_ei = (const int*)d_in[20];
    const int* mp0_et = (const int*)d_in[21];
    const int* mp0_eids = (const int*)d_in[22];
    const int* mp1_ei = (const int*)d_in[23];
    const int* mp1_et = (const int*)d_in[24];
    const int* mp1_eids = (const int*)d_in[25];
    float* out = (float*)d_out;  // [E_reg 2000*128 | pred 1024*100000]

    float *pBmp, *psem, *pmp;
    __half *pEh, *pXh, *pBmTh, *pxh;
    cudaGetSymbolAddress((void**)&pBmp, g_Bmp);
    cudaGetSymbolAddress((void**)&psem, g_sem);
    cudaGetSymbolAddress((void**)&pmp, g_mp);
    cudaGetSymbolAddress((void**)&pEh, g_Eh);
    cudaGetSymbolAddress((void**)&pXh, g_Xh);
    cudaGetSymbolAddress((void**)&pBmTh, g_BmainTh);
    cudaGetSymbolAddress((void**)&pxh, g_xh);

    const int TILE_B = 128 * SPAD * (int)sizeof(__half);  // 34,816
    const int SMEM_ROOT = 2 * TILE_B;                      // 69,632
    const int SMEM_EDGE = 3 * TILE_B + 2 * ECHUNK * 128 * (int)sizeof(int);  // 112,640
    const int SMEM_PRED = 3 * TILE_B;                      // 104,448
    cudaFuncSetAttribute(gemm_root, cudaFuncAttributeMaxDynamicSharedMemorySize, SMEM_ROOT);
    cudaFuncSetAttribute(gemm_edge, cudaFuncAttributeMaxDynamicSharedMemorySize, SMEM_EDGE);
    cudaFuncSetAttribute(gemm_pred, cudaFuncAttributeMaxDynamicSharedMemorySize, SMEM_PRED);

    cudaStream_t s1 = g_res.s1;

    // ===== fork 1: edge bucketing on s1, f2h + weight prep + root GEMM on main =====
    cudaEventRecord(g_res.evF1, 0);
    cudaStreamWaitEvent(s1, g_res.evF1, 0);

    edge_prefill<<<(TILES_CAP * 128 + 255) / 256, 256, 0, s1>>>();
    edge_hist<<<NCTA_E, 256, 0, s1>>>(edge_type);
    edge_prefix<<<1, 320, 0, s1>>>();
    edge_reorder<<<NCTA_E, 256, 0, s1>>>(edge_index, edge_type);

    f2h<<<(NE * EDIM / 4 + 255) / 256, 256>>>(E_weight, pXh, NE * EDIM / 4);
    build_BmainTh<<<((NR + 1) * EDIM * EDIM + 255) / 256, 256>>>(rgcn_W, rgcn_Wroot);
    gemm_root<<<(NE + 127) / 128, 256, SMEM_ROOT>>>(pXh, pBmTh, NE);

    cudaEventRecord(g_res.evJ1, s1);
    cudaStreamWaitEvent(0, g_res.evJ1, 0);

    // ===== main: fused edge GEMM + activation =====
    gemm_edge<<<TILES_CAP / ECHUNK, 256, SMEM_EDGE>>>(pXh, pBmTh);
    tanh_root<<<(NE * (EDIM / 4) + 255) / 256, 256>>>(rgcn_b);

    // ===== fork 2: metapath/attention tail on s1, pred GEMM on main =====
    cudaEventRecord(g_res.evF2, 0);
    cudaStreamWaitEvent(s1, g_res.evF2, 0);

    init_mp<<<NREG, 128, 0, s1>>>(0, mp0_eids);
    init_mp<<<NREG, 128, 0, s1>>>(1, mp1_eids);
    cudaMemcpyAsync(pBmp, mp0_W, (size_t)NMP_REL * EDIM * HID * 4,
                    cudaMemcpyDeviceToDevice, s1);
    cudaMemcpyAsync(pBmp + NMP_REL * EDIM * HID, mp0_Wroot, (size_t)EDIM * HID * 4,
                    cudaMemcpyDeviceToDevice, s1);
    cudaMemcpyAsync(pBmp + KMP * HID, mp1_W, (size_t)NMP_REL * EDIM * HID * 4,
                    cudaMemcpyDeviceToDevice, s1);
    cudaMemcpyAsync(pBmp + KMP * HID + NMP_REL * EDIM * HID, mp1_Wroot,
                    (size_t)EDIM * HID * 4, cudaMemcpyDeviceToDevice, s1);
    scatter_mp<<<NMP_E / 8, 256, 0, s1>>>(0, mp0_ei, mp0_et, mp0_eids);
    scatter_mp<<<NMP_E / 8, 256, 0, s1>>>(1, mp1_ei, mp1_et, mp1_eids);
    gemm_tf32<<<dim3((NREG + 127) / 128, HID / 128), 256, 0, s1>>>(
        pmp, KMP, pBmp, HID, mp0_b, psem, HID, NREG, HID, KMP, 2);
    gemm_tf32<<<dim3((NREG + 127) / 128, HID / 128), 256, 0, s1>>>(
        pmp + (size_t)NREG * KMP, KMP, pBmp + (size_t)KMP * HID, HID, mp1_b,
        psem + (size_t)NREG * HID, HID, NREG, HID, KMP, 2);
    attn<<<dim3(NREG, 2), ATT, 0, s1>>>(sa_w1, sa_b1, sa_w2);
    finalk<<<NREG, EDIM, 0, s1>>>(pred_W, pred_b, out);

    // main: KGE pred = (E[h]*R[r]) @ E^T
    build_x<<<NB, EDIM>>>(h_idx, r_idx, R_weight);
    gemm_pred<<<dim3(NB / (128 * PCHUNK), (NE + 127) / 128), 256, SMEM_PRED>>>(
        pxh, pEh, out + NREG * EDIM, NB, NE, NE);

    cudaEventRecord(g_res.evJ2, s1);
    cudaStreamWaitEvent(0, g_res.evJ2, 0);
}